// round 3
// baseline (speedup 1.0000x reference)
#include <cuda_runtime.h>
#include <math.h>

#define Nn 50000
#define Ee 800000
#define Mm 3
#define Fh 256   // H*D
#define Hh 8
#define HID 128

__device__ float g_feat[(size_t)Mm * Nn * Fh];   // per-metapath projected features
__device__ float g_z[(size_t)Mm * Nn * Fh];      // rst accumulator, then elu'd z_m
__device__ float g_el[(size_t)Mm * Nn * Hh];
__device__ float g_er[(size_t)Mm * Nn * Hh];
__device__ float g_esum[(size_t)Mm * Nn * Hh];
__device__ float g_w[Mm];
__device__ float g_aw[Mm];

__device__ __forceinline__ void red4(float* p, float a, float b, float c, float d) {
    asm volatile("red.global.add.v4.f32 [%0], {%1,%2,%3,%4};"
                 :: "l"(p), "f"(a), "f"(b), "f"(c), "f"(d) : "memory");
}

// ---------------------------------------------------------------------------
// Zero accumulators (graph replays reuse device globals)
// ---------------------------------------------------------------------------
__global__ void k_zero() {
    size_t i = (size_t)blockIdx.x * blockDim.x + threadIdx.x;
    size_t stride = (size_t)gridDim.x * blockDim.x;
    float4* z4 = (float4*)g_z;
    size_t nz4 = (size_t)Mm * Nn * Fh / 4;
    float4 zero4 = make_float4(0.f, 0.f, 0.f, 0.f);
    for (size_t j = i; j < nz4; j += stride) z4[j] = zero4;
    size_t ns = (size_t)Mm * Nn * Hh;
    for (size_t j = i; j < ns; j += stride) g_esum[j] = 0.f;
    if (i < Mm) g_w[i] = 0.f;
}

// ---------------------------------------------------------------------------
// feat[m] = h @ fc_w[m]   (fp32 tiled GEMM, 64x64 tile, 4x4 per thread)
// ---------------------------------------------------------------------------
__global__ void k_gemm(const float* __restrict__ A, const float* __restrict__ W) {
    int m = blockIdx.z;
    const float* Bm = W + (size_t)m * 256 * 256;
    float* C = g_feat + (size_t)m * Nn * Fh;

    __shared__ float As[64][17];
    __shared__ float Bs[16][64];

    int tx = threadIdx.x, ty = threadIdx.y;
    int tid = ty * 16 + tx;
    int row0 = blockIdx.y * 64;
    int col0 = blockIdx.x * 64;

    float acc[4][4] = {};

    for (int kb = 0; kb < 256; kb += 16) {
        #pragma unroll
        for (int t = 0; t < 4; t++) {
            int idx = tid + 256 * t;
            int i = idx >> 4, k = idx & 15;
            int row = row0 + i;
            As[i][k] = (row < Nn) ? A[(size_t)row * 256 + kb + k] : 0.f;
        }
        #pragma unroll
        for (int t = 0; t < 4; t++) {
            int idx = tid + 256 * t;
            int k = idx >> 6, j = idx & 63;
            Bs[k][j] = Bm[(size_t)(kb + k) * 256 + col0 + j];
        }
        __syncthreads();
        #pragma unroll
        for (int k = 0; k < 16; k++) {
            float a[4], b[4];
            #pragma unroll
            for (int i = 0; i < 4; i++) a[i] = As[ty + 16 * i][k];
            #pragma unroll
            for (int j = 0; j < 4; j++) b[j] = Bs[k][tx + 16 * j];
            #pragma unroll
            for (int i = 0; i < 4; i++)
                #pragma unroll
                for (int j = 0; j < 4; j++) acc[i][j] += a[i] * b[j];
        }
        __syncthreads();
    }
    #pragma unroll
    for (int i = 0; i < 4; i++) {
        int row = row0 + ty + 16 * i;
        if (row < Nn) {
            #pragma unroll
            for (int j = 0; j < 4; j++)
                C[(size_t)row * 256 + col0 + tx + 16 * j] = acc[i][j];
        }
    }
}

// ---------------------------------------------------------------------------
// el/er: per (node, head) dot(feat, attn).  Warp per node.
// ---------------------------------------------------------------------------
__global__ void k_eler(const float* __restrict__ attn_l, const float* __restrict__ attn_r) {
    int m = blockIdx.z;
    __shared__ float al[256], ar[256];
    int tid = threadIdx.x;
    al[tid] = attn_l[m * 256 + tid];
    ar[tid] = attn_r[m * 256 + tid];
    __syncthreads();

    int warp = tid >> 5, lane = tid & 31;
    int node = blockIdx.x * 8 + warp;
    if (node >= Nn) return;

    const float4* f4 = (const float4*)(g_feat + (size_t)m * Nn * Fh + (size_t)node * 256 + lane * 8);
    float4 x0 = f4[0], x1 = f4[1];
    const float* alp = al + lane * 8;
    const float* arp = ar + lane * 8;
    float sl = x0.x * alp[0] + x0.y * alp[1] + x0.z * alp[2] + x0.w * alp[3]
             + x1.x * alp[4] + x1.y * alp[5] + x1.z * alp[6] + x1.w * alp[7];
    float sr = x0.x * arp[0] + x0.y * arp[1] + x0.z * arp[2] + x0.w * arp[3]
             + x1.x * arp[4] + x1.y * arp[5] + x1.z * arp[6] + x1.w * arp[7];
    // reduce within each 4-lane group (one head per group)
    sl += __shfl_xor_sync(0xffffffffu, sl, 1);
    sl += __shfl_xor_sync(0xffffffffu, sl, 2);
    sr += __shfl_xor_sync(0xffffffffu, sr, 1);
    sr += __shfl_xor_sync(0xffffffffu, sr, 2);
    if ((lane & 3) == 0) {
        int h = lane >> 2;
        g_el[(size_t)m * Nn * Hh + node * 8 + h] = sl;
        g_er[(size_t)m * Nn * Hh + node * 8 + h] = sr;
    }
}

// ---------------------------------------------------------------------------
// Edge pass 1: esum[dst,h] += exp(lrelu(el[src,h]+er[dst,h]))
// (segment-max skipped: |e| is small, exp cannot overflow; alpha is identical)
// ---------------------------------------------------------------------------
__global__ void k_pass1(const int* __restrict__ src, const int* __restrict__ dst, int m) {
    int e = blockIdx.x * blockDim.x + threadIdx.x;
    if (e >= Ee) return;
    int s = src[e], d = dst[e];
    const float* base_el = g_el + (size_t)m * Nn * Hh;
    const float* base_er = g_er + (size_t)m * Nn * Hh;
    const float4* el4 = (const float4*)(base_el + (size_t)s * 8);
    const float4* er4 = (const float4*)(base_er + (size_t)d * 8);
    float4 a0 = el4[0], a1 = el4[1];
    float4 b0 = er4[0], b1 = er4[1];
    float v[8] = {a0.x + b0.x, a0.y + b0.y, a0.z + b0.z, a0.w + b0.w,
                  a1.x + b1.x, a1.y + b1.y, a1.z + b1.z, a1.w + b1.w};
    float ee[8];
    #pragma unroll
    for (int i = 0; i < 8; i++) {
        float x = v[i];
        x = x > 0.f ? x : 0.2f * x;
        ee[i] = __expf(x);
    }
    float* esp = g_esum + (size_t)m * Nn * Hh + (size_t)d * 8;
    red4(esp, ee[0], ee[1], ee[2], ee[3]);
    red4(esp + 4, ee[4], ee[5], ee[6], ee[7]);
}

// ---------------------------------------------------------------------------
// Edge pass 2: rst[dst] += feat[src] * alpha.  Warp per edge,
// lane covers 8 consecutive floats (head = lane/4).
// ---------------------------------------------------------------------------
__global__ void k_pass2(const int* __restrict__ src, const int* __restrict__ dst, int m) {
    int tid = blockIdx.x * blockDim.x + threadIdx.x;
    int e = tid >> 5;
    int lane = tid & 31;
    if (e >= Ee) return;
    int s = src[e], d = dst[e];

    const float* base_el = g_el + (size_t)m * Nn * Hh;
    const float* base_er = g_er + (size_t)m * Nn * Hh;
    const float* base_es = g_esum + (size_t)m * Nn * Hh;

    float alpha = 0.f;
    if (lane < 8) {
        float x = base_el[(size_t)s * 8 + lane] + base_er[(size_t)d * 8 + lane];
        x = x > 0.f ? x : 0.2f * x;
        alpha = __expf(x) / fmaxf(base_es[(size_t)d * 8 + lane], 1e-38f);
    }
    alpha = __shfl_sync(0xffffffffu, alpha, lane >> 2);

    const float4* f4 = (const float4*)(g_feat + (size_t)m * Nn * Fh + (size_t)s * 256 + lane * 8);
    float4 x0 = f4[0], x1 = f4[1];
    float* rp = g_z + (size_t)m * Nn * Fh + (size_t)d * 256 + lane * 8;
    red4(rp,     x0.x * alpha, x0.y * alpha, x0.z * alpha, x0.w * alpha);
    red4(rp + 4, x1.x * alpha, x1.y * alpha, x1.z * alpha, x1.w * alpha);
}

// ---------------------------------------------------------------------------
// z_m = elu(rst + bias)
// ---------------------------------------------------------------------------
__global__ void k_elu(const float* __restrict__ bias) {
    int i = blockIdx.x * blockDim.x + threadIdx.x;       // over M*N*F/4 float4s
    int total = Mm * Nn * (Fh / 4);
    if (i >= total) return;
    int f4 = i & 63;                 // float4 index within 256-row
    int row = i >> 6;                // m*N + n
    int m = row / Nn;
    float4 b = ((const float4*)(bias + (size_t)m * 256))[f4];
    float4 v = ((float4*)g_z)[i];
    v.x += b.x; v.y += b.y; v.z += b.z; v.w += b.w;
    v.x = v.x > 0.f ? v.x : expm1f(v.x);
    v.y = v.y > 0.f ? v.y : expm1f(v.y);
    v.z = v.z > 0.f ? v.z : expm1f(v.z);
    v.w = v.w > 0.f ? v.w : expm1f(v.w);
    ((float4*)g_z)[i] = v;
}

// ---------------------------------------------------------------------------
// Semantic attention projection:
//   w[m] += sum_rows( tanh(z @ w1 + b1) @ w2 )
// Block: 128 threads (one per hidden unit), 16 rows per block.
// ---------------------------------------------------------------------------
__global__ void k_sem(const float* __restrict__ w1, const float* __restrict__ b1,
                      const float* __restrict__ w2) {
    int m = blockIdx.z;
    int j = threadIdx.x;  // hidden index 0..127
    __shared__ float zs[16 * 256];
    __shared__ float redbuf[4];

    int row0 = blockIdx.x * 16;
    const float* Z = g_z + (size_t)m * Nn * Fh + (size_t)row0 * 256;
    #pragma unroll
    for (int t = 0; t < 32; t++) {
        int idx = j + 128 * t;
        zs[idx] = Z[idx];
    }
    __syncthreads();

    float acc[16];
    #pragma unroll
    for (int r = 0; r < 16; r++) acc[r] = 0.f;

    const float4* zs4 = (const float4*)zs;
    for (int k4 = 0; k4 < 64; k4++) {
        float wv0 = w1[(k4 * 4 + 0) * 128 + j];
        float wv1 = w1[(k4 * 4 + 1) * 128 + j];
        float wv2 = w1[(k4 * 4 + 2) * 128 + j];
        float wv3 = w1[(k4 * 4 + 3) * 128 + j];
        #pragma unroll
        for (int r = 0; r < 16; r++) {
            float4 zv = zs4[r * 64 + k4];
            acc[r] += zv.x * wv0 + zv.y * wv1 + zv.z * wv2 + zv.w * wv3;
        }
    }

    float bj = b1[j], wj = w2[j];
    float t = 0.f;
    #pragma unroll
    for (int r = 0; r < 16; r++) t += tanhf(acc[r] + bj) * wj;

    // reduce over 128 threads
    #pragma unroll
    for (int o = 16; o > 0; o >>= 1) t += __shfl_xor_sync(0xffffffffu, t, o);
    int warp = j >> 5, lane = j & 31;
    if (lane == 0) redbuf[warp] = t;
    __syncthreads();
    if (j == 0) {
        float total = redbuf[0] + redbuf[1] + redbuf[2] + redbuf[3];
        atomicAdd(&g_w[m], total);
    }
}

// ---------------------------------------------------------------------------
// softmax over 3 metapath scores (mean over N)
// ---------------------------------------------------------------------------
__global__ void k_aw() {
    float w0 = g_w[0] / (float)Nn;
    float w1 = g_w[1] / (float)Nn;
    float w2 = g_w[2] / (float)Nn;
    float mx = fmaxf(w0, fmaxf(w1, w2));
    float e0 = expf(w0 - mx), e1 = expf(w1 - mx), e2 = expf(w2 - mx);
    float s = e0 + e1 + e2;
    g_aw[0] = e0 / s; g_aw[1] = e1 / s; g_aw[2] = e2 / s;
}

// ---------------------------------------------------------------------------
// z = sum_m z_m * a_w[m]
// ---------------------------------------------------------------------------
__global__ void k_comb(float* __restrict__ out) {
    int i = blockIdx.x * blockDim.x + threadIdx.x;   // N*F/4
    int total = Nn * (Fh / 4);
    if (i >= total) return;
    float a0 = g_aw[0], a1 = g_aw[1], a2 = g_aw[2];
    const float4* z4 = (const float4*)g_z;
    float4 v0 = z4[i];
    float4 v1 = z4[i + (size_t)Nn * Fh / 4];
    float4 v2 = z4[i + 2 * (size_t)Nn * Fh / 4];
    float4 o;
    o.x = v0.x * a0 + v1.x * a1 + v2.x * a2;
    o.y = v0.y * a0 + v1.y * a1 + v2.y * a2;
    o.z = v0.z * a0 + v1.z * a1 + v2.z * a2;
    o.w = v0.w * a0 + v1.w * a1 + v2.w * a2;
    ((float4*)out)[i] = o;
}

// ---------------------------------------------------------------------------
extern "C" void kernel_launch(void* const* d_in, const int* in_sizes, int n_in,
                              void* d_out, int out_size) {
    const float* h      = (const float*)d_in[0];
    const int*   src    = (const int*)d_in[1];
    const int*   dst    = (const int*)d_in[2];
    const float* fc_w   = (const float*)d_in[3];
    const float* attn_l = (const float*)d_in[4];
    const float* attn_r = (const float*)d_in[5];
    const float* bias   = (const float*)d_in[6];
    const float* sem_w1 = (const float*)d_in[7];
    const float* sem_b1 = (const float*)d_in[8];
    const float* sem_w2 = (const float*)d_in[9];
    float* out = (float*)d_out;

    k_zero<<<4096, 256>>>();

    dim3 gb(4, (Nn + 63) / 64, Mm);
    k_gemm<<<gb, dim3(16, 16)>>>(h, fc_w);

    k_eler<<<dim3((Nn + 7) / 8, 1, Mm), 256>>>(attn_l, attn_r);

    for (int m = 0; m < Mm; m++) {
        k_pass1<<<(Ee + 255) / 256, 256>>>(src + (size_t)m * Ee, dst + (size_t)m * Ee, m);
        k_pass2<<<(Ee * 32 + 255) / 256, 256>>>(src + (size_t)m * Ee, dst + (size_t)m * Ee, m);
    }

    k_elu<<<(Mm * Nn * (Fh / 4) + 255) / 256, 256>>>(bias);

    k_sem<<<dim3(Nn / 16, 1, Mm), 128>>>(sem_w1, sem_b1, sem_w2);
    k_aw<<<1, 1>>>();
    k_comb<<<(Nn * (Fh / 4) + 255) / 256, 256>>>(out);
}

// round 5
// speedup vs baseline: 1.3853x; 1.3853x over previous
#include <cuda_runtime.h>
#include <cuda_bf16.h>
#include <math.h>

#define Nn 50000
#define Ee 800000
#define Mm 3
#define Fh 256   // H*D
#define Hh 8
#define HID 128
#define NZ (Mm * Nn)   // 150000 rows of z

__device__ __align__(16) float g_feat[(size_t)Mm * Nn * Fh];
__device__ __align__(16) float g_z[(size_t)Mm * Nn * Fh];
__device__ __align__(16) float g_el[(size_t)Mm * Nn * Hh];
__device__ __align__(16) float g_er[(size_t)Mm * Nn * Hh];
__device__ __align__(16) float g_esum[(size_t)Mm * Nn * Hh];
__device__ float g_w[Mm];
__device__ float g_aw[Mm];

// bf16 split buffers
__device__ __align__(16) __nv_bfloat16 g_h_hi[(size_t)Nn * Fh];
__device__ __align__(16) __nv_bfloat16 g_h_lo[(size_t)Nn * Fh];
__device__ __align__(16) __nv_bfloat16 g_fwT_hi[(size_t)Mm * Fh * Fh]; // [m][n][k]
__device__ __align__(16) __nv_bfloat16 g_fwT_lo[(size_t)Mm * Fh * Fh];
__device__ __align__(16) __nv_bfloat16 g_w1T_hi[HID * Fh];             // [n][k]
__device__ __align__(16) __nv_bfloat16 g_w1T_lo[HID * Fh];
__device__ __align__(16) __nv_bfloat16 g_z_hi[(size_t)NZ * Fh];
__device__ __align__(16) __nv_bfloat16 g_z_lo[(size_t)NZ * Fh];

__device__ __forceinline__ void red4(float* p, float a, float b, float c, float d) {
    asm volatile("red.global.add.v4.f32 [%0], {%1,%2,%3,%4};"
                 :: "l"(p), "f"(a), "f"(b), "f"(c), "f"(d) : "memory");
}

__device__ __forceinline__ float tanha(float x) {
    float y; asm("tanh.approx.f32 %0, %1;" : "=f"(y) : "f"(x)); return y;
}

#define MMA(d, a, b)                                                              \
    asm volatile("mma.sync.aligned.m16n8k16.row.col.f32.bf16.bf16.f32 "           \
                 "{%0,%1,%2,%3},{%4,%5,%6,%7},{%8,%9},{%0,%1,%2,%3};"             \
                 : "+f"((d)[0]), "+f"((d)[1]), "+f"((d)[2]), "+f"((d)[3])         \
                 : "r"((a)[0]), "r"((a)[1]), "r"((a)[2]), "r"((a)[3]),            \
                   "r"((b)[0]), "r"((b)[1]))

// ---------------------------------------------------------------------------
// Zero accumulators (graph replays reuse device globals)
// ---------------------------------------------------------------------------
__global__ void k_zero() {
    size_t i = (size_t)blockIdx.x * blockDim.x + threadIdx.x;
    size_t stride = (size_t)gridDim.x * blockDim.x;
    float4* z4 = (float4*)g_z;
    size_t nz4 = (size_t)Mm * Nn * Fh / 4;
    float4 zero4 = make_float4(0.f, 0.f, 0.f, 0.f);
    for (size_t j = i; j < nz4; j += stride) z4[j] = zero4;
    size_t ns = (size_t)Mm * Nn * Hh;
    for (size_t j = i; j < ns; j += stride) g_esum[j] = 0.f;
    if (i < Mm) g_w[i] = 0.f;
}

// ---------------------------------------------------------------------------
// Split h into bf16 hi/lo
// ---------------------------------------------------------------------------
__global__ void k_split_h(const float* __restrict__ h) {
    int i = blockIdx.x * blockDim.x + threadIdx.x;  // over Nn*Fh/4
    if (i >= Nn * Fh / 4) return;
    float4 v = ((const float4*)h)[i];
    __nv_bfloat16 h0 = __float2bfloat16(v.x), h1 = __float2bfloat16(v.y);
    __nv_bfloat16 h2 = __float2bfloat16(v.z), h3 = __float2bfloat16(v.w);
    __nv_bfloat16 l0 = __float2bfloat16(v.x - __bfloat162float(h0));
    __nv_bfloat16 l1 = __float2bfloat16(v.y - __bfloat162float(h1));
    __nv_bfloat16 l2 = __float2bfloat16(v.z - __bfloat162float(h2));
    __nv_bfloat16 l3 = __float2bfloat16(v.w - __bfloat162float(h3));
    __nv_bfloat162* hp = (__nv_bfloat162*)g_h_hi;
    __nv_bfloat162* lp = (__nv_bfloat162*)g_h_lo;
    hp[2 * i] = __nv_bfloat162(h0, h1);  hp[2 * i + 1] = __nv_bfloat162(h2, h3);
    lp[2 * i] = __nv_bfloat162(l0, l1);  lp[2 * i + 1] = __nv_bfloat162(l2, l3);
}

// ---------------------------------------------------------------------------
// Split + transpose weights: fc_w [m][k][n] -> fwT [m][n][k]; w1 [k][n] -> w1T [n][k]
// ---------------------------------------------------------------------------
__global__ void k_split_w(const float* __restrict__ fc_w, const float* __restrict__ sem_w1) {
    int i = blockIdx.x * blockDim.x + threadIdx.x;
    int total1 = Mm * Fh * Fh;
    if (i < total1) {
        int m = i / (Fh * Fh);
        int r = i % (Fh * Fh);
        int k = r / Fh, n = r % Fh;
        float a = fc_w[i];
        __nv_bfloat16 hi = __float2bfloat16(a);
        __nv_bfloat16 lo = __float2bfloat16(a - __bfloat162float(hi));
        size_t o = (size_t)m * Fh * Fh + (size_t)n * Fh + k;
        g_fwT_hi[o] = hi; g_fwT_lo[o] = lo;
    } else if (i < total1 + Fh * HID) {
        int j = i - total1;
        int k = j / HID, n = j % HID;
        float a = sem_w1[j];
        __nv_bfloat16 hi = __float2bfloat16(a);
        __nv_bfloat16 lo = __float2bfloat16(a - __bfloat162float(hi));
        size_t o = (size_t)n * Fh + k;
        g_w1T_hi[o] = hi; g_w1T_lo[o] = lo;
    }
}

// ---------------------------------------------------------------------------
// feat[m] = h @ fc_w[m] via bf16 split mma.sync (3-term: hh + hl + lh)
// CTA tile 128x128x16, 8 warps, warp tile 64x32, double-buffered smem.
// ---------------------------------------------------------------------------
__global__ __launch_bounds__(256) void k_gemm_feat() {
    __shared__ unsigned sA[2][2][1024];  // [stage][hi/lo][row*8 + swizzled word]
    __shared__ unsigned sB[2][2][1024];

    int tid = threadIdx.x;
    int lane = tid & 31, warp = tid >> 5;
    int g = lane >> 2, t = lane & 3;
    int warp_m = warp >> 2, warp_n = warp & 3;
    int row0 = blockIdx.x * 128;
    int col0 = blockIdx.y * 128;
    int m = blockIdx.z;

    const unsigned* Ah = (const unsigned*)g_h_hi;
    const unsigned* Al = (const unsigned*)g_h_lo;
    const unsigned* Bh = (const unsigned*)(g_fwT_hi + (size_t)m * Fh * Fh);
    const unsigned* Bl = (const unsigned*)(g_fwT_lo + (size_t)m * Fh * Fh);

    int lr = tid >> 1;         // tile row 0..127
    int lw = (tid & 1) * 4;    // word base 0 or 4

    float acc[4][4][4] = {};
    uint4 pa_h, pa_l, pb_h, pb_l;

    auto LOADG = [&](int ks) {
        int grow = row0 + lr;
        if (grow < Nn) {
            pa_h = *(const uint4*)(Ah + (size_t)grow * 128 + ks * 8 + lw);
            pa_l = *(const uint4*)(Al + (size_t)grow * 128 + ks * 8 + lw);
        } else {
            pa_h = make_uint4(0, 0, 0, 0); pa_l = make_uint4(0, 0, 0, 0);
        }
        pb_h = *(const uint4*)(Bh + (size_t)(col0 + lr) * 128 + ks * 8 + lw);
        pb_l = *(const uint4*)(Bl + (size_t)(col0 + lr) * 128 + ks * 8 + lw);
    };
    auto STORES = [&](int st) {
        int sbase = lr * 8;
        unsigned ah[4] = {pa_h.x, pa_h.y, pa_h.z, pa_h.w};
        unsigned al[4] = {pa_l.x, pa_l.y, pa_l.z, pa_l.w};
        unsigned bh[4] = {pb_h.x, pb_h.y, pb_h.z, pb_h.w};
        unsigned bl[4] = {pb_l.x, pb_l.y, pb_l.z, pb_l.w};
        #pragma unroll
        for (int q = 0; q < 4; q++) {
            int ws = (lw + q) ^ (lr & 7);
            sA[st][0][sbase + ws] = ah[q];
            sA[st][1][sbase + ws] = al[q];
            sB[st][0][sbase + ws] = bh[q];
            sB[st][1][sbase + ws] = bl[q];
        }
    };
    auto DOMMA = [&](int st) {
        unsigned a_h[4][4], a_l[4][4], b_h[4][2], b_l[4][2];
        #pragma unroll
        for (int mf = 0; mf < 4; mf++) {
            int r0 = warp_m * 64 + mf * 16 + g;
            int r1 = r0 + 8;
            int i00 = r0 * 8 + (t ^ (r0 & 7));
            int i10 = r1 * 8 + (t ^ (r1 & 7));
            int i01 = r0 * 8 + ((t + 4) ^ (r0 & 7));
            int i11 = r1 * 8 + ((t + 4) ^ (r1 & 7));
            a_h[mf][0] = sA[st][0][i00]; a_h[mf][1] = sA[st][0][i10];
            a_h[mf][2] = sA[st][0][i01]; a_h[mf][3] = sA[st][0][i11];
            a_l[mf][0] = sA[st][1][i00]; a_l[mf][1] = sA[st][1][i10];
            a_l[mf][2] = sA[st][1][i01]; a_l[mf][3] = sA[st][1][i11];
        }
        #pragma unroll
        for (int nf = 0; nf < 4; nf++) {
            int n = warp_n * 32 + nf * 8 + g;
            int j0 = n * 8 + (t ^ (n & 7));
            int j1 = n * 8 + ((t + 4) ^ (n & 7));
            b_h[nf][0] = sB[st][0][j0]; b_h[nf][1] = sB[st][0][j1];
            b_l[nf][0] = sB[st][1][j0]; b_l[nf][1] = sB[st][1][j1];
        }
        #pragma unroll
        for (int mf = 0; mf < 4; mf++)
            #pragma unroll
            for (int nf = 0; nf < 4; nf++) {
                MMA(acc[mf][nf], a_h[mf], b_h[nf]);
                MMA(acc[mf][nf], a_h[mf], b_l[nf]);
                MMA(acc[mf][nf], a_l[mf], b_h[nf]);
            }
    };

    LOADG(0); STORES(0); __syncthreads();
    for (int ks = 0; ks < 16; ks++) {
        int cur = ks & 1;
        if (ks < 15) LOADG(ks + 1);
        DOMMA(cur);
        __syncthreads();
        if (ks < 15) { STORES(cur ^ 1); __syncthreads(); }
    }

    float* C = g_feat + (size_t)m * Nn * Fh;
    #pragma unroll
    for (int mf = 0; mf < 4; mf++) {
        int r = row0 + warp_m * 64 + mf * 16 + g;
        #pragma unroll
        for (int nf = 0; nf < 4; nf++) {
            int c = col0 + warp_n * 32 + nf * 8 + 2 * t;
            if (r < Nn)
                *(float2*)&C[(size_t)r * 256 + c] = make_float2(acc[mf][nf][0], acc[mf][nf][1]);
            if (r + 8 < Nn)
                *(float2*)&C[(size_t)(r + 8) * 256 + c] = make_float2(acc[mf][nf][2], acc[mf][nf][3]);
        }
    }
}

// ---------------------------------------------------------------------------
// el/er: per (node, head) dot(feat, attn).  Warp per node.
// ---------------------------------------------------------------------------
__global__ void k_eler(const float* __restrict__ attn_l, const float* __restrict__ attn_r) {
    int m = blockIdx.z;
    __shared__ float al[256], ar[256];
    int tid = threadIdx.x;
    al[tid] = attn_l[m * 256 + tid];
    ar[tid] = attn_r[m * 256 + tid];
    __syncthreads();

    int warp = tid >> 5, lane = tid & 31;
    int node = blockIdx.x * 8 + warp;
    if (node >= Nn) return;

    const float4* f4 = (const float4*)(g_feat + (size_t)m * Nn * Fh + (size_t)node * 256 + lane * 8);
    float4 x0 = f4[0], x1 = f4[1];
    const float* alp = al + lane * 8;
    const float* arp = ar + lane * 8;
    float sl = x0.x * alp[0] + x0.y * alp[1] + x0.z * alp[2] + x0.w * alp[3]
             + x1.x * alp[4] + x1.y * alp[5] + x1.z * alp[6] + x1.w * alp[7];
    float sr = x0.x * arp[0] + x0.y * arp[1] + x0.z * arp[2] + x0.w * arp[3]
             + x1.x * arp[4] + x1.y * arp[5] + x1.z * arp[6] + x1.w * arp[7];
    sl += __shfl_xor_sync(0xffffffffu, sl, 1);
    sl += __shfl_xor_sync(0xffffffffu, sl, 2);
    sr += __shfl_xor_sync(0xffffffffu, sr, 1);
    sr += __shfl_xor_sync(0xffffffffu, sr, 2);
    if ((lane & 3) == 0) {
        int h = lane >> 2;
        g_el[(size_t)m * Nn * Hh + node * 8 + h] = sl;
        g_er[(size_t)m * Nn * Hh + node * 8 + h] = sr;
    }
}

// ---------------------------------------------------------------------------
// Edge pass 1: esum[dst,h] += exp(lrelu(el[src,h]+er[dst,h]))
// ---------------------------------------------------------------------------
__global__ void k_pass1(const int* __restrict__ src, const int* __restrict__ dst, int m) {
    int e = blockIdx.x * blockDim.x + threadIdx.x;
    if (e >= Ee) return;
    int s = src[e], d = dst[e];
    const float* base_el = g_el + (size_t)m * Nn * Hh;
    const float* base_er = g_er + (size_t)m * Nn * Hh;
    const float4* el4 = (const float4*)(base_el + (size_t)s * 8);
    const float4* er4 = (const float4*)(base_er + (size_t)d * 8);
    float4 a0 = el4[0], a1 = el4[1];
    float4 b0 = er4[0], b1 = er4[1];
    float v[8] = {a0.x + b0.x, a0.y + b0.y, a0.z + b0.z, a0.w + b0.w,
                  a1.x + b1.x, a1.y + b1.y, a1.z + b1.z, a1.w + b1.w};
    float ee[8];
    #pragma unroll
    for (int i = 0; i < 8; i++) {
        float x = v[i];
        x = x > 0.f ? x : 0.2f * x;
        ee[i] = __expf(x);
    }
    float* esp = g_esum + (size_t)m * Nn * Hh + (size_t)d * 8;
    red4(esp, ee[0], ee[1], ee[2], ee[3]);
    red4(esp + 4, ee[4], ee[5], ee[6], ee[7]);
}

// ---------------------------------------------------------------------------
// Edge pass 2: rst[dst] += feat[src] * alpha.  Warp per edge.
// ---------------------------------------------------------------------------
__global__ void k_pass2(const int* __restrict__ src, const int* __restrict__ dst, int m) {
    int tid = blockIdx.x * blockDim.x + threadIdx.x;
    int e = tid >> 5;
    int lane = tid & 31;
    if (e >= Ee) return;
    int s = src[e], d = dst[e];

    const float* base_el = g_el + (size_t)m * Nn * Hh;
    const float* base_er = g_er + (size_t)m * Nn * Hh;
    const float* base_es = g_esum + (size_t)m * Nn * Hh;

    float alpha = 0.f;
    if (lane < 8) {
        float x = base_el[(size_t)s * 8 + lane] + base_er[(size_t)d * 8 + lane];
        x = x > 0.f ? x : 0.2f * x;
        alpha = __expf(x) / fmaxf(base_es[(size_t)d * 8 + lane], 1e-38f);
    }
    alpha = __shfl_sync(0xffffffffu, alpha, lane >> 2);

    const float4* f4 = (const float4*)(g_feat + (size_t)m * Nn * Fh + (size_t)s * 256 + lane * 8);
    float4 x0 = f4[0], x1 = f4[1];
    float* rp = g_z + (size_t)m * Nn * Fh + (size_t)d * 256 + lane * 8;
    red4(rp,     x0.x * alpha, x0.y * alpha, x0.z * alpha, x0.w * alpha);
    red4(rp + 4, x1.x * alpha, x1.y * alpha, x1.z * alpha, x1.w * alpha);
}

// ---------------------------------------------------------------------------
// z_m = elu(rst + bias); also write bf16 hi/lo split of z for the sem GEMM
// ---------------------------------------------------------------------------
__global__ void k_elu_split(const float* __restrict__ bias) {
    int i = blockIdx.x * blockDim.x + threadIdx.x;   // over M*N*F/4 float4s
    int total = Mm * Nn * (Fh / 4);
    if (i >= total) return;
    int f4 = i & 63;
    int row = i >> 6;
    int m = row / Nn;
    float4 b = ((const float4*)(bias + (size_t)m * 256))[f4];
    float4 v = ((float4*)g_z)[i];
    v.x += b.x; v.y += b.y; v.z += b.z; v.w += b.w;
    v.x = v.x > 0.f ? v.x : expm1f(v.x);
    v.y = v.y > 0.f ? v.y : expm1f(v.y);
    v.z = v.z > 0.f ? v.z : expm1f(v.z);
    v.w = v.w > 0.f ? v.w : expm1f(v.w);
    ((float4*)g_z)[i] = v;

    __nv_bfloat16 h0 = __float2bfloat16(v.x), h1 = __float2bfloat16(v.y);
    __nv_bfloat16 h2 = __float2bfloat16(v.z), h3 = __float2bfloat16(v.w);
    __nv_bfloat16 l0 = __float2bfloat16(v.x - __bfloat162float(h0));
    __nv_bfloat16 l1 = __float2bfloat16(v.y - __bfloat162float(h1));
    __nv_bfloat16 l2 = __float2bfloat16(v.z - __bfloat162float(h2));
    __nv_bfloat16 l3 = __float2bfloat16(v.w - __bfloat162float(h3));
    __nv_bfloat162* hp = (__nv_bfloat162*)g_z_hi;
    __nv_bfloat162* lp = (__nv_bfloat162*)g_z_lo;
    hp[2 * i] = __nv_bfloat162(h0, h1);  hp[2 * i + 1] = __nv_bfloat162(h2, h3);
    lp[2 * i] = __nv_bfloat162(l0, l1);  lp[2 * i + 1] = __nv_bfloat162(l2, l3);
}

// ---------------------------------------------------------------------------
// Semantic GEMM: for 150k rows z: t = tanh(z @ w1 + b1) @ w2, accumulated into
// g_w[m] per metapath.  Same tile structure; fused epilogue reduction.
// ---------------------------------------------------------------------------
__global__ __launch_bounds__(256) void k_gemm_sem(const float* __restrict__ sem_b1,
                                                  const float* __restrict__ sem_w2) {
    __shared__ unsigned sA[2][2][1024];
    __shared__ unsigned sB[2][2][1024];
    __shared__ float s_rsum[128];
    __shared__ float s_mw[3];
    __shared__ float sb1[128], sw2[128];

    int tid = threadIdx.x;
    int lane = tid & 31, warp = tid >> 5;
    int g = lane >> 2, t = lane & 3;
    int warp_m = warp >> 2, warp_n = warp & 3;
    int row0 = blockIdx.x * 128;

    if (tid < 128) { s_rsum[tid] = 0.f; sb1[tid] = sem_b1[tid]; sw2[tid] = sem_w2[tid]; }
    if (tid < 3) s_mw[tid] = 0.f;

    const unsigned* Ah = (const unsigned*)g_z_hi;
    const unsigned* Al = (const unsigned*)g_z_lo;
    const unsigned* Bh = (const unsigned*)g_w1T_hi;
    const unsigned* Bl = (const unsigned*)g_w1T_lo;

    int lr = tid >> 1;
    int lw = (tid & 1) * 4;

    float acc[4][4][4] = {};
    uint4 pa_h, pa_l, pb_h, pb_l;

    auto LOADG = [&](int ks) {
        int grow = row0 + lr;
        if (grow < NZ) {
            pa_h = *(const uint4*)(Ah + (size_t)grow * 128 + ks * 8 + lw);
            pa_l = *(const uint4*)(Al + (size_t)grow * 128 + ks * 8 + lw);
        } else {
            pa_h = make_uint4(0, 0, 0, 0); pa_l = make_uint4(0, 0, 0, 0);
        }
        pb_h = *(const uint4*)(Bh + (size_t)lr * 128 + ks * 8 + lw);
        pb_l = *(const uint4*)(Bl + (size_t)lr * 128 + ks * 8 + lw);
    };
    auto STORES = [&](int st) {
        int sbase = lr * 8;
        unsigned ah[4] = {pa_h.x, pa_h.y, pa_h.z, pa_h.w};
        unsigned al[4] = {pa_l.x, pa_l.y, pa_l.z, pa_l.w};
        unsigned bh[4] = {pb_h.x, pb_h.y, pb_h.z, pb_h.w};
        unsigned bl[4] = {pb_l.x, pb_l.y, pb_l.z, pb_l.w};
        #pragma unroll
        for (int q = 0; q < 4; q++) {
            int ws = (lw + q) ^ (lr & 7);
            sA[st][0][sbase + ws] = ah[q];
            sA[st][1][sbase + ws] = al[q];
            sB[st][0][sbase + ws] = bh[q];
            sB[st][1][sbase + ws] = bl[q];
        }
    };
    auto DOMMA = [&](int st) {
        unsigned a_h[4][4], a_l[4][4], b_h[4][2], b_l[4][2];
        #pragma unroll
        for (int mf = 0; mf < 4; mf++) {
            int r0 = warp_m * 64 + mf * 16 + g;
            int r1 = r0 + 8;
            int i00 = r0 * 8 + (t ^ (r0 & 7));
            int i10 = r1 * 8 + (t ^ (r1 & 7));
            int i01 = r0 * 8 + ((t + 4) ^ (r0 & 7));
            int i11 = r1 * 8 + ((t + 4) ^ (r1 & 7));
            a_h[mf][0] = sA[st][0][i00]; a_h[mf][1] = sA[st][0][i10];
            a_h[mf][2] = sA[st][0][i01]; a_h[mf][3] = sA[st][0][i11];
            a_l[mf][0] = sA[st][1][i00]; a_l[mf][1] = sA[st][1][i10];
            a_l[mf][2] = sA[st][1][i01]; a_l[mf][3] = sA[st][1][i11];
        }
        #pragma unroll
        for (int nf = 0; nf < 4; nf++) {
            int n = warp_n * 32 + nf * 8 + g;
            int j0 = n * 8 + (t ^ (n & 7));
            int j1 = n * 8 + ((t + 4) ^ (n & 7));
            b_h[nf][0] = sB[st][0][j0]; b_h[nf][1] = sB[st][0][j1];
            b_l[nf][0] = sB[st][1][j0]; b_l[nf][1] = sB[st][1][j1];
        }
        #pragma unroll
        for (int mf = 0; mf < 4; mf++)
            #pragma unroll
            for (int nf = 0; nf < 4; nf++) {
                MMA(acc[mf][nf], a_h[mf], b_h[nf]);
                MMA(acc[mf][nf], a_h[mf], b_l[nf]);
                MMA(acc[mf][nf], a_l[mf], b_h[nf]);
            }
    };

    LOADG(0); STORES(0); __syncthreads();
    for (int ks = 0; ks < 16; ks++) {
        int cur = ks & 1;
        if (ks < 15) LOADG(ks + 1);
        DOMMA(cur);
        __syncthreads();
        if (ks < 15) { STORES(cur ^ 1); __syncthreads(); }
    }

    // epilogue: per row sum_j tanh(acc + b1[j]) * w2[j]
    #pragma unroll
    for (int mf = 0; mf < 4; mf++) {
        float rsa = 0.f, rsb = 0.f;
        #pragma unroll
        for (int nf = 0; nf < 4; nf++) {
            int c = warp_n * 32 + nf * 8 + 2 * t;
            float b0 = sb1[c], b1v = sb1[c + 1];
            float w20 = sw2[c], w21 = sw2[c + 1];
            rsa += tanha(acc[mf][nf][0] + b0) * w20 + tanha(acc[mf][nf][1] + b1v) * w21;
            rsb += tanha(acc[mf][nf][2] + b0) * w20 + tanha(acc[mf][nf][3] + b1v) * w21;
        }
        rsa += __shfl_xor_sync(0xffffffffu, rsa, 1);
        rsa += __shfl_xor_sync(0xffffffffu, rsa, 2);
        rsb += __shfl_xor_sync(0xffffffffu, rsb, 1);
        rsb += __shfl_xor_sync(0xffffffffu, rsb, 2);
        if (t == 0) {
            atomicAdd(&s_rsum[warp_m * 64 + mf * 16 + g], rsa);
            atomicAdd(&s_rsum[warp_m * 64 + mf * 16 + g + 8], rsb);
        }
    }
    __syncthreads();
    if (tid < 128) {
        int r = row0 + tid;
        if (r < NZ) atomicAdd(&s_mw[r / Nn], s_rsum[tid]);
    }
    __syncthreads();
    if (tid < 3) atomicAdd(&g_w[tid], s_mw[tid]);
}

// ---------------------------------------------------------------------------
// softmax over 3 metapath scores (mean over N)
// ---------------------------------------------------------------------------
__global__ void k_aw() {
    float w0 = g_w[0] / (float)Nn;
    float w1 = g_w[1] / (float)Nn;
    float w2 = g_w[2] / (float)Nn;
    float mx = fmaxf(w0, fmaxf(w1, w2));
    float e0 = expf(w0 - mx), e1 = expf(w1 - mx), e2 = expf(w2 - mx);
    float s = e0 + e1 + e2;
    g_aw[0] = e0 / s; g_aw[1] = e1 / s; g_aw[2] = e2 / s;
}

// ---------------------------------------------------------------------------
// z = sum_m z_m * a_w[m]
// ---------------------------------------------------------------------------
__global__ void k_comb(float* __restrict__ out) {
    int i = blockIdx.x * blockDim.x + threadIdx.x;
    int total = Nn * (Fh / 4);
    if (i >= total) return;
    float a0 = g_aw[0], a1 = g_aw[1], a2 = g_aw[2];
    const float4* z4 = (const float4*)g_z;
    float4 v0 = z4[i];
    float4 v1 = z4[i + (size_t)Nn * Fh / 4];
    float4 v2 = z4[i + 2 * (size_t)Nn * Fh / 4];
    float4 o;
    o.x = v0.x * a0 + v1.x * a1 + v2.x * a2;
    o.y = v0.y * a0 + v1.y * a1 + v2.y * a2;
    o.z = v0.z * a0 + v1.z * a1 + v2.z * a2;
    o.w = v0.w * a0 + v1.w * a1 + v2.w * a2;
    ((float4*)out)[i] = o;
}

// ---------------------------------------------------------------------------
extern "C" void kernel_launch(void* const* d_in, const int* in_sizes, int n_in,
                              void* d_out, int out_size) {
    const float* h      = (const float*)d_in[0];
    const int*   src    = (const int*)d_in[1];
    const int*   dst    = (const int*)d_in[2];
    const float* fc_w   = (const float*)d_in[3];
    const float* attn_l = (const float*)d_in[4];
    const float* attn_r = (const float*)d_in[5];
    const float* bias   = (const float*)d_in[6];
    const float* sem_w1 = (const float*)d_in[7];
    const float* sem_b1 = (const float*)d_in[8];
    const float* sem_w2 = (const float*)d_in[9];
    float* out = (float*)d_out;

    k_zero<<<4096, 256>>>();
    k_split_h<<<(Nn * Fh / 4 + 255) / 256, 256>>>(h);
    k_split_w<<<(Mm * Fh * Fh + Fh * HID + 255) / 256, 256>>>(fc_w, sem_w1);

    dim3 gfeat((Nn + 127) / 128, Fh / 128, Mm);
    k_gemm_feat<<<gfeat, 256>>>();

    k_eler<<<dim3((Nn + 7) / 8, 1, Mm), 256>>>(attn_l, attn_r);

    for (int m = 0; m < Mm; m++) {
        k_pass1<<<(Ee + 255) / 256, 256>>>(src + (size_t)m * Ee, dst + (size_t)m * Ee, m);
        k_pass2<<<(Ee * 32 + 255) / 256, 256>>>(src + (size_t)m * Ee, dst + (size_t)m * Ee, m);
    }

    k_elu_split<<<(Mm * Nn * (Fh / 4) + 255) / 256, 256>>>(bias);

    k_gemm_sem<<<(NZ + 127) / 128, 256>>>(sem_b1, sem_w2);
    k_aw<<<1, 1>>>();
    k_comb<<<(Nn * (Fh / 4) + 255) / 256, 256>>>(out);
}

// round 7
// speedup vs baseline: 2.2255x; 1.6066x over previous
#include <cuda_runtime.h>
#include <cuda_bf16.h>
#include <math.h>

#define Nn 50000
#define Ee 800000
#define Mm 3
#define Fh 256   // H*D
#define Hh 8
#define HID 128
#define NZ (Mm * Nn)        // 150000 rows of z
#define SCANB 196           // ceil(Nn/256)

__device__ __align__(16) float g_feat[(size_t)Mm * Nn * Fh];
__device__ __align__(16) float g_z[(size_t)Mm * Nn * Fh];
__device__ __align__(16) float g_el[(size_t)Mm * Nn * Hh];
__device__ __align__(16) float g_er[(size_t)Mm * Nn * Hh];
__device__ float g_w[Mm];
__device__ float g_aw[Mm];

// CSR scratch
__device__ int g_hist[Mm * Nn];     // becomes exclusive offsets after scan
__device__ int g_off[Mm * Nn];
__device__ int g_bsum[Mm * 256];
__device__ int g_cursor[Mm * Nn];
__device__ int g_csrc[(size_t)Mm * Ee];

// bf16 split buffers
__device__ __align__(16) __nv_bfloat16 g_h_hi[(size_t)Nn * Fh];
__device__ __align__(16) __nv_bfloat16 g_h_lo[(size_t)Nn * Fh];
__device__ __align__(16) __nv_bfloat16 g_fwT_hi[(size_t)Mm * Fh * Fh]; // [m][n][k]
__device__ __align__(16) __nv_bfloat16 g_fwT_lo[(size_t)Mm * Fh * Fh];
__device__ __align__(16) __nv_bfloat16 g_w1T_hi[HID * Fh];             // [n][k]
__device__ __align__(16) __nv_bfloat16 g_w1T_lo[HID * Fh];
__device__ __align__(16) __nv_bfloat16 g_z_hi[(size_t)NZ * Fh];
__device__ __align__(16) __nv_bfloat16 g_z_lo[(size_t)NZ * Fh];

__device__ __forceinline__ float tanha(float x) {
    float y; asm("tanh.approx.f32 %0, %1;" : "=f"(y) : "f"(x)); return y;
}

#define MMA(d, a, b)                                                              \
    asm volatile("mma.sync.aligned.m16n8k16.row.col.f32.bf16.bf16.f32 "           \
                 "{%0,%1,%2,%3},{%4,%5,%6,%7},{%8,%9},{%0,%1,%2,%3};"             \
                 : "+f"((d)[0]), "+f"((d)[1]), "+f"((d)[2]), "+f"((d)[3])         \
                 : "r"((a)[0]), "r"((a)[1]), "r"((a)[2]), "r"((a)[3]),            \
                   "r"((b)[0]), "r"((b)[1]))

// ---------------------------------------------------------------------------
// Zero per-call accumulators (graph replays reuse device globals)
// ---------------------------------------------------------------------------
__global__ void k_zero() {
    int i = blockIdx.x * blockDim.x + threadIdx.x;
    int stride = gridDim.x * blockDim.x;
    for (int j = i; j < Mm * Nn; j += stride) g_hist[j] = 0;
    if (i < Mm) g_w[i] = 0.f;
}

// ---------------------------------------------------------------------------
// Split h into bf16 hi/lo
// ---------------------------------------------------------------------------
__global__ void k_split_h(const float* __restrict__ h) {
    int i = blockIdx.x * blockDim.x + threadIdx.x;  // over Nn*Fh/4
    if (i >= Nn * Fh / 4) return;
    float4 v = ((const float4*)h)[i];
    __nv_bfloat16 h0 = __float2bfloat16(v.x), h1 = __float2bfloat16(v.y);
    __nv_bfloat16 h2 = __float2bfloat16(v.z), h3 = __float2bfloat16(v.w);
    __nv_bfloat16 l0 = __float2bfloat16(v.x - __bfloat162float(h0));
    __nv_bfloat16 l1 = __float2bfloat16(v.y - __bfloat162float(h1));
    __nv_bfloat16 l2 = __float2bfloat16(v.z - __bfloat162float(h2));
    __nv_bfloat16 l3 = __float2bfloat16(v.w - __bfloat162float(h3));
    __nv_bfloat162* hp = (__nv_bfloat162*)g_h_hi;
    __nv_bfloat162* lp = (__nv_bfloat162*)g_h_lo;
    hp[2 * i] = __nv_bfloat162(h0, h1);  hp[2 * i + 1] = __nv_bfloat162(h2, h3);
    lp[2 * i] = __nv_bfloat162(l0, l1);  lp[2 * i + 1] = __nv_bfloat162(l2, l3);
}

// ---------------------------------------------------------------------------
// Split + transpose weights: fc_w [m][k][n] -> fwT [m][n][k]; w1 [k][n] -> w1T [n][k]
// ---------------------------------------------------------------------------
__global__ void k_split_w(const float* __restrict__ fc_w, const float* __restrict__ sem_w1) {
    int i = blockIdx.x * blockDim.x + threadIdx.x;
    int total1 = Mm * Fh * Fh;
    if (i < total1) {
        int m = i / (Fh * Fh);
        int r = i % (Fh * Fh);
        int k = r / Fh, n = r % Fh;
        float a = fc_w[i];
        __nv_bfloat16 hi = __float2bfloat16(a);
        __nv_bfloat16 lo = __float2bfloat16(a - __bfloat162float(hi));
        size_t o = (size_t)m * Fh * Fh + (size_t)n * Fh + k;
        g_fwT_hi[o] = hi; g_fwT_lo[o] = lo;
    } else if (i < total1 + Fh * HID) {
        int j = i - total1;
        int k = j / HID, n = j % HID;
        float a = sem_w1[j];
        __nv_bfloat16 hi = __float2bfloat16(a);
        __nv_bfloat16 lo = __float2bfloat16(a - __bfloat162float(hi));
        size_t o = (size_t)n * Fh + k;
        g_w1T_hi[o] = hi; g_w1T_lo[o] = lo;
    }
}

// ---------------------------------------------------------------------------
// feat[m] = h @ fc_w[m] via bf16 split mma.sync (3-term: hh + hl + lh)
// ---------------------------------------------------------------------------
__global__ __launch_bounds__(256) void k_gemm_feat() {
    __shared__ unsigned sA[2][2][1024];
    __shared__ unsigned sB[2][2][1024];

    int tid = threadIdx.x;
    int lane = tid & 31, warp = tid >> 5;
    int g = lane >> 2, t = lane & 3;
    int warp_m = warp >> 2, warp_n = warp & 3;
    int row0 = blockIdx.x * 128;
    int col0 = blockIdx.y * 128;
    int m = blockIdx.z;

    const unsigned* Ah = (const unsigned*)g_h_hi;
    const unsigned* Al = (const unsigned*)g_h_lo;
    const unsigned* Bh = (const unsigned*)(g_fwT_hi + (size_t)m * Fh * Fh);
    const unsigned* Bl = (const unsigned*)(g_fwT_lo + (size_t)m * Fh * Fh);

    int lr = tid >> 1;
    int lw = (tid & 1) * 4;

    float acc[4][4][4] = {};
    uint4 pa_h, pa_l, pb_h, pb_l;

    auto LOADG = [&](int ks) {
        int grow = row0 + lr;
        if (grow < Nn) {
            pa_h = *(const uint4*)(Ah + (size_t)grow * 128 + ks * 8 + lw);
            pa_l = *(const uint4*)(Al + (size_t)grow * 128 + ks * 8 + lw);
        } else {
            pa_h = make_uint4(0, 0, 0, 0); pa_l = make_uint4(0, 0, 0, 0);
        }
        pb_h = *(const uint4*)(Bh + (size_t)(col0 + lr) * 128 + ks * 8 + lw);
        pb_l = *(const uint4*)(Bl + (size_t)(col0 + lr) * 128 + ks * 8 + lw);
    };
    auto STORES = [&](int st) {
        int sbase = lr * 8;
        unsigned ah[4] = {pa_h.x, pa_h.y, pa_h.z, pa_h.w};
        unsigned al[4] = {pa_l.x, pa_l.y, pa_l.z, pa_l.w};
        unsigned bh[4] = {pb_h.x, pb_h.y, pb_h.z, pb_h.w};
        unsigned bl[4] = {pb_l.x, pb_l.y, pb_l.z, pb_l.w};
        #pragma unroll
        for (int q = 0; q < 4; q++) {
            int ws = (lw + q) ^ (lr & 7);
            sA[st][0][sbase + ws] = ah[q];
            sA[st][1][sbase + ws] = al[q];
            sB[st][0][sbase + ws] = bh[q];
            sB[st][1][sbase + ws] = bl[q];
        }
    };
    auto DOMMA = [&](int st) {
        unsigned a_h[4][4], a_l[4][4], b_h[4][2], b_l[4][2];
        #pragma unroll
        for (int mf = 0; mf < 4; mf++) {
            int r0 = warp_m * 64 + mf * 16 + g;
            int r1 = r0 + 8;
            int i00 = r0 * 8 + (t ^ (r0 & 7));
            int i10 = r1 * 8 + (t ^ (r1 & 7));
            int i01 = r0 * 8 + ((t + 4) ^ (r0 & 7));
            int i11 = r1 * 8 + ((t + 4) ^ (r1 & 7));
            a_h[mf][0] = sA[st][0][i00]; a_h[mf][1] = sA[st][0][i10];
            a_h[mf][2] = sA[st][0][i01]; a_h[mf][3] = sA[st][0][i11];
            a_l[mf][0] = sA[st][1][i00]; a_l[mf][1] = sA[st][1][i10];
            a_l[mf][2] = sA[st][1][i01]; a_l[mf][3] = sA[st][1][i11];
        }
        #pragma unroll
        for (int nf = 0; nf < 4; nf++) {
            int n = warp_n * 32 + nf * 8 + g;
            int j0 = n * 8 + (t ^ (n & 7));
            int j1 = n * 8 + ((t + 4) ^ (n & 7));
            b_h[nf][0] = sB[st][0][j0]; b_h[nf][1] = sB[st][0][j1];
            b_l[nf][0] = sB[st][1][j0]; b_l[nf][1] = sB[st][1][j1];
        }
        #pragma unroll
        for (int mf = 0; mf < 4; mf++)
            #pragma unroll
            for (int nf = 0; nf < 4; nf++) {
                MMA(acc[mf][nf], a_h[mf], b_h[nf]);
                MMA(acc[mf][nf], a_h[mf], b_l[nf]);
                MMA(acc[mf][nf], a_l[mf], b_h[nf]);
            }
    };

    LOADG(0); STORES(0); __syncthreads();
    for (int ks = 0; ks < 16; ks++) {
        int cur = ks & 1;
        if (ks < 15) LOADG(ks + 1);
        DOMMA(cur);
        __syncthreads();
        if (ks < 15) { STORES(cur ^ 1); __syncthreads(); }
    }

    float* C = g_feat + (size_t)m * Nn * Fh;
    #pragma unroll
    for (int mf = 0; mf < 4; mf++) {
        int r = row0 + warp_m * 64 + mf * 16 + g;
        #pragma unroll
        for (int nf = 0; nf < 4; nf++) {
            int c = col0 + warp_n * 32 + nf * 8 + 2 * t;
            if (r < Nn)
                *(float2*)&C[(size_t)r * 256 + c] = make_float2(acc[mf][nf][0], acc[mf][nf][1]);
            if (r + 8 < Nn)
                *(float2*)&C[(size_t)(r + 8) * 256 + c] = make_float2(acc[mf][nf][2], acc[mf][nf][3]);
        }
    }
}

// ---------------------------------------------------------------------------
// el/er: per (node, head) dot(feat, attn).  Warp per node.
// ---------------------------------------------------------------------------
__global__ void k_eler(const float* __restrict__ attn_l, const float* __restrict__ attn_r) {
    int m = blockIdx.z;
    __shared__ float al[256], ar[256];
    int tid = threadIdx.x;
    al[tid] = attn_l[m * 256 + tid];
    ar[tid] = attn_r[m * 256 + tid];
    __syncthreads();

    int warp = tid >> 5, lane = tid & 31;
    int node = blockIdx.x * 8 + warp;
    if (node >= Nn) return;

    const float4* f4 = (const float4*)(g_feat + (size_t)m * Nn * Fh + (size_t)node * 256 + lane * 8);
    float4 x0 = f4[0], x1 = f4[1];
    const float* alp = al + lane * 8;
    const float* arp = ar + lane * 8;
    float sl = x0.x * alp[0] + x0.y * alp[1] + x0.z * alp[2] + x0.w * alp[3]
             + x1.x * alp[4] + x1.y * alp[5] + x1.z * alp[6] + x1.w * alp[7];
    float sr = x0.x * arp[0] + x0.y * arp[1] + x0.z * arp[2] + x0.w * arp[3]
             + x1.x * arp[4] + x1.y * arp[5] + x1.z * arp[6] + x1.w * arp[7];
    sl += __shfl_xor_sync(0xffffffffu, sl, 1);
    sl += __shfl_xor_sync(0xffffffffu, sl, 2);
    sr += __shfl_xor_sync(0xffffffffu, sr, 1);
    sr += __shfl_xor_sync(0xffffffffu, sr, 2);
    if ((lane & 3) == 0) {
        int h = lane >> 2;
        g_el[(size_t)m * Nn * Hh + node * 8 + h] = sl;
        g_er[(size_t)m * Nn * Hh + node * 8 + h] = sr;
    }
}

// ---------------------------------------------------------------------------
// CSR build: histogram -> block scan -> block-sum scan -> fixup -> scatter
// ---------------------------------------------------------------------------
__global__ void k_hist(const int* __restrict__ dst_all) {
    int m = blockIdx.y;
    int e = blockIdx.x * blockDim.x + threadIdx.x;
    if (e < Ee) atomicAdd(&g_hist[m * Nn + dst_all[(size_t)m * Ee + e]], 1);
}

__global__ void k_scan1() {
    __shared__ int s[256];
    int m = blockIdx.y, tid = threadIdx.x;
    int i = blockIdx.x * 256 + tid;
    int v = (i < Nn) ? g_hist[m * Nn + i] : 0;
    s[tid] = v; __syncthreads();
    #pragma unroll
    for (int o = 1; o < 256; o <<= 1) {
        int t = (tid >= o) ? s[tid - o] : 0;
        __syncthreads();
        s[tid] += t;
        __syncthreads();
    }
    if (i < Nn) g_off[m * Nn + i] = s[tid] - v;
    if (tid == 255) g_bsum[m * 256 + blockIdx.x] = s[tid];
}

__global__ void k_scan2() {
    __shared__ int s[256];
    int m = blockIdx.x, tid = threadIdx.x;
    int v = (tid < SCANB) ? g_bsum[m * 256 + tid] : 0;
    s[tid] = v; __syncthreads();
    #pragma unroll
    for (int o = 1; o < 256; o <<= 1) {
        int t = (tid >= o) ? s[tid - o] : 0;
        __syncthreads();
        s[tid] += t;
        __syncthreads();
    }
    g_bsum[m * 256 + tid] = s[tid] - v;   // exclusive
}

__global__ void k_scan3() {
    int m = blockIdx.y, tid = threadIdx.x;
    int i = blockIdx.x * 256 + tid;
    if (i < Nn) {
        int o = g_off[m * Nn + i] + g_bsum[m * 256 + blockIdx.x];
        g_off[m * Nn + i] = o;
        g_cursor[m * Nn + i] = o;
    }
}

__global__ void k_scatter(const int* __restrict__ src_all, const int* __restrict__ dst_all) {
    int m = blockIdx.y;
    int e = blockIdx.x * blockDim.x + threadIdx.x;
    if (e >= Ee) return;
    int d = dst_all[(size_t)m * Ee + e];
    int p = atomicAdd(&g_cursor[m * Nn + d], 1);
    g_csrc[(size_t)m * Ee + p] = src_all[(size_t)m * Ee + e];
}

// ---------------------------------------------------------------------------
// Fused edge pass: warp per dst node. Accumulate unnormalized messages and
// esum in registers; epilogue: /esum, +bias, elu, write z fp32 + bf16 hi/lo.
// ---------------------------------------------------------------------------
__global__ __launch_bounds__(256) void k_pass(const float* __restrict__ bias, int m) {
    int warp = threadIdx.x >> 5, lane = threadIdx.x & 31;
    int d = blockIdx.x * 8 + warp;
    if (d >= Nn) return;

    int beg = g_off[m * Nn + d];
    int end = (d + 1 < Nn) ? g_off[m * Nn + d + 1] : Ee;

    const float* elb = g_el + (size_t)m * Nn * Hh;
    const float* erb = g_er + (size_t)m * Nn * Hh;
    const int*   cs  = g_csrc + (size_t)m * Ee;
    const float* F   = g_feat + (size_t)m * Nn * Fh;

    float er_h = (lane < 8) ? erb[(size_t)d * 8 + lane] : 0.f;

    float acc[8] = {};
    float esum = 0.f;

    #pragma unroll 4
    for (int j = beg; j < end; j++) {
        int s = cs[j];
        float ee = 0.f;
        if (lane < 8) {
            float x = elb[(size_t)s * 8 + lane] + er_h;
            x = x > 0.f ? x : 0.2f * x;
            ee = __expf(x);
            esum += ee;
        }
        float w = __shfl_sync(0xffffffffu, ee, lane >> 2);
        const float4* f4 = (const float4*)(F + (size_t)s * 256 + lane * 8);
        float4 a = f4[0], b = f4[1];
        acc[0] += w * a.x; acc[1] += w * a.y; acc[2] += w * a.z; acc[3] += w * a.w;
        acc[4] += w * b.x; acc[5] += w * b.y; acc[6] += w * b.z; acc[7] += w * b.w;
    }

    float es = __shfl_sync(0xffffffffu, esum, lane >> 2);
    float inv = 1.f / fmaxf(es, 1e-38f);

    const float4* bp = (const float4*)(bias + (size_t)m * 256 + lane * 8);
    float4 b0 = bp[0], b1 = bp[1];
    float r[8];
    r[0] = acc[0] * inv + b0.x; r[1] = acc[1] * inv + b0.y;
    r[2] = acc[2] * inv + b0.z; r[3] = acc[3] * inv + b0.w;
    r[4] = acc[4] * inv + b1.x; r[5] = acc[5] * inv + b1.y;
    r[6] = acc[6] * inv + b1.z; r[7] = acc[7] * inv + b1.w;
    #pragma unroll
    for (int i = 0; i < 8; i++) r[i] = r[i] > 0.f ? r[i] : expm1f(r[i]);

    size_t rowb = ((size_t)m * Nn + d) * 256 + lane * 8;
    float4* zp = (float4*)(g_z + rowb);
    zp[0] = make_float4(r[0], r[1], r[2], r[3]);
    zp[1] = make_float4(r[4], r[5], r[6], r[7]);

    __nv_bfloat16 hi[8]; float lo[8];
    #pragma unroll
    for (int i = 0; i < 8; i++) {
        hi[i] = __float2bfloat16(r[i]);
        lo[i] = r[i] - __bfloat162float(hi[i]);
    }
    __nv_bfloat162* hp = (__nv_bfloat162*)(g_z_hi + rowb);
    __nv_bfloat162* lp = (__nv_bfloat162*)(g_z_lo + rowb);
    #pragma unroll
    for (int i = 0; i < 4; i++) {
        hp[i] = __nv_bfloat162(hi[2 * i], hi[2 * i + 1]);
        lp[i] = __nv_bfloat162(__float2bfloat16(lo[2 * i]), __float2bfloat16(lo[2 * i + 1]));
    }
}

// ---------------------------------------------------------------------------
// Semantic GEMM with fused tanh/w2/row-reduction epilogue.
// ---------------------------------------------------------------------------
__global__ __launch_bounds__(256) void k_gemm_sem(const float* __restrict__ sem_b1,
                                                  const float* __restrict__ sem_w2) {
    __shared__ unsigned sA[2][2][1024];
    __shared__ unsigned sB[2][2][1024];
    __shared__ float s_rsum[128];
    __shared__ float s_mw[3];
    __shared__ float sb1[128], sw2[128];

    int tid = threadIdx.x;
    int lane = tid & 31, warp = tid >> 5;
    int g = lane >> 2, t = lane & 3;
    int warp_m = warp >> 2, warp_n = warp & 3;
    int row0 = blockIdx.x * 128;

    if (tid < 128) { s_rsum[tid] = 0.f; sb1[tid] = sem_b1[tid]; sw2[tid] = sem_w2[tid]; }
    if (tid < 3) s_mw[tid] = 0.f;

    const unsigned* Ah = (const unsigned*)g_z_hi;
    const unsigned* Al = (const unsigned*)g_z_lo;
    const unsigned* Bh = (const unsigned*)g_w1T_hi;
    const unsigned* Bl = (const unsigned*)g_w1T_lo;

    int lr = tid >> 1;
    int lw = (tid & 1) * 4;

    float acc[4][4][4] = {};
    uint4 pa_h, pa_l, pb_h, pb_l;

    auto LOADG = [&](int ks) {
        int grow = row0 + lr;
        if (grow < NZ) {
            pa_h = *(const uint4*)(Ah + (size_t)grow * 128 + ks * 8 + lw);
            pa_l = *(const uint4*)(Al + (size_t)grow * 128 + ks * 8 + lw);
        } else {
            pa_h = make_uint4(0, 0, 0, 0); pa_l = make_uint4(0, 0, 0, 0);
        }
        pb_h = *(const uint4*)(Bh + (size_t)lr * 128 + ks * 8 + lw);
        pb_l = *(const uint4*)(Bl + (size_t)lr * 128 + ks * 8 + lw);
    };
    auto STORES = [&](int st) {
        int sbase = lr * 8;
        unsigned ah[4] = {pa_h.x, pa_h.y, pa_h.z, pa_h.w};
        unsigned al[4] = {pa_l.x, pa_l.y, pa_l.z, pa_l.w};
        unsigned bh[4] = {pb_h.x, pb_h.y, pb_h.z, pb_h.w};
        unsigned bl[4] = {pb_l.x, pb_l.y, pb_l.z, pb_l.w};
        #pragma unroll
        for (int q = 0; q < 4; q++) {
            int ws = (lw + q) ^ (lr & 7);
            sA[st][0][sbase + ws] = ah[q];
            sA[st][1][sbase + ws] = al[q];
            sB[st][0][sbase + ws] = bh[q];
            sB[st][1][sbase + ws] = bl[q];
        }
    };
    auto DOMMA = [&](int st) {
        unsigned a_h[4][4], a_l[4][4], b_h[4][2], b_l[4][2];
        #pragma unroll
        for (int mf = 0; mf < 4; mf++) {
            int r0 = warp_m * 64 + mf * 16 + g;
            int r1 = r0 + 8;
            int i00 = r0 * 8 + (t ^ (r0 & 7));
            int i10 = r1 * 8 + (t ^ (r1 & 7));
            int i01 = r0 * 8 + ((t + 4) ^ (r0 & 7));
            int i11 = r1 * 8 + ((t + 4) ^ (r1 & 7));
            a_h[mf][0] = sA[st][0][i00]; a_h[mf][1] = sA[st][0][i10];
            a_h[mf][2] = sA[st][0][i01]; a_h[mf][3] = sA[st][0][i11];
            a_l[mf][0] = sA[st][1][i00]; a_l[mf][1] = sA[st][1][i10];
            a_l[mf][2] = sA[st][1][i01]; a_l[mf][3] = sA[st][1][i11];
        }
        #pragma unroll
        for (int nf = 0; nf < 4; nf++) {
            int n = warp_n * 32 + nf * 8 + g;
            int j0 = n * 8 + (t ^ (n & 7));
            int j1 = n * 8 + ((t + 4) ^ (n & 7));
            b_h[nf][0] = sB[st][0][j0]; b_h[nf][1] = sB[st][0][j1];
            b_l[nf][0] = sB[st][1][j0]; b_l[nf][1] = sB[st][1][j1];
        }
        #pragma unroll
        for (int mf = 0; mf < 4; mf++)
            #pragma unroll
            for (int nf = 0; nf < 4; nf++) {
                MMA(acc[mf][nf], a_h[mf], b_h[nf]);
                MMA(acc[mf][nf], a_h[mf], b_l[nf]);
                MMA(acc[mf][nf], a_l[mf], b_h[nf]);
            }
    };

    LOADG(0); STORES(0); __syncthreads();
    for (int ks = 0; ks < 16; ks++) {
        int cur = ks & 1;
        if (ks < 15) LOADG(ks + 1);
        DOMMA(cur);
        __syncthreads();
        if (ks < 15) { STORES(cur ^ 1); __syncthreads(); }
    }

    #pragma unroll
    for (int mf = 0; mf < 4; mf++) {
        float rsa = 0.f, rsb = 0.f;
        #pragma unroll
        for (int nf = 0; nf < 4; nf++) {
            int c = warp_n * 32 + nf * 8 + 2 * t;
            float b0 = sb1[c], b1v = sb1[c + 1];
            float w20 = sw2[c], w21 = sw2[c + 1];
            rsa += tanha(acc[mf][nf][0] + b0) * w20 + tanha(acc[mf][nf][1] + b1v) * w21;
            rsb += tanha(acc[mf][nf][2] + b0) * w20 + tanha(acc[mf][nf][3] + b1v) * w21;
        }
        rsa += __shfl_xor_sync(0xffffffffu, rsa, 1);
        rsa += __shfl_xor_sync(0xffffffffu, rsa, 2);
        rsb += __shfl_xor_sync(0xffffffffu, rsb, 1);
        rsb += __shfl_xor_sync(0xffffffffu, rsb, 2);
        if (t == 0) {
            atomicAdd(&s_rsum[warp_m * 64 + mf * 16 + g], rsa);
            atomicAdd(&s_rsum[warp_m * 64 + mf * 16 + g + 8], rsb);
        }
    }
    __syncthreads();
    if (tid < 128) {
        int r = row0 + tid;
        if (r < NZ) atomicAdd(&s_mw[r / Nn], s_rsum[tid]);
    }
    __syncthreads();
    if (tid < 3) atomicAdd(&g_w[tid], s_mw[tid]);
}

// ---------------------------------------------------------------------------
__global__ void k_aw() {
    float w0 = g_w[0] / (float)Nn;
    float w1 = g_w[1] / (float)Nn;
    float w2 = g_w[2] / (float)Nn;
    float mx = fmaxf(w0, fmaxf(w1, w2));
    float e0 = expf(w0 - mx), e1 = expf(w1 - mx), e2 = expf(w2 - mx);
    float s = e0 + e1 + e2;
    g_aw[0] = e0 / s; g_aw[1] = e1 / s; g_aw[2] = e2 / s;
}

__global__ void k_comb(float* __restrict__ out) {
    int i = blockIdx.x * blockDim.x + threadIdx.x;
    int total = Nn * (Fh / 4);
    if (i >= total) return;
    float a0 = g_aw[0], a1 = g_aw[1], a2 = g_aw[2];
    const float4* z4 = (const float4*)g_z;
    float4 v0 = z4[i];
    float4 v1 = z4[i + (size_t)Nn * Fh / 4];
    float4 v2 = z4[i + 2 * (size_t)Nn * Fh / 4];
    float4 o;
    o.x = v0.x * a0 + v1.x * a1 + v2.x * a2;
    o.y = v0.y * a0 + v1.y * a1 + v2.y * a2;
    o.z = v0.z * a0 + v1.z * a1 + v2.z * a2;
    o.w = v0.w * a0 + v1.w * a1 + v2.w * a2;
    ((float4*)out)[i] = o;
}

// ---------------------------------------------------------------------------
extern "C" void kernel_launch(void* const* d_in, const int* in_sizes, int n_in,
                              void* d_out, int out_size) {
    const float* h      = (const float*)d_in[0];
    const int*   src    = (const int*)d_in[1];
    const int*   dst    = (const int*)d_in[2];
    const float* fc_w   = (const float*)d_in[3];
    const float* attn_l = (const float*)d_in[4];
    const float* attn_r = (const float*)d_in[5];
    const float* bias   = (const float*)d_in[6];
    const float* sem_w1 = (const float*)d_in[7];
    const float* sem_b1 = (const float*)d_in[8];
    const float* sem_w2 = (const float*)d_in[9];
    float* out = (float*)d_out;

    k_zero<<<256, 256>>>();
    k_split_h<<<(Nn * Fh / 4 + 255) / 256, 256>>>(h);
    k_split_w<<<(Mm * Fh * Fh + Fh * HID + 255) / 256, 256>>>(fc_w, sem_w1);

    // CSR build (overlaps conceptually with GEMM in the stream order)
    k_hist<<<dim3((Ee + 255) / 256, Mm), 256>>>(dst);
    k_scan1<<<dim3(SCANB, Mm), 256>>>();
    k_scan2<<<Mm, 256>>>();
    k_scan3<<<dim3(SCANB, Mm), 256>>>();
    k_scatter<<<dim3((Ee + 255) / 256, Mm), 256>>>(src, dst);

    dim3 gfeat((Nn + 127) / 128, Fh / 128, Mm);
    k_gemm_feat<<<gfeat, 256>>>();

    k_eler<<<dim3((Nn + 7) / 8, 1, Mm), 256>>>(attn_l, attn_r);

    for (int m = 0; m < Mm; m++)
        k_pass<<<(Nn + 7) / 8, 256>>>(bias, m);

    k_gemm_sem<<<(NZ + 127) / 128, 256>>>(sem_b1, sem_w2);
    k_aw<<<1, 1>>>();
    k_comb<<<(Nn * (Fh / 4) + 255) / 256, 256>>>(out);
}

// round 8
// speedup vs baseline: 2.7122x; 1.2187x over previous
#include <cuda_runtime.h>
#include <cuda_bf16.h>
#include <math.h>

#define Nn 50000
#define Ee 800000
#define Mm 3
#define Fh 256   // H*D
#define Hh 8
#define HID 128
#define NZ (Mm * Nn)        // 150000 rows of z
#define SCANB 196           // ceil(Nn/256)

__device__ __align__(16) float g_feat[(size_t)Mm * Nn * Fh];
__device__ __align__(16) float g_z[(size_t)Mm * Nn * Fh];
__device__ __align__(16) float g_el[(size_t)Mm * Nn * Hh];
__device__ __align__(16) float g_er[(size_t)Mm * Nn * Hh];
__device__ float g_w[Mm];
__device__ float g_aw[Mm];

// CSR scratch
__device__ int g_hist[Mm * Nn];
__device__ int g_off[Mm * Nn];
__device__ int g_bsum[Mm * 256];
__device__ int g_cursor[Mm * Nn];
__device__ int g_csrc[(size_t)Mm * Ee];

// bf16 split buffers
__device__ __align__(16) __nv_bfloat16 g_h_hi[(size_t)Nn * Fh];
__device__ __align__(16) __nv_bfloat16 g_h_lo[(size_t)Nn * Fh];
__device__ __align__(16) __nv_bfloat16 g_fwT_hi[(size_t)Mm * Fh * Fh]; // [m][n][k]
__device__ __align__(16) __nv_bfloat16 g_fwT_lo[(size_t)Mm * Fh * Fh];
__device__ __align__(16) __nv_bfloat16 g_w1T_hi[HID * Fh];             // [n][k]
__device__ __align__(16) __nv_bfloat16 g_w1T_lo[HID * Fh];
__device__ __align__(16) __nv_bfloat16 g_z_hi[(size_t)NZ * Fh];
__device__ __align__(16) __nv_bfloat16 g_z_lo[(size_t)NZ * Fh];

__device__ __forceinline__ float tanha(float x) {
    float y; asm("tanh.approx.f32 %0, %1;" : "=f"(y) : "f"(x)); return y;
}

#define MMA(d, a, b)                                                              \
    asm volatile("mma.sync.aligned.m16n8k16.row.col.f32.bf16.bf16.f32 "           \
                 "{%0,%1,%2,%3},{%4,%5,%6,%7},{%8,%9},{%0,%1,%2,%3};"             \
                 : "+f"((d)[0]), "+f"((d)[1]), "+f"((d)[2]), "+f"((d)[3])         \
                 : "r"((a)[0]), "r"((a)[1]), "r"((a)[2]), "r"((a)[3]),            \
                   "r"((b)[0]), "r"((b)[1]))

#define LDSM4(r, addr)                                                            \
    asm volatile("ldmatrix.sync.aligned.m8n8.x4.shared.b16 {%0,%1,%2,%3}, [%4];"  \
                 : "=r"((r)[0]), "=r"((r)[1]), "=r"((r)[2]), "=r"((r)[3])         \
                 : "r"(addr))

// chunk swizzle: 16B chunks, 2 per 32B row; conflict-free for STS.128 and LDSM
__device__ __forceinline__ int chunk_idx(int r, int c) {
    return r * 2 + (c ^ ((r >> 2) & 1));
}

// ---------------------------------------------------------------------------
__global__ void k_zero() {
    int i = blockIdx.x * blockDim.x + threadIdx.x;
    int stride = gridDim.x * blockDim.x;
    for (int j = i; j < Mm * Nn; j += stride) g_hist[j] = 0;
    if (i < Mm) g_w[i] = 0.f;
}

// ---------------------------------------------------------------------------
__global__ void k_split_h(const float* __restrict__ h) {
    int i = blockIdx.x * blockDim.x + threadIdx.x;
    if (i >= Nn * Fh / 4) return;
    float4 v = ((const float4*)h)[i];
    __nv_bfloat16 h0 = __float2bfloat16(v.x), h1 = __float2bfloat16(v.y);
    __nv_bfloat16 h2 = __float2bfloat16(v.z), h3 = __float2bfloat16(v.w);
    __nv_bfloat16 l0 = __float2bfloat16(v.x - __bfloat162float(h0));
    __nv_bfloat16 l1 = __float2bfloat16(v.y - __bfloat162float(h1));
    __nv_bfloat16 l2 = __float2bfloat16(v.z - __bfloat162float(h2));
    __nv_bfloat16 l3 = __float2bfloat16(v.w - __bfloat162float(h3));
    __nv_bfloat162* hp = (__nv_bfloat162*)g_h_hi;
    __nv_bfloat162* lp = (__nv_bfloat162*)g_h_lo;
    hp[2 * i] = __nv_bfloat162(h0, h1);  hp[2 * i + 1] = __nv_bfloat162(h2, h3);
    lp[2 * i] = __nv_bfloat162(l0, l1);  lp[2 * i + 1] = __nv_bfloat162(l2, l3);
}

// ---------------------------------------------------------------------------
__global__ void k_split_w(const float* __restrict__ fc_w, const float* __restrict__ sem_w1) {
    int i = blockIdx.x * blockDim.x + threadIdx.x;
    int total1 = Mm * Fh * Fh;
    if (i < total1) {
        int m = i / (Fh * Fh);
        int r = i % (Fh * Fh);
        int k = r / Fh, n = r % Fh;
        float a = fc_w[i];
        __nv_bfloat16 hi = __float2bfloat16(a);
        __nv_bfloat16 lo = __float2bfloat16(a - __bfloat162float(hi));
        size_t o = (size_t)m * Fh * Fh + (size_t)n * Fh + k;
        g_fwT_hi[o] = hi; g_fwT_lo[o] = lo;
    } else if (i < total1 + Fh * HID) {
        int j = i - total1;
        int k = j / HID, n = j % HID;
        float a = sem_w1[j];
        __nv_bfloat16 hi = __float2bfloat16(a);
        __nv_bfloat16 lo = __float2bfloat16(a - __bfloat162float(hi));
        size_t o = (size_t)n * Fh + k;
        g_w1T_hi[o] = hi; g_w1T_lo[o] = lo;
    }
}

// ---------------------------------------------------------------------------
// feat[m] = h @ fc_w[m]: bf16 split mma with ldmatrix fragment loads.
// Epilogue also computes el/er (each warp's 32 cols == exactly one head).
// ---------------------------------------------------------------------------
__global__ __launch_bounds__(256) void k_gemm_feat(const float* __restrict__ attn_l,
                                                   const float* __restrict__ attn_r) {
    __shared__ uint4 sA[2][2][256];
    __shared__ uint4 sB[2][2][256];

    int tid = threadIdx.x;
    int lane = tid & 31, warp = tid >> 5;
    int g = lane >> 2, t = lane & 3;
    int warp_m = warp >> 2, warp_n = warp & 3;
    int row0 = blockIdx.x * 128;
    int col0 = blockIdx.y * 128;
    int m = blockIdx.z;

    const unsigned* Ah = (const unsigned*)g_h_hi;
    const unsigned* Al = (const unsigned*)g_h_lo;
    const unsigned* Bh = (const unsigned*)(g_fwT_hi + (size_t)m * Fh * Fh);
    const unsigned* Bl = (const unsigned*)(g_fwT_lo + (size_t)m * Fh * Fh);

    int lr = tid >> 1;         // tile row 0..127
    int ch = tid & 1;          // 16B chunk 0/1

    float acc[4][4][4] = {};
    uint4 pa_h, pa_l, pb_h, pb_l;

    auto LOADG = [&](int ks) {
        int grow = row0 + lr;
        int koff = ks * 8 + ch * 4;
        if (grow < Nn) {
            pa_h = *(const uint4*)(Ah + (size_t)grow * 128 + koff);
            pa_l = *(const uint4*)(Al + (size_t)grow * 128 + koff);
        } else {
            pa_h = make_uint4(0, 0, 0, 0); pa_l = make_uint4(0, 0, 0, 0);
        }
        pb_h = *(const uint4*)(Bh + (size_t)(col0 + lr) * 128 + koff);
        pb_l = *(const uint4*)(Bl + (size_t)(col0 + lr) * 128 + koff);
    };
    auto STORES = [&](int st) {
        int ci = chunk_idx(lr, ch);
        sA[st][0][ci] = pa_h;
        sA[st][1][ci] = pa_l;
        sB[st][0][ci] = pb_h;
        sB[st][1][ci] = pb_l;
    };
    int arow = warp_m * 64 + (lane & 15);
    int ac = lane >> 4;
    unsigned aoff = (unsigned)chunk_idx(arow, ac) * 16;
    int ngrp = lane >> 3;
    int nrow = warp_n * 32 + ((ngrp >> 1) << 3) + (lane & 7);
    int nc = ngrp & 1;
    unsigned boff = (unsigned)chunk_idx(nrow, nc) * 16;

    auto DOMMA = [&](int st) {
        unsigned bA0 = (unsigned)__cvta_generic_to_shared(&sA[st][0][0]);
        unsigned bA1 = (unsigned)__cvta_generic_to_shared(&sA[st][1][0]);
        unsigned bB0 = (unsigned)__cvta_generic_to_shared(&sB[st][0][0]);
        unsigned bB1 = (unsigned)__cvta_generic_to_shared(&sB[st][1][0]);
        unsigned a_h[4][4], a_l[4][4], b_h[2][4], b_l[2][4];
        #pragma unroll
        for (int mf = 0; mf < 4; mf++) {
            LDSM4(a_h[mf], bA0 + aoff + mf * 512);
            LDSM4(a_l[mf], bA1 + aoff + mf * 512);
        }
        #pragma unroll
        for (int j = 0; j < 2; j++) {
            LDSM4(b_h[j], bB0 + boff + j * 512);
            LDSM4(b_l[j], bB1 + boff + j * 512);
        }
        #pragma unroll
        for (int mf = 0; mf < 4; mf++)
            #pragma unroll
            for (int nf = 0; nf < 4; nf++) {
                unsigned* bh = &b_h[nf >> 1][(nf & 1) * 2];
                unsigned* bl = &b_l[nf >> 1][(nf & 1) * 2];
                MMA(acc[mf][nf], a_h[mf], bh);
                MMA(acc[mf][nf], a_h[mf], bl);
                MMA(acc[mf][nf], a_l[mf], bh);
            }
    };

    LOADG(0); STORES(0); __syncthreads();
    for (int ks = 0; ks < 16; ks++) {
        int cur = ks & 1;
        if (ks < 15) LOADG(ks + 1);
        DOMMA(cur);
        __syncthreads();
        if (ks < 15) { STORES(cur ^ 1); __syncthreads(); }
    }

    // --- epilogue: store feat; compute el/er for this warp's head ---
    int head = blockIdx.y * 4 + warp_n;
    float alv[8], arv[8];
    #pragma unroll
    for (int nf = 0; nf < 4; nf++) {
        int c = head * 32 + nf * 8 + 2 * t;
        alv[nf * 2]     = attn_l[m * 256 + c];
        alv[nf * 2 + 1] = attn_l[m * 256 + c + 1];
        arv[nf * 2]     = attn_r[m * 256 + c];
        arv[nf * 2 + 1] = attn_r[m * 256 + c + 1];
    }

    float* C = g_feat + (size_t)m * Nn * Fh;
    #pragma unroll
    for (int mf = 0; mf < 4; mf++) {
        int r = row0 + warp_m * 64 + mf * 16 + g;
        float e0 = 0.f, e1 = 0.f, f0 = 0.f, f1 = 0.f;
        #pragma unroll
        for (int nf = 0; nf < 4; nf++) {
            int c = col0 + warp_n * 32 + nf * 8 + 2 * t;
            if (r < Nn)
                *(float2*)&C[(size_t)r * 256 + c] = make_float2(acc[mf][nf][0], acc[mf][nf][1]);
            if (r + 8 < Nn)
                *(float2*)&C[(size_t)(r + 8) * 256 + c] = make_float2(acc[mf][nf][2], acc[mf][nf][3]);
            e0 += acc[mf][nf][0] * alv[nf * 2] + acc[mf][nf][1] * alv[nf * 2 + 1];
            e1 += acc[mf][nf][2] * alv[nf * 2] + acc[mf][nf][3] * alv[nf * 2 + 1];
            f0 += acc[mf][nf][0] * arv[nf * 2] + acc[mf][nf][1] * arv[nf * 2 + 1];
            f1 += acc[mf][nf][2] * arv[nf * 2] + acc[mf][nf][3] * arv[nf * 2 + 1];
        }
        e0 += __shfl_xor_sync(0xffffffffu, e0, 1); e0 += __shfl_xor_sync(0xffffffffu, e0, 2);
        e1 += __shfl_xor_sync(0xffffffffu, e1, 1); e1 += __shfl_xor_sync(0xffffffffu, e1, 2);
        f0 += __shfl_xor_sync(0xffffffffu, f0, 1); f0 += __shfl_xor_sync(0xffffffffu, f0, 2);
        f1 += __shfl_xor_sync(0xffffffffu, f1, 1); f1 += __shfl_xor_sync(0xffffffffu, f1, 2);
        if (t == 0) {
            if (r < Nn) {
                g_el[((size_t)m * Nn + r) * 8 + head] = e0;
                g_er[((size_t)m * Nn + r) * 8 + head] = f0;
            }
            if (r + 8 < Nn) {
                g_el[((size_t)m * Nn + r + 8) * 8 + head] = e1;
                g_er[((size_t)m * Nn + r + 8) * 8 + head] = f1;
            }
        }
    }
}

// ---------------------------------------------------------------------------
// CSR build: histogram -> block scan -> block-sum scan -> fixup -> scatter
// ---------------------------------------------------------------------------
__global__ void k_hist(const int* __restrict__ dst_all) {
    int m = blockIdx.y;
    int e = blockIdx.x * blockDim.x + threadIdx.x;
    if (e < Ee) atomicAdd(&g_hist[m * Nn + dst_all[(size_t)m * Ee + e]], 1);
}

__global__ void k_scan1() {
    __shared__ int s[256];
    int m = blockIdx.y, tid = threadIdx.x;
    int i = blockIdx.x * 256 + tid;
    int v = (i < Nn) ? g_hist[m * Nn + i] : 0;
    s[tid] = v; __syncthreads();
    #pragma unroll
    for (int o = 1; o < 256; o <<= 1) {
        int t = (tid >= o) ? s[tid - o] : 0;
        __syncthreads();
        s[tid] += t;
        __syncthreads();
    }
    if (i < Nn) g_off[m * Nn + i] = s[tid] - v;
    if (tid == 255) g_bsum[m * 256 + blockIdx.x] = s[tid];
}

__global__ void k_scan2() {
    __shared__ int s[256];
    int m = blockIdx.x, tid = threadIdx.x;
    int v = (tid < SCANB) ? g_bsum[m * 256 + tid] : 0;
    s[tid] = v; __syncthreads();
    #pragma unroll
    for (int o = 1; o < 256; o <<= 1) {
        int t = (tid >= o) ? s[tid - o] : 0;
        __syncthreads();
        s[tid] += t;
        __syncthreads();
    }
    g_bsum[m * 256 + tid] = s[tid] - v;
}

__global__ void k_scan3() {
    int m = blockIdx.y, tid = threadIdx.x;
    int i = blockIdx.x * 256 + tid;
    if (i < Nn) {
        int o = g_off[m * Nn + i] + g_bsum[m * 256 + blockIdx.x];
        g_off[m * Nn + i] = o;
        g_cursor[m * Nn + i] = o;
    }
}

__global__ void k_scatter(const int* __restrict__ src_all, const int* __restrict__ dst_all) {
    int m = blockIdx.y;
    int e = blockIdx.x * blockDim.x + threadIdx.x;
    if (e >= Ee) return;
    int d = dst_all[(size_t)m * Ee + e];
    int p = atomicAdd(&g_cursor[m * Nn + d], 1);
    g_csrc[(size_t)m * Ee + p] = src_all[(size_t)m * Ee + e];
}

// ---------------------------------------------------------------------------
// Fused edge pass: warp per dst node.
// ---------------------------------------------------------------------------
__global__ __launch_bounds__(256) void k_pass(const float* __restrict__ bias, int m) {
    int warp = threadIdx.x >> 5, lane = threadIdx.x & 31;
    int d = blockIdx.x * 8 + warp;
    if (d >= Nn) return;

    int beg = g_off[m * Nn + d];
    int end = (d + 1 < Nn) ? g_off[m * Nn + d + 1] : Ee;

    const float* elb = g_el + (size_t)m * Nn * Hh;
    const float* erb = g_er + (size_t)m * Nn * Hh;
    const int*   cs  = g_csrc + (size_t)m * Ee;
    const float* F   = g_feat + (size_t)m * Nn * Fh;

    float er_h = (lane < 8) ? erb[(size_t)d * 8 + lane] : 0.f;

    float acc[8] = {};
    float esum = 0.f;

    #pragma unroll 4
    for (int j = beg; j < end; j++) {
        int s = cs[j];
        float ee = 0.f;
        if (lane < 8) {
            float x = elb[(size_t)s * 8 + lane] + er_h;
            x = x > 0.f ? x : 0.2f * x;
            ee = __expf(x);
            esum += ee;
        }
        float w = __shfl_sync(0xffffffffu, ee, lane >> 2);
        const float4* f4 = (const float4*)(F + (size_t)s * 256 + lane * 8);
        float4 a = f4[0], b = f4[1];
        acc[0] += w * a.x; acc[1] += w * a.y; acc[2] += w * a.z; acc[3] += w * a.w;
        acc[4] += w * b.x; acc[5] += w * b.y; acc[6] += w * b.z; acc[7] += w * b.w;
    }

    float es = __shfl_sync(0xffffffffu, esum, lane >> 2);
    float inv = 1.f / fmaxf(es, 1e-38f);

    const float4* bp = (const float4*)(bias + (size_t)m * 256 + lane * 8);
    float4 b0 = bp[0], b1 = bp[1];
    float r[8];
    r[0] = acc[0] * inv + b0.x; r[1] = acc[1] * inv + b0.y;
    r[2] = acc[2] * inv + b0.z; r[3] = acc[3] * inv + b0.w;
    r[4] = acc[4] * inv + b1.x; r[5] = acc[5] * inv + b1.y;
    r[6] = acc[6] * inv + b1.z; r[7] = acc[7] * inv + b1.w;
    #pragma unroll
    for (int i = 0; i < 8; i++) r[i] = r[i] > 0.f ? r[i] : expm1f(r[i]);

    size_t rowb = ((size_t)m * Nn + d) * 256 + lane * 8;
    float4* zp = (float4*)(g_z + rowb);
    zp[0] = make_float4(r[0], r[1], r[2], r[3]);
    zp[1] = make_float4(r[4], r[5], r[6], r[7]);

    __nv_bfloat16 hi[8]; float lo[8];
    #pragma unroll
    for (int i = 0; i < 8; i++) {
        hi[i] = __float2bfloat16(r[i]);
        lo[i] = r[i] - __bfloat162float(hi[i]);
    }
    __nv_bfloat162* hp = (__nv_bfloat162*)(g_z_hi + rowb);
    __nv_bfloat162* lp = (__nv_bfloat162*)(g_z_lo + rowb);
    #pragma unroll
    for (int i = 0; i < 4; i++) {
        hp[i] = __nv_bfloat162(hi[2 * i], hi[2 * i + 1]);
        lp[i] = __nv_bfloat162(__float2bfloat16(lo[2 * i]), __float2bfloat16(lo[2 * i + 1]));
    }
}

// ---------------------------------------------------------------------------
// Semantic GEMM (ldmatrix): fused tanh/w2/row-reduction epilogue.
// ---------------------------------------------------------------------------
__global__ __launch_bounds__(256) void k_gemm_sem(const float* __restrict__ sem_b1,
                                                  const float* __restrict__ sem_w2) {
    __shared__ uint4 sA[2][2][256];
    __shared__ uint4 sB[2][2][256];
    __shared__ float s_rsum[128];
    __shared__ float s_mw[3];
    __shared__ float sb1[128], sw2[128];

    int tid = threadIdx.x;
    int lane = tid & 31, warp = tid >> 5;
    int g = lane >> 2, t = lane & 3;
    int warp_m = warp >> 2, warp_n = warp & 3;
    int row0 = blockIdx.x * 128;

    if (tid < 128) { s_rsum[tid] = 0.f; sb1[tid] = sem_b1[tid]; sw2[tid] = sem_w2[tid]; }
    if (tid < 3) s_mw[tid] = 0.f;

    const unsigned* Ah = (const unsigned*)g_z_hi;
    const unsigned* Al = (const unsigned*)g_z_lo;
    const unsigned* Bh = (const unsigned*)g_w1T_hi;
    const unsigned* Bl = (const unsigned*)g_w1T_lo;

    int lr = tid >> 1;
    int ch = tid & 1;

    float acc[4][4][4] = {};
    uint4 pa_h, pa_l, pb_h, pb_l;

    auto LOADG = [&](int ks) {
        int grow = row0 + lr;
        int koff = ks * 8 + ch * 4;
        if (grow < NZ) {
            pa_h = *(const uint4*)(Ah + (size_t)grow * 128 + koff);
            pa_l = *(const uint4*)(Al + (size_t)grow * 128 + koff);
        } else {
            pa_h = make_uint4(0, 0, 0, 0); pa_l = make_uint4(0, 0, 0, 0);
        }
        pb_h = *(const uint4*)(Bh + (size_t)lr * 128 + koff);
        pb_l = *(const uint4*)(Bl + (size_t)lr * 128 + koff);
    };
    auto STORES = [&](int st) {
        int ci = chunk_idx(lr, ch);
        sA[st][0][ci] = pa_h;
        sA[st][1][ci] = pa_l;
        sB[st][0][ci] = pb_h;
        sB[st][1][ci] = pb_l;
    };
    int arow = warp_m * 64 + (lane & 15);
    int ac = lane >> 4;
    unsigned aoff = (unsigned)chunk_idx(arow, ac) * 16;
    int ngrp = lane >> 3;
    int nrow = warp_n * 32 + ((ngrp >> 1) << 3) + (lane & 7);
    int nc = ngrp & 1;
    unsigned boff = (unsigned)chunk_idx(nrow, nc) * 16;

    auto DOMMA = [&](int st) {
        unsigned bA0 = (unsigned)__cvta_generic_to_shared(&sA[st][0][0]);
        unsigned bA1 = (unsigned)__cvta_generic_to_shared(&sA[st][1][0]);
        unsigned bB0 = (unsigned)__cvta_generic_to_shared(&sB[st][0][0]);
        unsigned bB1 = (unsigned)__cvta_generic_to_shared(&sB[st][1][0]);
        unsigned a_h[4][4], a_l[4][4], b_h[2][4], b_l[2][4];
        #pragma unroll
        for (int mf = 0; mf < 4; mf++) {
            LDSM4(a_h[mf], bA0 + aoff + mf * 512);
            LDSM4(a_l[mf], bA1 + aoff + mf * 512);
        }
        #pragma unroll
        for (int j = 0; j < 2; j++) {
            LDSM4(b_h[j], bB0 + boff + j * 512);
            LDSM4(b_l[j], bB1 + boff + j * 512);
        }
        #pragma unroll
        for (int mf = 0; mf < 4; mf++)
            #pragma unroll
            for (int nf = 0; nf < 4; nf++) {
                unsigned* bh = &b_h[nf >> 1][(nf & 1) * 2];
                unsigned* bl = &b_l[nf >> 1][(nf & 1) * 2];
                MMA(acc[mf][nf], a_h[mf], bh);
                MMA(acc[mf][nf], a_h[mf], bl);
                MMA(acc[mf][nf], a_l[mf], bh);
            }
    };

    LOADG(0); STORES(0); __syncthreads();
    for (int ks = 0; ks < 16; ks++) {
        int cur = ks & 1;
        if (ks < 15) LOADG(ks + 1);
        DOMMA(cur);
        __syncthreads();
        if (ks < 15) { STORES(cur ^ 1); __syncthreads(); }
    }

    #pragma unroll
    for (int mf = 0; mf < 4; mf++) {
        float rsa = 0.f, rsb = 0.f;
        #pragma unroll
        for (int nf = 0; nf < 4; nf++) {
            int c = warp_n * 32 + nf * 8 + 2 * t;
            float b0 = sb1[c], b1v = sb1[c + 1];
            float w20 = sw2[c], w21 = sw2[c + 1];
            rsa += tanha(acc[mf][nf][0] + b0) * w20 + tanha(acc[mf][nf][1] + b1v) * w21;
            rsb += tanha(acc[mf][nf][2] + b0) * w20 + tanha(acc[mf][nf][3] + b1v) * w21;
        }
        rsa += __shfl_xor_sync(0xffffffffu, rsa, 1);
        rsa += __shfl_xor_sync(0xffffffffu, rsa, 2);
        rsb += __shfl_xor_sync(0xffffffffu, rsb, 1);
        rsb += __shfl_xor_sync(0xffffffffu, rsb, 2);
        if (t == 0) {
            atomicAdd(&s_rsum[warp_m * 64 + mf * 16 + g], rsa);
            atomicAdd(&s_rsum[warp_m * 64 + mf * 16 + g + 8], rsb);
        }
    }
    __syncthreads();
    if (tid < 128) {
        int r = row0 + tid;
        if (r < NZ) atomicAdd(&s_mw[r / Nn], s_rsum[tid]);
    }
    __syncthreads();
    if (tid < 3) atomicAdd(&g_w[tid], s_mw[tid]);
}

// ---------------------------------------------------------------------------
__global__ void k_aw() {
    float w0 = g_w[0] / (float)Nn;
    float w1 = g_w[1] / (float)Nn;
    float w2 = g_w[2] / (float)Nn;
    float mx = fmaxf(w0, fmaxf(w1, w2));
    float e0 = expf(w0 - mx), e1 = expf(w1 - mx), e2 = expf(w2 - mx);
    float s = e0 + e1 + e2;
    g_aw[0] = e0 / s; g_aw[1] = e1 / s; g_aw[2] = e2 / s;
}

__global__ void k_comb(float* __restrict__ out) {
    int i = blockIdx.x * blockDim.x + threadIdx.x;
    int total = Nn * (Fh / 4);
    if (i >= total) return;
    float a0 = g_aw[0], a1 = g_aw[1], a2 = g_aw[2];
    const float4* z4 = (const float4*)g_z;
    float4 v0 = z4[i];
    float4 v1 = z4[i + (size_t)Nn * Fh / 4];
    float4 v2 = z4[i + 2 * (size_t)Nn * Fh / 4];
    float4 o;
    o.x = v0.x * a0 + v1.x * a1 + v2.x * a2;
    o.y = v0.y * a0 + v1.y * a1 + v2.y * a2;
    o.z = v0.z * a0 + v1.z * a1 + v2.z * a2;
    o.w = v0.w * a0 + v1.w * a1 + v2.w * a2;
    ((float4*)out)[i] = o;
}

// ---------------------------------------------------------------------------
extern "C" void kernel_launch(void* const* d_in, const int* in_sizes, int n_in,
                              void* d_out, int out_size) {
    const float* h      = (const float*)d_in[0];
    const int*   src    = (const int*)d_in[1];
    const int*   dst    = (const int*)d_in[2];
    const float* fc_w   = (const float*)d_in[3];
    const float* attn_l = (const float*)d_in[4];
    const float* attn_r = (const float*)d_in[5];
    const float* bias   = (const float*)d_in[6];
    const float* sem_w1 = (const float*)d_in[7];
    const float* sem_b1 = (const float*)d_in[8];
    const float* sem_w2 = (const float*)d_in[9];
    float* out = (float*)d_out;

    k_zero<<<256, 256>>>();
    k_split_h<<<(Nn * Fh / 4 + 255) / 256, 256>>>(h);
    k_split_w<<<(Mm * Fh * Fh + Fh * HID + 255) / 256, 256>>>(fc_w, sem_w1);

    k_hist<<<dim3((Ee + 255) / 256, Mm), 256>>>(dst);
    k_scan1<<<dim3(SCANB, Mm), 256>>>();
    k_scan2<<<Mm, 256>>>();
    k_scan3<<<dim3(SCANB, Mm), 256>>>();
    k_scatter<<<dim3((Ee + 255) / 256, Mm), 256>>>(src, dst);

    dim3 gfeat((Nn + 127) / 128, Fh / 128, Mm);
    k_gemm_feat<<<gfeat, 256>>>(attn_l, attn_r);

    for (int m = 0; m < Mm; m++)
        k_pass<<<(Nn + 7) / 8, 256>>>(bias, m);

    k_gemm_sem<<<(NZ + 127) / 128, 256>>>(sem_b1, sem_w2);
    k_aw<<<1, 1>>>();
    k_comb<<<(Nn * (Fh / 4) + 255) / 256, 256>>>(out);
}

// round 9
// speedup vs baseline: 2.9440x; 1.0855x over previous
#include <cuda_runtime.h>
#include <cuda_fp16.h>
#include <math.h>

#define Nn 50000
#define Ee 800000
#define Mm 3
#define Fh 256   // H*D
#define Hh 8
#define HID 128
#define NZ (Mm * Nn)        // 150000 rows of z
#define SCANB 196           // ceil(Nn/256)

__device__ __align__(16) __half g_feat16[(size_t)Mm * Nn * Fh];
__device__ __align__(16) float  g_z[(size_t)Mm * Nn * Fh];
__device__ __align__(16) float  g_el[(size_t)Mm * Nn * Hh];
__device__ __align__(16) float  g_er[(size_t)Mm * Nn * Hh];
__device__ float g_w[Mm];
__device__ float g_aw[Mm];

// CSR scratch
__device__ int g_hist[Mm * Nn];
__device__ int g_off[Mm * Nn];
__device__ int g_bsum[Mm * 256];
__device__ int g_cursor[Mm * Nn];
__device__ int g_csrc[(size_t)Mm * Ee];

// fp16 hi/lo split weights (pre-transposed to [n][k])
__device__ __align__(16) __half g_fwT_hi[(size_t)Mm * Fh * Fh];
__device__ __align__(16) __half g_fwT_lo[(size_t)Mm * Fh * Fh];
__device__ __align__(16) __half g_w1T_hi[HID * Fh];
__device__ __align__(16) __half g_w1T_lo[HID * Fh];

__device__ __forceinline__ float tanha(float x) {
    float y; asm("tanh.approx.f32 %0, %1;" : "=f"(y) : "f"(x)); return y;
}

#define MMA(d, a, b)                                                              \
    asm volatile("mma.sync.aligned.m16n8k16.row.col.f32.f16.f16.f32 "             \
                 "{%0,%1,%2,%3},{%4,%5,%6,%7},{%8,%9},{%0,%1,%2,%3};"             \
                 : "+f"((d)[0]), "+f"((d)[1]), "+f"((d)[2]), "+f"((d)[3])         \
                 : "r"((a)[0]), "r"((a)[1]), "r"((a)[2]), "r"((a)[3]),            \
                   "r"((b)[0]), "r"((b)[1]))

#define LDSM4(r, addr)                                                            \
    asm volatile("ldmatrix.sync.aligned.m8n8.x4.shared.b16 {%0,%1,%2,%3}, [%4];"  \
                 : "=r"((r)[0]), "=r"((r)[1]), "=r"((r)[2]), "=r"((r)[3])         \
                 : "r"(addr))

// chunk swizzle: 16B chunks, 2 per 32B row; conflict-free for STS.128 and LDSM
__device__ __forceinline__ int chunk_idx(int r, int c) {
    return r * 2 + (c ^ ((r >> 2) & 1));
}

// split 8 floats into packed fp16 hi (uint4) + lo (uint4)
__device__ __forceinline__ void split8(const float* f, uint4* hiv, uint4* lov) {
    unsigned* hi = (unsigned*)hiv;
    unsigned* lo = (unsigned*)lov;
    #pragma unroll
    for (int i = 0; i < 4; i++) {
        __half h0 = __float2half_rn(f[2 * i]);
        __half h1 = __float2half_rn(f[2 * i + 1]);
        __half l0 = __float2half_rn(f[2 * i] - __half2float(h0));
        __half l1 = __float2half_rn(f[2 * i + 1] - __half2float(h1));
        __half2 H = __halves2half2(h0, h1);
        __half2 L = __halves2half2(l0, l1);
        hi[i] = *reinterpret_cast<unsigned*>(&H);
        lo[i] = *reinterpret_cast<unsigned*>(&L);
    }
}

// ---------------------------------------------------------------------------
__global__ void k_zero() {
    int i = blockIdx.x * blockDim.x + threadIdx.x;
    int stride = gridDim.x * blockDim.x;
    for (int j = i; j < Mm * Nn; j += stride) g_hist[j] = 0;
    if (i < Mm) g_w[i] = 0.f;
}

// ---------------------------------------------------------------------------
// Split + transpose weights: fc_w [m][k][n] -> fwT [m][n][k]; w1 [k][n] -> w1T [n][k]
// ---------------------------------------------------------------------------
__global__ void k_split_w(const float* __restrict__ fc_w, const float* __restrict__ sem_w1) {
    int i = blockIdx.x * blockDim.x + threadIdx.x;
    int total1 = Mm * Fh * Fh;
    if (i < total1) {
        int m = i / (Fh * Fh);
        int r = i % (Fh * Fh);
        int k = r / Fh, n = r % Fh;
        float a = fc_w[i];
        __half hi = __float2half_rn(a);
        __half lo = __float2half_rn(a - __half2float(hi));
        size_t o = (size_t)m * Fh * Fh + (size_t)n * Fh + k;
        g_fwT_hi[o] = hi; g_fwT_lo[o] = lo;
    } else if (i < total1 + Fh * HID) {
        int j = i - total1;
        int k = j / HID, n = j % HID;
        float a = sem_w1[j];
        __half hi = __float2half_rn(a);
        __half lo = __float2half_rn(a - __half2float(hi));
        size_t o = (size_t)n * Fh + k;
        g_w1T_hi[o] = hi; g_w1T_lo[o] = lo;
    }
}

// ---------------------------------------------------------------------------
// feat[m] = h @ fc_w[m]: fp16 split mma (3-term), ldmatrix fragment loads.
// A loaded fp32 and split inline. Output feat as fp16. Epilogue computes el/er.
// ---------------------------------------------------------------------------
__global__ __launch_bounds__(256) void k_gemm_feat(const float* __restrict__ hsrc,
                                                   const float* __restrict__ attn_l,
                                                   const float* __restrict__ attn_r) {
    __shared__ uint4 sA[2][2][256];
    __shared__ uint4 sB[2][2][256];

    int tid = threadIdx.x;
    int lane = tid & 31, warp = tid >> 5;
    int g = lane >> 2, t = lane & 3;
    int warp_m = warp >> 2, warp_n = warp & 3;
    int row0 = blockIdx.x * 128;
    int col0 = blockIdx.y * 128;
    int m = blockIdx.z;

    const unsigned* Bh = (const unsigned*)(g_fwT_hi + (size_t)m * Fh * Fh);
    const unsigned* Bl = (const unsigned*)(g_fwT_lo + (size_t)m * Fh * Fh);

    int lr = tid >> 1;         // tile row 0..127
    int ch = tid & 1;          // 8-elem chunk 0/1

    float acc[4][4][4] = {};
    uint4 pa_h, pa_l, pb_h, pb_l;

    auto LOADG = [&](int ks) {
        int grow = row0 + lr;
        float f[8];
        if (grow < Nn) {
            const float4* ap = (const float4*)(hsrc + (size_t)grow * 256 + ks * 16 + ch * 8);
            float4 v0 = ap[0], v1 = ap[1];
            f[0] = v0.x; f[1] = v0.y; f[2] = v0.z; f[3] = v0.w;
            f[4] = v1.x; f[5] = v1.y; f[6] = v1.z; f[7] = v1.w;
        } else {
            #pragma unroll
            for (int i = 0; i < 8; i++) f[i] = 0.f;
        }
        split8(f, &pa_h, &pa_l);
        int koff = ks * 8 + ch * 4;   // in uint (2-half) units
        pb_h = *(const uint4*)(Bh + (size_t)(col0 + lr) * 128 + koff);
        pb_l = *(const uint4*)(Bl + (size_t)(col0 + lr) * 128 + koff);
    };
    auto STORES = [&](int st) {
        int ci = chunk_idx(lr, ch);
        sA[st][0][ci] = pa_h;
        sA[st][1][ci] = pa_l;
        sB[st][0][ci] = pb_h;
        sB[st][1][ci] = pb_l;
    };
    int arow = warp_m * 64 + (lane & 15);
    int ac = lane >> 4;
    unsigned aoff = (unsigned)chunk_idx(arow, ac) * 16;
    int ngrp = lane >> 3;
    int nrow = warp_n * 32 + ((ngrp >> 1) << 3) + (lane & 7);
    int nc = ngrp & 1;
    unsigned boff = (unsigned)chunk_idx(nrow, nc) * 16;

    auto DOMMA = [&](int st) {
        unsigned bA0 = (unsigned)__cvta_generic_to_shared(&sA[st][0][0]);
        unsigned bA1 = (unsigned)__cvta_generic_to_shared(&sA[st][1][0]);
        unsigned bB0 = (unsigned)__cvta_generic_to_shared(&sB[st][0][0]);
        unsigned bB1 = (unsigned)__cvta_generic_to_shared(&sB[st][1][0]);
        unsigned a_h[4][4], a_l[4][4], b_h[2][4], b_l[2][4];
        #pragma unroll
        for (int mf = 0; mf < 4; mf++) {
            LDSM4(a_h[mf], bA0 + aoff + mf * 512);
            LDSM4(a_l[mf], bA1 + aoff + mf * 512);
        }
        #pragma unroll
        for (int j = 0; j < 2; j++) {
            LDSM4(b_h[j], bB0 + boff + j * 512);
            LDSM4(b_l[j], bB1 + boff + j * 512);
        }
        #pragma unroll
        for (int mf = 0; mf < 4; mf++)
            #pragma unroll
            for (int nf = 0; nf < 4; nf++) {
                unsigned* bh = &b_h[nf >> 1][(nf & 1) * 2];
                unsigned* bl = &b_l[nf >> 1][(nf & 1) * 2];
                MMA(acc[mf][nf], a_h[mf], bh);
                MMA(acc[mf][nf], a_h[mf], bl);
                MMA(acc[mf][nf], a_l[mf], bh);
            }
    };

    LOADG(0); STORES(0); __syncthreads();
    for (int ks = 0; ks < 16; ks++) {
        int cur = ks & 1;
        if (ks < 15) LOADG(ks + 1);
        DOMMA(cur);
        __syncthreads();
        if (ks < 15) { STORES(cur ^ 1); __syncthreads(); }
    }

    // --- epilogue: store feat16; compute el/er for this warp's head ---
    int head = blockIdx.y * 4 + warp_n;
    float alv[8], arv[8];
    #pragma unroll
    for (int nf = 0; nf < 4; nf++) {
        int c = head * 32 + nf * 8 + 2 * t;
        alv[nf * 2]     = attn_l[m * 256 + c];
        alv[nf * 2 + 1] = attn_l[m * 256 + c + 1];
        arv[nf * 2]     = attn_r[m * 256 + c];
        arv[nf * 2 + 1] = attn_r[m * 256 + c + 1];
    }

    __half* C = g_feat16 + (size_t)m * Nn * Fh;
    #pragma unroll
    for (int mf = 0; mf < 4; mf++) {
        int r = row0 + warp_m * 64 + mf * 16 + g;
        float e0 = 0.f, e1 = 0.f, f0 = 0.f, f1 = 0.f;
        #pragma unroll
        for (int nf = 0; nf < 4; nf++) {
            int c = col0 + warp_n * 32 + nf * 8 + 2 * t;
            if (r < Nn)
                *(__half2*)&C[(size_t)r * 256 + c] = __floats2half2_rn(acc[mf][nf][0], acc[mf][nf][1]);
            if (r + 8 < Nn)
                *(__half2*)&C[(size_t)(r + 8) * 256 + c] = __floats2half2_rn(acc[mf][nf][2], acc[mf][nf][3]);
            e0 += acc[mf][nf][0] * alv[nf * 2] + acc[mf][nf][1] * alv[nf * 2 + 1];
            e1 += acc[mf][nf][2] * alv[nf * 2] + acc[mf][nf][3] * alv[nf * 2 + 1];
            f0 += acc[mf][nf][0] * arv[nf * 2] + acc[mf][nf][1] * arv[nf * 2 + 1];
            f1 += acc[mf][nf][2] * arv[nf * 2] + acc[mf][nf][3] * arv[nf * 2 + 1];
        }
        e0 += __shfl_xor_sync(0xffffffffu, e0, 1); e0 += __shfl_xor_sync(0xffffffffu, e0, 2);
        e1 += __shfl_xor_sync(0xffffffffu, e1, 1); e1 += __shfl_xor_sync(0xffffffffu, e1, 2);
        f0 += __shfl_xor_sync(0xffffffffu, f0, 1); f0 += __shfl_xor_sync(0xffffffffu, f0, 2);
        f1 += __shfl_xor_sync(0xffffffffu, f1, 1); f1 += __shfl_xor_sync(0xffffffffu, f1, 2);
        if (t == 0) {
            if (r < Nn) {
                g_el[((size_t)m * Nn + r) * 8 + head] = e0;
                g_er[((size_t)m * Nn + r) * 8 + head] = f0;
            }
            if (r + 8 < Nn) {
                g_el[((size_t)m * Nn + r + 8) * 8 + head] = e1;
                g_er[((size_t)m * Nn + r + 8) * 8 + head] = f1;
            }
        }
    }
}

// ---------------------------------------------------------------------------
// CSR build
// ---------------------------------------------------------------------------
__global__ void k_hist(const int* __restrict__ dst_all) {
    int m = blockIdx.y;
    int e = blockIdx.x * blockDim.x + threadIdx.x;
    if (e < Ee) atomicAdd(&g_hist[m * Nn + dst_all[(size_t)m * Ee + e]], 1);
}

__global__ void k_scan1() {
    __shared__ int s[256];
    int m = blockIdx.y, tid = threadIdx.x;
    int i = blockIdx.x * 256 + tid;
    int v = (i < Nn) ? g_hist[m * Nn + i] : 0;
    s[tid] = v; __syncthreads();
    #pragma unroll
    for (int o = 1; o < 256; o <<= 1) {
        int t = (tid >= o) ? s[tid - o] : 0;
        __syncthreads();
        s[tid] += t;
        __syncthreads();
    }
    if (i < Nn) g_off[m * Nn + i] = s[tid] - v;
    if (tid == 255) g_bsum[m * 256 + blockIdx.x] = s[tid];
}

__global__ void k_scan2() {
    __shared__ int s[256];
    int m = blockIdx.x, tid = threadIdx.x;
    int v = (tid < SCANB) ? g_bsum[m * 256 + tid] : 0;
    s[tid] = v; __syncthreads();
    #pragma unroll
    for (int o = 1; o < 256; o <<= 1) {
        int t = (tid >= o) ? s[tid - o] : 0;
        __syncthreads();
        s[tid] += t;
        __syncthreads();
    }
    g_bsum[m * 256 + tid] = s[tid] - v;
}

__global__ void k_scan3() {
    int m = blockIdx.y, tid = threadIdx.x;
    int i = blockIdx.x * 256 + tid;
    if (i < Nn) {
        int o = g_off[m * Nn + i] + g_bsum[m * 256 + blockIdx.x];
        g_off[m * Nn + i] = o;
        g_cursor[m * Nn + i] = o;
    }
}

__global__ void k_scatter(const int* __restrict__ src_all, const int* __restrict__ dst_all) {
    int m = blockIdx.y;
    int e = blockIdx.x * blockDim.x + threadIdx.x;
    if (e >= Ee) return;
    int d = dst_all[(size_t)m * Ee + e];
    int p = atomicAdd(&g_cursor[m * Nn + d], 1);
    g_csrc[(size_t)m * Ee + p] = src_all[(size_t)m * Ee + e];
}

// ---------------------------------------------------------------------------
// Fused edge pass, ALL metapaths in one launch (grid.y = m).
// Warp per dst node: gather fp16 feat, fp32 accumulate, /esum, +bias, elu -> z.
// ---------------------------------------------------------------------------
__global__ __launch_bounds__(256) void k_pass_all(const float* __restrict__ bias) {
    int warp = threadIdx.x >> 5, lane = threadIdx.x & 31;
    int d = blockIdx.x * 8 + warp;
    int m = blockIdx.y;
    if (d >= Nn) return;

    int beg = g_off[m * Nn + d];
    int end = (d + 1 < Nn) ? g_off[m * Nn + d + 1] : Ee;

    const float*  elb = g_el + (size_t)m * Nn * Hh;
    const float*  erb = g_er + (size_t)m * Nn * Hh;
    const int*    cs  = g_csrc + (size_t)m * Ee;
    const __half* F   = g_feat16 + (size_t)m * Nn * Fh;

    float er_h = (lane < 8) ? erb[(size_t)d * 8 + lane] : 0.f;

    float acc[8] = {};
    float esum = 0.f;

    #pragma unroll 4
    for (int j = beg; j < end; j++) {
        int s = cs[j];
        float ee = 0.f;
        if (lane < 8) {
            float x = elb[(size_t)s * 8 + lane] + er_h;
            x = x > 0.f ? x : 0.2f * x;
            ee = __expf(x);
            esum += ee;
        }
        float w = __shfl_sync(0xffffffffu, ee, lane >> 2);
        uint4 p = *(const uint4*)(F + (size_t)s * 256 + lane * 8);
        __half2* hp = (__half2*)&p;
        float2 v0 = __half22float2(hp[0]);
        float2 v1 = __half22float2(hp[1]);
        float2 v2 = __half22float2(hp[2]);
        float2 v3 = __half22float2(hp[3]);
        acc[0] += w * v0.x; acc[1] += w * v0.y; acc[2] += w * v1.x; acc[3] += w * v1.y;
        acc[4] += w * v2.x; acc[5] += w * v2.y; acc[6] += w * v3.x; acc[7] += w * v3.y;
    }

    float es = __shfl_sync(0xffffffffu, esum, lane >> 2);
    float inv = 1.f / fmaxf(es, 1e-38f);

    const float4* bp = (const float4*)(bias + (size_t)m * 256 + lane * 8);
    float4 b0 = bp[0], b1 = bp[1];
    float r[8];
    r[0] = acc[0] * inv + b0.x; r[1] = acc[1] * inv + b0.y;
    r[2] = acc[2] * inv + b0.z; r[3] = acc[3] * inv + b0.w;
    r[4] = acc[4] * inv + b1.x; r[5] = acc[5] * inv + b1.y;
    r[6] = acc[6] * inv + b1.z; r[7] = acc[7] * inv + b1.w;
    #pragma unroll
    for (int i = 0; i < 8; i++) r[i] = r[i] > 0.f ? r[i] : expm1f(r[i]);

    size_t rowb = ((size_t)m * Nn + d) * 256 + lane * 8;
    float4* zp = (float4*)(g_z + rowb);
    zp[0] = make_float4(r[0], r[1], r[2], r[3]);
    zp[1] = make_float4(r[4], r[5], r[6], r[7]);
}

// ---------------------------------------------------------------------------
// Semantic GEMM: A = z fp32 (inline fp16 split), B = w1T fp16 hi/lo.
// Fused tanh/w2/row-reduction epilogue.
// ---------------------------------------------------------------------------
__global__ __launch_bounds__(256) void k_gemm_sem(const float* __restrict__ sem_b1,
                                                  const float* __restrict__ sem_w2) {
    __shared__ uint4 sA[2][2][256];
    __shared__ uint4 sB[2][2][256];
    __shared__ float s_rsum[128];
    __shared__ float s_mw[3];
    __shared__ float sb1[128], sw2[128];

    int tid = threadIdx.x;
    int lane = tid & 31, warp = tid >> 5;
    int g = lane >> 2, t = lane & 3;
    int warp_m = warp >> 2, warp_n = warp & 3;
    int row0 = blockIdx.x * 128;

    if (tid < 128) { s_rsum[tid] = 0.f; sb1[tid] = sem_b1[tid]; sw2[tid] = sem_w2[tid]; }
    if (tid < 3) s_mw[tid] = 0.f;

    const unsigned* Bh = (const unsigned*)g_w1T_hi;
    const unsigned* Bl = (const unsigned*)g_w1T_lo;

    int lr = tid >> 1;
    int ch = tid & 1;

    float acc[4][4][4] = {};
    uint4 pa_h, pa_l, pb_h, pb_l;

    auto LOADG = [&](int ks) {
        int grow = row0 + lr;
        float f[8];
        if (grow < NZ) {
            const float4* ap = (const float4*)(g_z + (size_t)grow * 256 + ks * 16 + ch * 8);
            float4 v0 = ap[0], v1 = ap[1];
            f[0] = v0.x; f[1] = v0.y; f[2] = v0.z; f[3] = v0.w;
            f[4] = v1.x; f[5] = v1.y; f[6] = v1.z; f[7] = v1.w;
        } else {
            #pragma unroll
            for (int i = 0; i < 8; i++) f[i] = 0.f;
        }
        split8(f, &pa_h, &pa_l);
        int koff = ks * 8 + ch * 4;
        pb_h = *(const uint4*)(Bh + (size_t)lr * 128 + koff);
        pb_l = *(const uint4*)(Bl + (size_t)lr * 128 + koff);
    };
    auto STORES = [&](int st) {
        int ci = chunk_idx(lr, ch);
        sA[st][0][ci] = pa_h;
        sA[st][1][ci] = pa_l;
        sB[st][0][ci] = pb_h;
        sB[st][1][ci] = pb_l;
    };
    int arow = warp_m * 64 + (lane & 15);
    int ac = lane >> 4;
    unsigned aoff = (unsigned)chunk_idx(arow, ac) * 16;
    int ngrp = lane >> 3;
    int nrow = warp_n * 32 + ((ngrp >> 1) << 3) + (lane & 7);
    int nc = ngrp & 1;
    unsigned boff = (unsigned)chunk_idx(nrow, nc) * 16;

    auto DOMMA = [&](int st) {
        unsigned bA0 = (unsigned)__cvta_generic_to_shared(&sA[st][0][0]);
        unsigned bA1 = (unsigned)__cvta_generic_to_shared(&sA[st][1][0]);
        unsigned bB0 = (unsigned)__cvta_generic_to_shared(&sB[st][0][0]);
        unsigned bB1 = (unsigned)__cvta_generic_to_shared(&sB[st][1][0]);
        unsigned a_h[4][4], a_l[4][4], b_h[2][4], b_l[2][4];
        #pragma unroll
        for (int mf = 0; mf < 4; mf++) {
            LDSM4(a_h[mf], bA0 + aoff + mf * 512);
            LDSM4(a_l[mf], bA1 + aoff + mf * 512);
        }
        #pragma unroll
        for (int j = 0; j < 2; j++) {
            LDSM4(b_h[j], bB0 + boff + j * 512);
            LDSM4(b_l[j], bB1 + boff + j * 512);
        }
        #pragma unroll
        for (int mf = 0; mf < 4; mf++)
            #pragma unroll
            for (int nf = 0; nf < 4; nf++) {
                unsigned* bh = &b_h[nf >> 1][(nf & 1) * 2];
                unsigned* bl = &b_l[nf >> 1][(nf & 1) * 2];
                MMA(acc[mf][nf], a_h[mf], bh);
                MMA(acc[mf][nf], a_h[mf], bl);
                MMA(acc[mf][nf], a_l[mf], bh);
            }
    };

    LOADG(0); STORES(0); __syncthreads();
    for (int ks = 0; ks < 16; ks++) {
        int cur = ks & 1;
        if (ks < 15) LOADG(ks + 1);
        DOMMA(cur);
        __syncthreads();
        if (ks < 15) { STORES(cur ^ 1); __syncthreads(); }
    }

    #pragma unroll
    for (int mf = 0; mf < 4; mf++) {
        float rsa = 0.f, rsb = 0.f;
        #pragma unroll
        for (int nf = 0; nf < 4; nf++) {
            int c = warp_n * 32 + nf * 8 + 2 * t;
            float b0 = sb1[c], b1v = sb1[c + 1];
            float w20 = sw2[c], w21 = sw2[c + 1];
            rsa += tanha(acc[mf][nf][0] + b0) * w20 + tanha(acc[mf][nf][1] + b1v) * w21;
            rsb += tanha(acc[mf][nf][2] + b0) * w20 + tanha(acc[mf][nf][3] + b1v) * w21;
        }
        rsa += __shfl_xor_sync(0xffffffffu, rsa, 1);
        rsa += __shfl_xor_sync(0xffffffffu, rsa, 2);
        rsb += __shfl_xor_sync(0xffffffffu, rsb, 1);
        rsb += __shfl_xor_sync(0xffffffffu, rsb, 2);
        if (t == 0) {
            atomicAdd(&s_rsum[warp_m * 64 + mf * 16 + g], rsa);
            atomicAdd(&s_rsum[warp_m * 64 + mf * 16 + g + 8], rsb);
        }
    }
    __syncthreads();
    if (tid < 128) {
        int r = row0 + tid;
        if (r < NZ) atomicAdd(&s_mw[r / Nn], s_rsum[tid]);
    }
    __syncthreads();
    if (tid < 3) atomicAdd(&g_w[tid], s_mw[tid]);
}

// ---------------------------------------------------------------------------
__global__ void k_aw() {
    float w0 = g_w[0] / (float)Nn;
    float w1 = g_w[1] / (float)Nn;
    float w2 = g_w[2] / (float)Nn;
    float mx = fmaxf(w0, fmaxf(w1, w2));
    float e0 = expf(w0 - mx), e1 = expf(w1 - mx), e2 = expf(w2 - mx);
    float s = e0 + e1 + e2;
    g_aw[0] = e0 / s; g_aw[1] = e1 / s; g_aw[2] = e2 / s;
}

__global__ void k_comb(float* __restrict__ out) {
    int i = blockIdx.x * blockDim.x + threadIdx.x;
    int total = Nn * (Fh / 4);
    if (i >= total) return;
    float a0 = g_aw[0], a1 = g_aw[1], a2 = g_aw[2];
    const float4* z4 = (const float4*)g_z;
    float4 v0 = z4[i];
    float4 v1 = z4[i + (size_t)Nn * Fh / 4];
    float4 v2 = z4[i + 2 * (size_t)Nn * Fh / 4];
    float4 o;
    o.x = v0.x * a0 + v1.x * a1 + v2.x * a2;
    o.y = v0.y * a0 + v1.y * a1 + v2.y * a2;
    o.z = v0.z * a0 + v1.z * a1 + v2.z * a2;
    o.w = v0.w * a0 + v1.w * a1 + v2.w * a2;
    ((float4*)out)[i] = o;
}

// ---------------------------------------------------------------------------
extern "C" void kernel_launch(void* const* d_in, const int* in_sizes, int n_in,
                              void* d_out, int out_size) {
    const float* h      = (const float*)d_in[0];
    const int*   src    = (const int*)d_in[1];
    const int*   dst    = (const int*)d_in[2];
    const float* fc_w   = (const float*)d_in[3];
    const float* attn_l = (const float*)d_in[4];
    const float* attn_r = (const float*)d_in[5];
    const float* bias   = (const float*)d_in[6];
    const float* sem_w1 = (const float*)d_in[7];
    const float* sem_b1 = (const float*)d_in[8];
    const float* sem_w2 = (const float*)d_in[9];
    float* out = (float*)d_out;

    k_zero<<<256, 256>>>();
    k_split_w<<<(Mm * Fh * Fh + Fh * HID + 255) / 256, 256>>>(fc_w, sem_w1);

    k_hist<<<dim3((Ee + 255) / 256, Mm), 256>>>(dst);
    k_scan1<<<dim3(SCANB, Mm), 256>>>();
    k_scan2<<<Mm, 256>>>();
    k_scan3<<<dim3(SCANB, Mm), 256>>>();
    k_scatter<<<dim3((Ee + 255) / 256, Mm), 256>>>(src, dst);

    dim3 gfeat((Nn + 127) / 128, Fh / 128, Mm);
    k_gemm_feat<<<gfeat, 256>>>(h, attn_l, attn_r);

    k_pass_all<<<dim3((Nn + 7) / 8, Mm), 256>>>(bias);

    k_gemm_sem<<<(NZ + 127) / 128, 256>>>(sem_b1, sem_w2);
    k_aw<<<1, 1>>>();
    k_comb<<<(Nn * (Fh / 4) + 255) / 256, 256>>>(out);
}

// round 11
// speedup vs baseline: 2.9592x; 1.0052x over previous
#include <cuda_runtime.h>
#include <cuda_fp16.h>
#include <math.h>

#define Nn 50000
#define Ee 800000
#define Mm 3
#define Fh 256   // H*D
#define Hh 8
#define HID 128
#define NZ (Mm * Nn)        // 150000 rows of z
#define SCANB 196           // ceil(Nn/256)

__device__ __align__(16) __half g_feat16[(size_t)Mm * Nn * Fh];
__device__ __align__(16) float  g_z[(size_t)Mm * Nn * Fh];
__device__ __align__(16) float  g_el[(size_t)Mm * Nn * Hh];
__device__ __align__(16) float  g_er[(size_t)Mm * Nn * Hh];
__device__ float g_w[Mm];
__device__ float g_aw[Mm];

// CSR scratch
__device__ int g_hist[Mm * Nn];
__device__ int g_off[Mm * Nn];
__device__ int g_bsum[Mm * 256];
__device__ int g_cursor[Mm * Nn];
__device__ int g_csrc[(size_t)Mm * Ee];

// fp16 hi/lo split weights (pre-transposed to [n][k])
__device__ __align__(16) __half g_fwT_hi[(size_t)Mm * Fh * Fh];
__device__ __align__(16) __half g_fwT_lo[(size_t)Mm * Fh * Fh];
__device__ __align__(16) __half g_w1T_hi[HID * Fh];
__device__ __align__(16) __half g_w1T_lo[HID * Fh];

__device__ __forceinline__ float tanha(float x) {
    float y; asm("tanh.approx.f32 %0, %1;" : "=f"(y) : "f"(x)); return y;
}

#define MMA(d, a, b)                                                              \
    asm volatile("mma.sync.aligned.m16n8k16.row.col.f32.f16.f16.f32 "             \
                 "{%0,%1,%2,%3},{%4,%5,%6,%7},{%8,%9},{%0,%1,%2,%3};"             \
                 : "+f"((d)[0]), "+f"((d)[1]), "+f"((d)[2]), "+f"((d)[3])         \
                 : "r"((a)[0]), "r"((a)[1]), "r"((a)[2]), "r"((a)[3]),            \
                   "r"((b)[0]), "r"((b)[1]))

#define LDSM4(r, addr)                                                            \
    asm volatile("ldmatrix.sync.aligned.m8n8.x4.shared.b16 {%0,%1,%2,%3}, [%4];"  \
                 : "=r"((r)[0]), "=r"((r)[1]), "=r"((r)[2]), "=r"((r)[3])         \
                 : "r"(addr))

// chunk swizzle: 16B chunks, 2 per 32B row; conflict-free for STS.128 and LDSM
__device__ __forceinline__ int chunk_idx(int r, int c) {
    return r * 2 + (c ^ ((r >> 2) & 1));
}

// split 8 floats into packed fp16 hi (uint4) + lo (uint4)
__device__ __forceinline__ void split8(const float* f, uint4* hiv, uint4* lov) {
    unsigned* hi = (unsigned*)hiv;
    unsigned* lo = (unsigned*)lov;
    #pragma unroll
    for (int i = 0; i < 4; i++) {
        __half h0 = __float2half_rn(f[2 * i]);
        __half h1 = __float2half_rn(f[2 * i + 1]);
        __half l0 = __float2half_rn(f[2 * i] - __half2float(h0));
        __half l1 = __float2half_rn(f[2 * i + 1] - __half2float(h1));
        __half2 H = __halves2half2(h0, h1);
        __half2 L = __halves2half2(l0, l1);
        hi[i] = *reinterpret_cast<unsigned*>(&H);
        lo[i] = *reinterpret_cast<unsigned*>(&L);
    }
}

// ---------------------------------------------------------------------------
__global__ void k_zero() {
    int i = blockIdx.x * blockDim.x + threadIdx.x;
    int stride = gridDim.x * blockDim.x;
    for (int j = i; j < Mm * Nn; j += stride) g_hist[j] = 0;
    if (i < Mm) g_w[i] = 0.f;
}

// ---------------------------------------------------------------------------
__global__ void k_split_w(const float* __restrict__ fc_w, const float* __restrict__ sem_w1) {
    int i = blockIdx.x * blockDim.x + threadIdx.x;
    int total1 = Mm * Fh * Fh;
    if (i < total1) {
        int m = i / (Fh * Fh);
        int r = i % (Fh * Fh);
        int k = r / Fh, n = r % Fh;
        float a = fc_w[i];
        __half hi = __float2half_rn(a);
        __half lo = __float2half_rn(a - __half2float(hi));
        size_t o = (size_t)m * Fh * Fh + (size_t)n * Fh + k;
        g_fwT_hi[o] = hi; g_fwT_lo[o] = lo;
    } else if (i < total1 + Fh * HID) {
        int j = i - total1;
        int k = j / HID, n = j % HID;
        float a = sem_w1[j];
        __half hi = __float2half_rn(a);
        __half lo = __float2half_rn(a - __half2float(hi));
        size_t o = (size_t)n * Fh + k;
        g_w1T_hi[o] = hi; g_w1T_lo[o] = lo;
    }
}

// ---------------------------------------------------------------------------
// feat[m] = h @ fc_w[m]: fp16 split mma (3-term), ldmatrix, 3-stage pipeline
// (single __syncthreads per k-step). Epilogue computes el/er.
// ---------------------------------------------------------------------------
__global__ __launch_bounds__(256) void k_gemm_feat(const float* __restrict__ hsrc,
                                                   const float* __restrict__ attn_l,
                                                   const float* __restrict__ attn_r) {
    __shared__ uint4 sA[3][2][256];
    __shared__ uint4 sB[3][2][256];

    int tid = threadIdx.x;
    int lane = tid & 31, warp = tid >> 5;
    int g = lane >> 2, t = lane & 3;
    int warp_m = warp >> 2, warp_n = warp & 3;
    int row0 = blockIdx.x * 128;
    int col0 = blockIdx.y * 128;
    int m = blockIdx.z;

    const unsigned* Bh = (const unsigned*)(g_fwT_hi + (size_t)m * Fh * Fh);
    const unsigned* Bl = (const unsigned*)(g_fwT_lo + (size_t)m * Fh * Fh);

    int lr = tid >> 1;         // tile row 0..127
    int ch = tid & 1;          // 8-elem chunk 0/1

    float acc[4][4][4] = {};
    uint4 pa_h, pa_l, pb_h, pb_l;

    auto LOADG = [&](int ks) {
        int grow = row0 + lr;
        float f[8];
        if (grow < Nn) {
            const float4* ap = (const float4*)(hsrc + (size_t)grow * 256 + ks * 16 + ch * 8);
            float4 v0 = ap[0], v1 = ap[1];
            f[0] = v0.x; f[1] = v0.y; f[2] = v0.z; f[3] = v0.w;
            f[4] = v1.x; f[5] = v1.y; f[6] = v1.z; f[7] = v1.w;
        } else {
            #pragma unroll
            for (int i = 0; i < 8; i++) f[i] = 0.f;
        }
        split8(f, &pa_h, &pa_l);
        int koff = ks * 8 + ch * 4;   // in uint (2-half) units
        pb_h = *(const uint4*)(Bh + (size_t)(col0 + lr) * 128 + koff);
        pb_l = *(const uint4*)(Bl + (size_t)(col0 + lr) * 128 + koff);
    };
    auto STORES = [&](int st) {
        int ci = chunk_idx(lr, ch);
        sA[st][0][ci] = pa_h;
        sA[st][1][ci] = pa_l;
        sB[st][0][ci] = pb_h;
        sB[st][1][ci] = pb_l;
    };
    int arow = warp_m * 64 + (lane & 15);
    int ac = lane >> 4;
    unsigned aoff = (unsigned)chunk_idx(arow, ac) * 16;
    int ngrp = lane >> 3;
    int nrow = warp_n * 32 + ((ngrp >> 1) << 3) + (lane & 7);
    int nc = ngrp & 1;
    unsigned boff = (unsigned)chunk_idx(nrow, nc) * 16;

    auto DOMMA = [&](int st) {
        unsigned bA0 = (unsigned)__cvta_generic_to_shared(&sA[st][0][0]);
        unsigned bA1 = (unsigned)__cvta_generic_to_shared(&sA[st][1][0]);
        unsigned bB0 = (unsigned)__cvta_generic_to_shared(&sB[st][0][0]);
        unsigned bB1 = (unsigned)__cvta_generic_to_shared(&sB[st][1][0]);
        unsigned a_h[4][4], a_l[4][4], b_h[2][4], b_l[2][4];
        #pragma unroll
        for (int mf = 0; mf < 4; mf++) {
            LDSM4(a_h[mf], bA0 + aoff + mf * 512);
            LDSM4(a_l[mf], bA1 + aoff + mf * 512);
        }
        #pragma unroll
        for (int j = 0; j < 2; j++) {
            LDSM4(b_h[j], bB0 + boff + j * 512);
            LDSM4(b_l[j], bB1 + boff + j * 512);
        }
        #pragma unroll
        for (int mf = 0; mf < 4; mf++)
            #pragma unroll
            for (int nf = 0; nf < 4; nf++) {
                unsigned* bh = &b_h[nf >> 1][(nf & 1) * 2];
                unsigned* bl = &b_l[nf >> 1][(nf & 1) * 2];
                MMA(acc[mf][nf], a_h[mf], bh);
                MMA(acc[mf][nf], a_h[mf], bl);
                MMA(acc[mf][nf], a_l[mf], bh);
            }
    };

    LOADG(0); STORES(0);
    LOADG(1);
    __syncthreads();
    #pragma unroll 1
    for (int ks = 0; ks < 16; ks++) {
        if (ks + 1 < 16) STORES((ks + 1) % 3);
        if (ks + 2 < 16) LOADG(ks + 2);
        DOMMA(ks % 3);
        __syncthreads();
    }

    // --- epilogue: store feat16; compute el/er for this warp's head ---
    int head = blockIdx.y * 4 + warp_n;
    float alv[8], arv[8];
    #pragma unroll
    for (int nf = 0; nf < 4; nf++) {
        int c = head * 32 + nf * 8 + 2 * t;
        alv[nf * 2]     = attn_l[m * 256 + c];
        alv[nf * 2 + 1] = attn_l[m * 256 + c + 1];
        arv[nf * 2]     = attn_r[m * 256 + c];
        arv[nf * 2 + 1] = attn_r[m * 256 + c + 1];
    }

    __half* C = g_feat16 + (size_t)m * Nn * Fh;
    #pragma unroll
    for (int mf = 0; mf < 4; mf++) {
        int r = row0 + warp_m * 64 + mf * 16 + g;
        float e0 = 0.f, e1 = 0.f, f0 = 0.f, f1 = 0.f;
        #pragma unroll
        for (int nf = 0; nf < 4; nf++) {
            int c = col0 + warp_n * 32 + nf * 8 + 2 * t;
            if (r < Nn)
                *(__half2*)&C[(size_t)r * 256 + c] = __floats2half2_rn(acc[mf][nf][0], acc[mf][nf][1]);
            if (r + 8 < Nn)
                *(__half2*)&C[(size_t)(r + 8) * 256 + c] = __floats2half2_rn(acc[mf][nf][2], acc[mf][nf][3]);
            e0 += acc[mf][nf][0] * alv[nf * 2] + acc[mf][nf][1] * alv[nf * 2 + 1];
            e1 += acc[mf][nf][2] * alv[nf * 2] + acc[mf][nf][3] * alv[nf * 2 + 1];
            f0 += acc[mf][nf][0] * arv[nf * 2] + acc[mf][nf][1] * arv[nf * 2 + 1];
            f1 += acc[mf][nf][2] * arv[nf * 2] + acc[mf][nf][3] * arv[nf * 2 + 1];
        }
        e0 += __shfl_xor_sync(0xffffffffu, e0, 1); e0 += __shfl_xor_sync(0xffffffffu, e0, 2);
        e1 += __shfl_xor_sync(0xffffffffu, e1, 1); e1 += __shfl_xor_sync(0xffffffffu, e1, 2);
        f0 += __shfl_xor_sync(0xffffffffu, f0, 1); f0 += __shfl_xor_sync(0xffffffffu, f0, 2);
        f1 += __shfl_xor_sync(0xffffffffu, f1, 1); f1 += __shfl_xor_sync(0xffffffffu, f1, 2);
        if (t == 0) {
            if (r < Nn) {
                g_el[((size_t)m * Nn + r) * 8 + head] = e0;
                g_er[((size_t)m * Nn + r) * 8 + head] = f0;
            }
            if (r + 8 < Nn) {
                g_el[((size_t)m * Nn + r + 8) * 8 + head] = e1;
                g_er[((size_t)m * Nn + r + 8) * 8 + head] = f1;
            }
        }
    }
}

// ---------------------------------------------------------------------------
// CSR build
// ---------------------------------------------------------------------------
__global__ void k_hist(const int* __restrict__ dst_all) {
    int m = blockIdx.y;
    int e = blockIdx.x * blockDim.x + threadIdx.x;
    if (e < Ee) atomicAdd(&g_hist[m * Nn + dst_all[(size_t)m * Ee + e]], 1);
}

__global__ void k_scan1() {
    __shared__ int s[256];
    int m = blockIdx.y, tid = threadIdx.x;
    int i = blockIdx.x * 256 + tid;
    int v = (i < Nn) ? g_hist[m * Nn + i] : 0;
    s[tid] = v; __syncthreads();
    #pragma unroll
    for (int o = 1; o < 256; o <<= 1) {
        int t = (tid >= o) ? s[tid - o] : 0;
        __syncthreads();
        s[tid] += t;
        __syncthreads();
    }
    if (i < Nn) g_off[m * Nn + i] = s[tid] - v;
    if (tid == 255) g_bsum[m * 256 + blockIdx.x] = s[tid];
}

__global__ void k_scan2() {
    __shared__ int s[256];
    int m = blockIdx.x, tid = threadIdx.x;
    int v = (tid < SCANB) ? g_bsum[m * 256 + tid] : 0;
    s[tid] = v; __syncthreads();
    #pragma unroll
    for (int o = 1; o < 256; o <<= 1) {
        int t = (tid >= o) ? s[tid - o] : 0;
        __syncthreads();
        s[tid] += t;
        __syncthreads();
    }
    g_bsum[m * 256 + tid] = s[tid] - v;
}

__global__ void k_scan3() {
    int m = blockIdx.y, tid = threadIdx.x;
    int i = blockIdx.x * 256 + tid;
    if (i < Nn) {
        int o = g_off[m * Nn + i] + g_bsum[m * 256 + blockIdx.x];
        g_off[m * Nn + i] = o;
        g_cursor[m * Nn + i] = o;
    }
}

__global__ void k_scatter(const int* __restrict__ src_all, const int* __restrict__ dst_all) {
    int m = blockIdx.y;
    int e = blockIdx.x * blockDim.x + threadIdx.x;
    if (e >= Ee) return;
    int d = dst_all[(size_t)m * Ee + e];
    int p = atomicAdd(&g_cursor[m * Nn + d], 1);
    g_csrc[(size_t)m * Ee + p] = src_all[(size_t)m * Ee + e];
}

// ---------------------------------------------------------------------------
// Fused edge pass, all metapaths (grid.y = m). Warp per dst node.
// Per 32-edge block: coalesced index prefetch; exp precompute spread over all
// 32 lanes (lane -> (edge j*4 + lane>>3, head lane&7)); then a pure
// gather+FMA consume loop with static ev[] indexing.
// ---------------------------------------------------------------------------
__global__ __launch_bounds__(256) void k_pass_all(const float* __restrict__ bias) {
    int warp = threadIdx.x >> 5, lane = threadIdx.x & 31;
    int d = blockIdx.x * 8 + warp;
    int m = blockIdx.y;
    if (d >= Nn) return;

    int beg = g_off[m * Nn + d];
    int end = (d + 1 < Nn) ? g_off[m * Nn + d + 1] : Ee;

    const float*  elb = g_el + (size_t)m * Nn * Hh;
    const float*  erb = g_er + (size_t)m * Nn * Hh;
    const int*    cs  = g_csrc + (size_t)m * Ee;
    const __half* F   = g_feat16 + (size_t)m * Nn * Fh;

    int myh = lane & 7;                       // head this lane computes exp for
    int esub = lane >> 3;                     // edge-subslot 0..3
    float er8 = __ldg(&erb[(size_t)d * 8 + myh]);

    float acc[8] = {};
    float esum = 0.f;

    for (int base = beg; base < end; base += 32) {
        int rem = end - base;                 // >0
        int idx = 0;
        if (lane < rem) idx = __ldg(&cs[base + lane]);

        // precompute ee for up to 32 edges
        float ev[8];
        #pragma unroll
        for (int j = 0; j < 8; j++) {
            int k = j * 4 + esub;
            int s = __shfl_sync(0xffffffffu, idx, k);
            float e = 0.f;
            if (k < rem) {
                float x = __ldg(&elb[(size_t)s * 8 + myh]) + er8;
                x = x > 0.f ? x : 0.2f * x;
                e = __expf(x);
            }
            ev[j] = e;
            esum += e;
        }

        int cnt = rem < 32 ? rem : 32;
        #pragma unroll
        for (int j = 0; j < 8; j++) {
            int k0 = j * 4;
            if (k0 >= cnt) break;
            float evj = ev[j];
            #pragma unroll
            for (int u = 0; u < 4; u++) {
                int kk = k0 + u;
                if (kk < cnt) {
                    int s = __shfl_sync(0xffffffffu, idx, kk);
                    float w = __shfl_sync(0xffffffffu, evj, ((kk & 3) << 3) + (lane >> 2));
                    uint4 p = *(const uint4*)(F + (size_t)s * 256 + lane * 8);
                    __half2* hp = (__half2*)&p;
                    float2 v0 = __half22float2(hp[0]);
                    float2 v1 = __half22float2(hp[1]);
                    float2 v2 = __half22float2(hp[2]);
                    float2 v3 = __half22float2(hp[3]);
                    acc[0] += w * v0.x; acc[1] += w * v0.y;
                    acc[2] += w * v1.x; acc[3] += w * v1.y;
                    acc[4] += w * v2.x; acc[5] += w * v2.y;
                    acc[6] += w * v3.x; acc[7] += w * v3.y;
                }
            }
        }
    }

    // reduce esum over lanes sharing the same head (lanes h, h+8, h+16, h+24)
    esum += __shfl_xor_sync(0xffffffffu, esum, 8);
    esum += __shfl_xor_sync(0xffffffffu, esum, 16);
    float es = __shfl_sync(0xffffffffu, esum, lane >> 2);   // lane g holds head g
    float inv = 1.f / fmaxf(es, 1e-38f);

    const float4* bp = (const float4*)(bias + (size_t)m * 256 + lane * 8);
    float4 b0 = bp[0], b1 = bp[1];
    float r[8];
    r[0] = acc[0] * inv + b0.x; r[1] = acc[1] * inv + b0.y;
    r[2] = acc[2] * inv + b0.z; r[3] = acc[3] * inv + b0.w;
    r[4] = acc[4] * inv + b1.x; r[5] = acc[5] * inv + b1.y;
    r[6] = acc[6] * inv + b1.z; r[7] = acc[7] * inv + b1.w;
    #pragma unroll
    for (int i = 0; i < 8; i++) r[i] = r[i] > 0.f ? r[i] : expm1f(r[i]);

    size_t rowb = ((size_t)m * Nn + d) * 256 + lane * 8;
    float4* zp = (float4*)(g_z + rowb);
    zp[0] = make_float4(r[0], r[1], r[2], r[3]);
    zp[1] = make_float4(r[4], r[5], r[6], r[7]);
}

// ---------------------------------------------------------------------------
// Semantic GEMM: A = z fp32 (inline fp16 split), B = w1T fp16 hi/lo.
// Fused tanh/w2/row-reduction epilogue.  (2-stage double buffer.)
// ---------------------------------------------------------------------------
__global__ __launch_bounds__(256) void k_gemm_sem(const float* __restrict__ sem_b1,
                                                  const float* __restrict__ sem_w2) {
    __shared__ uint4 sA[2][2][256];
    __shared__ uint4 sB[2][2][256];
    __shared__ float s_rsum[128];
    __shared__ float s_mw[3];
    __shared__ float sb1[128], sw2[128];

    int tid = threadIdx.x;
    int lane = tid & 31, warp = tid >> 5;
    int g = lane >> 2, t = lane & 3;
    int warp_m = warp >> 2, warp_n = warp & 3;
    int row0 = blockIdx.x * 128;

    if (tid < 128) { s_rsum[tid] = 0.f; sb1[tid] = sem_b1[tid]; sw2[tid] = sem_w2[tid]; }
    if (tid < 3) s_mw[tid] = 0.f;

    const unsigned* Bh = (const unsigned*)g_w1T_hi;
    const unsigned* Bl = (const unsigned*)g_w1T_lo;

    int lr = tid >> 1;
    int ch = tid & 1;

    float acc[4][4][4] = {};
    uint4 pa_h, pa_l, pb_h, pb_l;

    auto LOADG = [&](int ks) {
        int grow = row0 + lr;
        float f[8];
        if (grow < NZ) {
            const float4* ap = (const float4*)(g_z + (size_t)grow * 256 + ks * 16 + ch * 8);
            float4 v0 = ap[0], v1 = ap[1];
            f[0] = v0.x; f[1] = v0.y; f[2] = v0.z; f[3] = v0.w;
            f[4] = v1.x; f[5] = v1.y; f[6] = v1.z; f[7] = v1.w;
        } else {
            #pragma unroll
            for (int i = 0; i < 8; i++) f[i] = 0.f;
        }
        split8(f, &pa_h, &pa_l);
        int koff = ks * 8 + ch * 4;
        pb_h = *(const uint4*)(Bh + (size_t)lr * 128 + koff);
        pb_l = *(const uint4*)(Bl + (size_t)lr * 128 + koff);
    };
    auto STORES = [&](int st) {
        int ci = chunk_idx(lr, ch);
        sA[st][0][ci] = pa_h;
        sA[st][1][ci] = pa_l;
        sB[st][0][ci] = pb_h;
        sB[st][1][ci] = pb_l;
    };
    int arow = warp_m * 64 + (lane & 15);
    int ac = lane >> 4;
    unsigned aoff = (unsigned)chunk_idx(arow, ac) * 16;
    int ngrp = lane >> 3;
    int nrow = warp_n * 32 + ((ngrp >> 1) << 3) + (lane & 7);
    int nc = ngrp & 1;
    unsigned boff = (unsigned)chunk_idx(nrow, nc) * 16;

    auto DOMMA = [&](int st) {
        unsigned bA0 = (unsigned)__cvta_generic_to_shared(&sA[st][0][0]);
        unsigned bA1 = (unsigned)__cvta_generic_to_shared(&sA[st][1][0]);
        unsigned bB0 = (unsigned)__cvta_generic_to_shared(&sB[st][0][0]);
        unsigned bB1 = (unsigned)__cvta_generic_to_shared(&sB[st][1][0]);
        unsigned a_h[4][4], a_l[4][4], b_h[2][4], b_l[2][4];
        #pragma unroll
        for (int mf = 0; mf < 4; mf++) {
            LDSM4(a_h[mf], bA0 + aoff + mf * 512);
            LDSM4(a_l[mf], bA1 + aoff + mf * 512);
        }
        #pragma unroll
        for (int j = 0; j < 2; j++) {
            LDSM4(b_h[j], bB0 + boff + j * 512);
            LDSM4(b_l[j], bB1 + boff + j * 512);
        }
        #pragma unroll
        for (int mf = 0; mf < 4; mf++)
            #pragma unroll
            for (int nf = 0; nf < 4; nf++) {
                unsigned* bh = &b_h[nf >> 1][(nf & 1) * 2];
                unsigned* bl = &b_l[nf >> 1][(nf & 1) * 2];
                MMA(acc[mf][nf], a_h[mf], bh);
                MMA(acc[mf][nf], a_h[mf], bl);
                MMA(acc[mf][nf], a_l[mf], bh);
            }
    };

    LOADG(0); STORES(0); __syncthreads();
    for (int ks = 0; ks < 16; ks++) {
        int cur = ks & 1;
        if (ks < 15) LOADG(ks + 1);
        DOMMA(cur);
        __syncthreads();
        if (ks < 15) { STORES(cur ^ 1); __syncthreads(); }
    }

    #pragma unroll
    for (int mf = 0; mf < 4; mf++) {
        float rsa = 0.f, rsb = 0.f;
        #pragma unroll
        for (int nf = 0; nf < 4; nf++) {
            int c = warp_n * 32 + nf * 8 + 2 * t;
            float b0 = sb1[c], b1v = sb1[c + 1];
            float w20 = sw2[c], w21 = sw2[c + 1];
            rsa += tanha(acc[mf][nf][0] + b0) * w20 + tanha(acc[mf][nf][1] + b1v) * w21;
            rsb += tanha(acc[mf][nf][2] + b0) * w20 + tanha(acc[mf][nf][3] + b1v) * w21;
        }
        rsa += __shfl_xor_sync(0xffffffffu, rsa, 1);
        rsa += __shfl_xor_sync(0xffffffffu, rsa, 2);
        rsb += __shfl_xor_sync(0xffffffffu, rsb, 1);
        rsb += __shfl_xor_sync(0xffffffffu, rsb, 2);
        if (t == 0) {
            atomicAdd(&s_rsum[warp_m * 64 + mf * 16 + g], rsa);
            atomicAdd(&s_rsum[warp_m * 64 + mf * 16 + g + 8], rsb);
        }
    }
    __syncthreads();
    if (tid < 128) {
        int r = row0 + tid;
        if (r < NZ) atomicAdd(&s_mw[r / Nn], s_rsum[tid]);
    }
    __syncthreads();
    if (tid < 3) atomicAdd(&g_w[tid], s_mw[tid]);
}

// ---------------------------------------------------------------------------
__global__ void k_aw() {
    float w0 = g_w[0] / (float)Nn;
    float w1 = g_w[1] / (float)Nn;
    float w2 = g_w[2] / (float)Nn;
    float mx = fmaxf(w0, fmaxf(w1, w2));
    float e0 = expf(w0 - mx), e1 = expf(w1 - mx), e2 = expf(w2 - mx);
    float s = e0 + e1 + e2;
    g_aw[0] = e0 / s; g_aw[1] = e1 / s; g_aw[2] = e2 / s;
}

__global__ void k_comb(float* __restrict__ out) {
    int i = blockIdx.x * blockDim.x + threadIdx.x;
    int total = Nn * (Fh / 4);
    if (i >= total) return;
    float a0 = g_aw[0], a1 = g_aw[1], a2 = g_aw[2];
    const float4* z4 = (const float4*)g_z;
    float4 v0 = z4[i];
    float4 v1 = z4[i + (size_t)Nn * Fh / 4];
    float4 v2 = z4[i + 2 * (size_t)Nn * Fh / 4];
    float4 o;
    o.x = v0.x * a0 + v1.x * a1 + v2.x * a2;
    o.y = v0.y * a0 + v1.y * a1 + v2.y * a2;
    o.z = v0.z * a0 + v1.z * a1 + v2.z * a2;
    o.w = v0.w * a0 + v1.w * a1 + v2.w * a2;
    ((float4*)out)[i] = o;
}

// ---------------------------------------------------------------------------
extern "C" void kernel_launch(void* const* d_in, const int* in_sizes, int n_in,
                              void* d_out, int out_size) {
    const float* h      = (const float*)d_in[0];
    const int*   src    = (const int*)d_in[1];
    const int*   dst    = (const int*)d_in[2];
    const float* fc_w   = (const float*)d_in[3];
    const float* attn_l = (const float*)d_in[4];
    const float* attn_r = (const float*)d_in[5];
    const float* bias   = (const float*)d_in[6];
    const float* sem_w1 = (const float*)d_in[7];
    const float* sem_b1 = (const float*)d_in[8];
    const float* sem_w2 = (const float*)d_in[9];
    float* out = (float*)d_out;

    k_zero<<<256, 256>>>();
    k_split_w<<<(Mm * Fh * Fh + Fh * HID + 255) / 256, 256>>>(fc_w, sem_w1);

    k_hist<<<dim3((Ee + 255) / 256, Mm), 256>>>(dst);
    k_scan1<<<dim3(SCANB, Mm), 256>>>();
    k_scan2<<<Mm, 256>>>();
    k_scan3<<<dim3(SCANB, Mm), 256>>>();
    k_scatter<<<dim3((Ee + 255) / 256, Mm), 256>>>(src, dst);

    dim3 gfeat((Nn + 127) / 128, Fh / 128, Mm);
    k_gemm_feat<<<gfeat, 256>>>(h, attn_l, attn_r);

    k_pass_all<<<dim3((Nn + 7) / 8, Mm), 256>>>(bias);

    k_gemm_sem<<<(NZ + 127) / 128, 256>>>(sem_b1, sem_w2);
    k_aw<<<1, 1>>>();
    k_comb<<<(Nn * (Fh / 4) + 255) / 256, 256>>>(out);
}

// round 12
// speedup vs baseline: 3.2464x; 1.0970x over previous
#include <cuda_runtime.h>
#include <cuda_fp16.h>
#include <math.h>

#define Nn 50000
#define Ee 800000
#define Mm 3
#define Fh 256   // H*D
#define Hh 8
#define HID 128
#define NZ (Mm * Nn)        // 150000 rows of z
#define SCANB 196           // ceil(Nn/256)

__device__ __align__(16) __half g_feat16[(size_t)Mm * Nn * Fh];
__device__ __align__(16) __half g_z16[(size_t)Mm * Nn * Fh];
__device__ __align__(16) float  g_el[(size_t)Mm * Nn * Hh];
__device__ __align__(16) float  g_er[(size_t)Mm * Nn * Hh];
__device__ float g_w[Mm];
__device__ float g_aw[Mm];

// CSR scratch
__device__ int g_hist[Mm * Nn];
__device__ int g_off[Mm * Nn];
__device__ int g_bsum[Mm * 256];
__device__ int g_cursor[Mm * Nn];
__device__ int g_csrc[(size_t)Mm * Ee];

// fp16 hi/lo split weights (pre-transposed to [n][k])
__device__ __align__(16) __half g_fwT_hi[(size_t)Mm * Fh * Fh];
__device__ __align__(16) __half g_fwT_lo[(size_t)Mm * Fh * Fh];
__device__ __align__(16) __half g_w1T_hi[HID * Fh];
__device__ __align__(16) __half g_w1T_lo[HID * Fh];

__device__ __forceinline__ float tanha(float x) {
    float y; asm("tanh.approx.f32 %0, %1;" : "=f"(y) : "f"(x)); return y;
}

#define MMA(d, a, b)                                                              \
    asm volatile("mma.sync.aligned.m16n8k16.row.col.f32.f16.f16.f32 "             \
                 "{%0,%1,%2,%3},{%4,%5,%6,%7},{%8,%9},{%0,%1,%2,%3};"             \
                 : "+f"((d)[0]), "+f"((d)[1]), "+f"((d)[2]), "+f"((d)[3])         \
                 : "r"((a)[0]), "r"((a)[1]), "r"((a)[2]), "r"((a)[3]),            \
                   "r"((b)[0]), "r"((b)[1]))

#define LDSM4(r, addr)                                                            \
    asm volatile("ldmatrix.sync.aligned.m8n8.x4.shared.b16 {%0,%1,%2,%3}, [%4];"  \
                 : "=r"((r)[0]), "=r"((r)[1]), "=r"((r)[2]), "=r"((r)[3])         \
                 : "r"(addr))

// chunk swizzle: 16B chunks, 2 per 32B row; conflict-free for STS.128 and LDSM
__device__ __forceinline__ int chunk_idx(int r, int c) {
    return r * 2 + (c ^ ((r >> 2) & 1));
}

// split 8 floats into packed fp16 hi (uint4) + lo (uint4)
__device__ __forceinline__ void split8(const float* f, uint4* hiv, uint4* lov) {
    unsigned* hi = (unsigned*)hiv;
    unsigned* lo = (unsigned*)lov;
    #pragma unroll
    for (int i = 0; i < 4; i++) {
        __half h0 = __float2half_rn(f[2 * i]);
        __half h1 = __float2half_rn(f[2 * i + 1]);
        __half l0 = __float2half_rn(f[2 * i] - __half2float(h0));
        __half l1 = __float2half_rn(f[2 * i + 1] - __half2float(h1));
        __half2 H = __halves2half2(h0, h1);
        __half2 L = __halves2half2(l0, l1);
        hi[i] = *reinterpret_cast<unsigned*>(&H);
        lo[i] = *reinterpret_cast<unsigned*>(&L);
    }
}

// ---------------------------------------------------------------------------
__global__ void k_zero() {
    int i = blockIdx.x * blockDim.x + threadIdx.x;
    int stride = gridDim.x * blockDim.x;
    for (int j = i; j < Mm * Nn; j += stride) g_hist[j] = 0;
    if (i < Mm) g_w[i] = 0.f;
}

// ---------------------------------------------------------------------------
__global__ void k_split_w(const float* __restrict__ fc_w, const float* __restrict__ sem_w1) {
    int i = blockIdx.x * blockDim.x + threadIdx.x;
    int total1 = Mm * Fh * Fh;
    if (i < total1) {
        int m = i / (Fh * Fh);
        int r = i % (Fh * Fh);
        int k = r / Fh, n = r % Fh;
        float a = fc_w[i];
        __half hi = __float2half_rn(a);
        __half lo = __float2half_rn(a - __half2float(hi));
        size_t o = (size_t)m * Fh * Fh + (size_t)n * Fh + k;
        g_fwT_hi[o] = hi; g_fwT_lo[o] = lo;
    } else if (i < total1 + Fh * HID) {
        int j = i - total1;
        int k = j / HID, n = j % HID;
        float a = sem_w1[j];
        __half hi = __float2half_rn(a);
        __half lo = __float2half_rn(a - __half2float(hi));
        size_t o = (size_t)n * Fh + k;
        g_w1T_hi[o] = hi; g_w1T_lo[o] = lo;
    }
}

// ---------------------------------------------------------------------------
// feat[m] = h @ fc_w[m]: fp16 split mma (3-term), ldmatrix, 3-stage pipeline.
// Epilogue computes el/er in-register.
// ---------------------------------------------------------------------------
__global__ __launch_bounds__(256) void k_gemm_feat(const float* __restrict__ hsrc,
                                                   const float* __restrict__ attn_l,
                                                   const float* __restrict__ attn_r) {
    __shared__ uint4 sA[3][2][256];
    __shared__ uint4 sB[3][2][256];

    int tid = threadIdx.x;
    int lane = tid & 31, warp = tid >> 5;
    int g = lane >> 2, t = lane & 3;
    int warp_m = warp >> 2, warp_n = warp & 3;
    int row0 = blockIdx.x * 128;
    int col0 = blockIdx.y * 128;
    int m = blockIdx.z;

    const unsigned* Bh = (const unsigned*)(g_fwT_hi + (size_t)m * Fh * Fh);
    const unsigned* Bl = (const unsigned*)(g_fwT_lo + (size_t)m * Fh * Fh);

    int lr = tid >> 1;         // tile row 0..127
    int ch = tid & 1;          // 8-elem chunk 0/1

    float acc[4][4][4] = {};
    uint4 pa_h, pa_l, pb_h, pb_l;

    auto LOADG = [&](int ks) {
        int grow = row0 + lr;
        float f[8];
        if (grow < Nn) {
            const float4* ap = (const float4*)(hsrc + (size_t)grow * 256 + ks * 16 + ch * 8);
            float4 v0 = ap[0], v1 = ap[1];
            f[0] = v0.x; f[1] = v0.y; f[2] = v0.z; f[3] = v0.w;
            f[4] = v1.x; f[5] = v1.y; f[6] = v1.z; f[7] = v1.w;
        } else {
            #pragma unroll
            for (int i = 0; i < 8; i++) f[i] = 0.f;
        }
        split8(f, &pa_h, &pa_l);
        int koff = ks * 8 + ch * 4;   // in uint (2-half) units
        pb_h = *(const uint4*)(Bh + (size_t)(col0 + lr) * 128 + koff);
        pb_l = *(const uint4*)(Bl + (size_t)(col0 + lr) * 128 + koff);
    };
    auto STORES = [&](int st) {
        int ci = chunk_idx(lr, ch);
        sA[st][0][ci] = pa_h;
        sA[st][1][ci] = pa_l;
        sB[st][0][ci] = pb_h;
        sB[st][1][ci] = pb_l;
    };
    int arow = warp_m * 64 + (lane & 15);
    int ac = lane >> 4;
    unsigned aoff = (unsigned)chunk_idx(arow, ac) * 16;
    int ngrp = lane >> 3;
    int nrow = warp_n * 32 + ((ngrp >> 1) << 3) + (lane & 7);
    int nc = ngrp & 1;
    unsigned boff = (unsigned)chunk_idx(nrow, nc) * 16;

    auto DOMMA = [&](int st) {
        unsigned bA0 = (unsigned)__cvta_generic_to_shared(&sA[st][0][0]);
        unsigned bA1 = (unsigned)__cvta_generic_to_shared(&sA[st][1][0]);
        unsigned bB0 = (unsigned)__cvta_generic_to_shared(&sB[st][0][0]);
        unsigned bB1 = (unsigned)__cvta_generic_to_shared(&sB[st][1][0]);
        unsigned a_h[4][4], a_l[4][4], b_h[2][4], b_l[2][4];
        #pragma unroll
        for (int mf = 0; mf < 4; mf++) {
            LDSM4(a_h[mf], bA0 + aoff + mf * 512);
            LDSM4(a_l[mf], bA1 + aoff + mf * 512);
        }
        #pragma unroll
        for (int j = 0; j < 2; j++) {
            LDSM4(b_h[j], bB0 + boff + j * 512);
            LDSM4(b_l[j], bB1 + boff + j * 512);
        }
        #pragma unroll
        for (int mf = 0; mf < 4; mf++)
            #pragma unroll
            for (int nf = 0; nf < 4; nf++) {
                unsigned* bh = &b_h[nf >> 1][(nf & 1) * 2];
                unsigned* bl = &b_l[nf >> 1][(nf & 1) * 2];
                MMA(acc[mf][nf], a_h[mf], bh);
                MMA(acc[mf][nf], a_h[mf], bl);
                MMA(acc[mf][nf], a_l[mf], bh);
            }
    };

    LOADG(0); STORES(0);
    LOADG(1);
    __syncthreads();
    #pragma unroll 1
    for (int ks = 0; ks < 16; ks++) {
        if (ks + 1 < 16) STORES((ks + 1) % 3);
        if (ks + 2 < 16) LOADG(ks + 2);
        DOMMA(ks % 3);
        __syncthreads();
    }

    // --- epilogue: store feat16; compute el/er for this warp's head ---
    int head = blockIdx.y * 4 + warp_n;
    float alv[8], arv[8];
    #pragma unroll
    for (int nf = 0; nf < 4; nf++) {
        int c = head * 32 + nf * 8 + 2 * t;
        alv[nf * 2]     = attn_l[m * 256 + c];
        alv[nf * 2 + 1] = attn_l[m * 256 + c + 1];
        arv[nf * 2]     = attn_r[m * 256 + c];
        arv[nf * 2 + 1] = attn_r[m * 256 + c + 1];
    }

    __half* C = g_feat16 + (size_t)m * Nn * Fh;
    #pragma unroll
    for (int mf = 0; mf < 4; mf++) {
        int r = row0 + warp_m * 64 + mf * 16 + g;
        float e0 = 0.f, e1 = 0.f, f0 = 0.f, f1 = 0.f;
        #pragma unroll
        for (int nf = 0; nf < 4; nf++) {
            int c = col0 + warp_n * 32 + nf * 8 + 2 * t;
            if (r < Nn)
                *(__half2*)&C[(size_t)r * 256 + c] = __floats2half2_rn(acc[mf][nf][0], acc[mf][nf][1]);
            if (r + 8 < Nn)
                *(__half2*)&C[(size_t)(r + 8) * 256 + c] = __floats2half2_rn(acc[mf][nf][2], acc[mf][nf][3]);
            e0 += acc[mf][nf][0] * alv[nf * 2] + acc[mf][nf][1] * alv[nf * 2 + 1];
            e1 += acc[mf][nf][2] * alv[nf * 2] + acc[mf][nf][3] * alv[nf * 2 + 1];
            f0 += acc[mf][nf][0] * arv[nf * 2] + acc[mf][nf][1] * arv[nf * 2 + 1];
            f1 += acc[mf][nf][2] * arv[nf * 2] + acc[mf][nf][3] * arv[nf * 2 + 1];
        }
        e0 += __shfl_xor_sync(0xffffffffu, e0, 1); e0 += __shfl_xor_sync(0xffffffffu, e0, 2);
        e1 += __shfl_xor_sync(0xffffffffu, e1, 1); e1 += __shfl_xor_sync(0xffffffffu, e1, 2);
        f0 += __shfl_xor_sync(0xffffffffu, f0, 1); f0 += __shfl_xor_sync(0xffffffffu, f0, 2);
        f1 += __shfl_xor_sync(0xffffffffu, f1, 1); f1 += __shfl_xor_sync(0xffffffffu, f1, 2);
        if (t == 0) {
            if (r < Nn) {
                g_el[((size_t)m * Nn + r) * 8 + head] = e0;
                g_er[((size_t)m * Nn + r) * 8 + head] = f0;
            }
            if (r + 8 < Nn) {
                g_el[((size_t)m * Nn + r + 8) * 8 + head] = e1;
                g_er[((size_t)m * Nn + r + 8) * 8 + head] = f1;
            }
        }
    }
}

// ---------------------------------------------------------------------------
// CSR build
// ---------------------------------------------------------------------------
__global__ void k_hist(const int* __restrict__ dst_all) {
    int m = blockIdx.y;
    int e = blockIdx.x * blockDim.x + threadIdx.x;
    if (e < Ee) atomicAdd(&g_hist[m * Nn + dst_all[(size_t)m * Ee + e]], 1);
}

__global__ void k_scan1() {
    __shared__ int s[256];
    int m = blockIdx.y, tid = threadIdx.x;
    int i = blockIdx.x * 256 + tid;
    int v = (i < Nn) ? g_hist[m * Nn + i] : 0;
    s[tid] = v; __syncthreads();
    #pragma unroll
    for (int o = 1; o < 256; o <<= 1) {
        int t = (tid >= o) ? s[tid - o] : 0;
        __syncthreads();
        s[tid] += t;
        __syncthreads();
    }
    if (i < Nn) g_off[m * Nn + i] = s[tid] - v;
    if (tid == 255) g_bsum[m * 256 + blockIdx.x] = s[tid];
}

__global__ void k_scan2() {
    __shared__ int s[256];
    int m = blockIdx.x, tid = threadIdx.x;
    int v = (tid < SCANB) ? g_bsum[m * 256 + tid] : 0;
    s[tid] = v; __syncthreads();
    #pragma unroll
    for (int o = 1; o < 256; o <<= 1) {
        int t = (tid >= o) ? s[tid - o] : 0;
        __syncthreads();
        s[tid] += t;
        __syncthreads();
    }
    g_bsum[m * 256 + tid] = s[tid] - v;
}

__global__ void k_scan3() {
    int m = blockIdx.y, tid = threadIdx.x;
    int i = blockIdx.x * 256 + tid;
    if (i < Nn) {
        int o = g_off[m * Nn + i] + g_bsum[m * 256 + blockIdx.x];
        g_off[m * Nn + i] = o;
        g_cursor[m * Nn + i] = o;
    }
}

__global__ void k_scatter(const int* __restrict__ src_all, const int* __restrict__ dst_all) {
    int m = blockIdx.y;
    int e = blockIdx.x * blockDim.x + threadIdx.x;
    if (e >= Ee) return;
    int d = dst_all[(size_t)m * Ee + e];
    int p = atomicAdd(&g_cursor[m * Nn + d], 1);
    g_csrc[(size_t)m * Ee + p] = src_all[(size_t)m * Ee + e];
}

// ---------------------------------------------------------------------------
// Fused edge pass, all metapaths (grid.y = m). Warp per dst node.
// Writes z as fp16.
// ---------------------------------------------------------------------------
__global__ __launch_bounds__(256) void k_pass_all(const float* __restrict__ bias) {
    int warp = threadIdx.x >> 5, lane = threadIdx.x & 31;
    int d = blockIdx.x * 8 + warp;
    int m = blockIdx.y;
    if (d >= Nn) return;

    int beg = g_off[m * Nn + d];
    int end = (d + 1 < Nn) ? g_off[m * Nn + d + 1] : Ee;

    const float*  elb = g_el + (size_t)m * Nn * Hh;
    const float*  erb = g_er + (size_t)m * Nn * Hh;
    const int*    cs  = g_csrc + (size_t)m * Ee;
    const __half* F   = g_feat16 + (size_t)m * Nn * Fh;

    int myh = lane & 7;
    int esub = lane >> 3;
    float er8 = __ldg(&erb[(size_t)d * 8 + myh]);

    float acc[8] = {};
    float esum = 0.f;

    for (int base = beg; base < end; base += 32) {
        int rem = end - base;
        int idx = 0;
        if (lane < rem) idx = __ldg(&cs[base + lane]);

        float ev[8];
        #pragma unroll
        for (int j = 0; j < 8; j++) {
            int k = j * 4 + esub;
            int s = __shfl_sync(0xffffffffu, idx, k);
            float e = 0.f;
            if (k < rem) {
                float x = __ldg(&elb[(size_t)s * 8 + myh]) + er8;
                x = x > 0.f ? x : 0.2f * x;
                e = __expf(x);
            }
            ev[j] = e;
            esum += e;
        }

        int cnt = rem < 32 ? rem : 32;
        #pragma unroll
        for (int j = 0; j < 8; j++) {
            int k0 = j * 4;
            if (k0 >= cnt) break;
            float evj = ev[j];
            #pragma unroll
            for (int u = 0; u < 4; u++) {
                int kk = k0 + u;
                if (kk < cnt) {
                    int s = __shfl_sync(0xffffffffu, idx, kk);
                    float w = __shfl_sync(0xffffffffu, evj, ((kk & 3) << 3) + (lane >> 2));
                    uint4 p = *(const uint4*)(F + (size_t)s * 256 + lane * 8);
                    __half2* hp = (__half2*)&p;
                    float2 v0 = __half22float2(hp[0]);
                    float2 v1 = __half22float2(hp[1]);
                    float2 v2 = __half22float2(hp[2]);
                    float2 v3 = __half22float2(hp[3]);
                    acc[0] += w * v0.x; acc[1] += w * v0.y;
                    acc[2] += w * v1.x; acc[3] += w * v1.y;
                    acc[4] += w * v2.x; acc[5] += w * v2.y;
                    acc[6] += w * v3.x; acc[7] += w * v3.y;
                }
            }
        }
    }

    esum += __shfl_xor_sync(0xffffffffu, esum, 8);
    esum += __shfl_xor_sync(0xffffffffu, esum, 16);
    float es = __shfl_sync(0xffffffffu, esum, lane >> 2);
    float inv = 1.f / fmaxf(es, 1e-38f);

    const float4* bp = (const float4*)(bias + (size_t)m * 256 + lane * 8);
    float4 b0 = bp[0], b1 = bp[1];
    float r[8];
    r[0] = acc[0] * inv + b0.x; r[1] = acc[1] * inv + b0.y;
    r[2] = acc[2] * inv + b0.z; r[3] = acc[3] * inv + b0.w;
    r[4] = acc[4] * inv + b1.x; r[5] = acc[5] * inv + b1.y;
    r[6] = acc[6] * inv + b1.z; r[7] = acc[7] * inv + b1.w;
    #pragma unroll
    for (int i = 0; i < 8; i++) r[i] = r[i] > 0.f ? r[i] : expm1f(r[i]);

    size_t rowb = ((size_t)m * Nn + d) * 256 + lane * 8;
    __half2 o[4];
    #pragma unroll
    for (int i = 0; i < 4; i++) o[i] = __floats2half2_rn(r[2 * i], r[2 * i + 1]);
    *(uint4*)(g_z16 + rowb) = *(uint4*)o;
}

// ---------------------------------------------------------------------------
// Semantic GEMM: A = z fp16 (exact, single term), B = w1T fp16 hi/lo (2-term).
// Fused tanh/w2/row-reduction epilogue.
// ---------------------------------------------------------------------------
__global__ __launch_bounds__(256) void k_gemm_sem(const float* __restrict__ sem_b1,
                                                  const float* __restrict__ sem_w2) {
    __shared__ uint4 sA[2][256];
    __shared__ uint4 sB[2][2][256];
    __shared__ float s_rsum[128];
    __shared__ float s_mw[3];
    __shared__ float sb1[128], sw2[128];

    int tid = threadIdx.x;
    int lane = tid & 31, warp = tid >> 5;
    int g = lane >> 2, t = lane & 3;
    int warp_m = warp >> 2, warp_n = warp & 3;
    int row0 = blockIdx.x * 128;

    if (tid < 128) { s_rsum[tid] = 0.f; sb1[tid] = sem_b1[tid]; sw2[tid] = sem_w2[tid]; }
    if (tid < 3) s_mw[tid] = 0.f;

    const unsigned* Az = (const unsigned*)g_z16;
    const unsigned* Bh = (const unsigned*)g_w1T_hi;
    const unsigned* Bl = (const unsigned*)g_w1T_lo;

    int lr = tid >> 1;
    int ch = tid & 1;

    float acc[4][4][4] = {};
    uint4 pa, pb_h, pb_l;

    auto LOADG = [&](int ks) {
        int grow = row0 + lr;
        int koff = ks * 8 + ch * 4;
        if (grow < NZ) {
            pa = *(const uint4*)(Az + (size_t)grow * 128 + koff);
        } else {
            pa = make_uint4(0, 0, 0, 0);
        }
        pb_h = *(const uint4*)(Bh + (size_t)lr * 128 + koff);
        pb_l = *(const uint4*)(Bl + (size_t)lr * 128 + koff);
    };
    auto STORES = [&](int st) {
        int ci = chunk_idx(lr, ch);
        sA[st][ci] = pa;
        sB[st][0][ci] = pb_h;
        sB[st][1][ci] = pb_l;
    };
    int arow = warp_m * 64 + (lane & 15);
    int ac = lane >> 4;
    unsigned aoff = (unsigned)chunk_idx(arow, ac) * 16;
    int ngrp = lane >> 3;
    int nrow = warp_n * 32 + ((ngrp >> 1) << 3) + (lane & 7);
    int nc = ngrp & 1;
    unsigned boff = (unsigned)chunk_idx(nrow, nc) * 16;

    auto DOMMA = [&](int st) {
        unsigned bA0 = (unsigned)__cvta_generic_to_shared(&sA[st][0]);
        unsigned bB0 = (unsigned)__cvta_generic_to_shared(&sB[st][0][0]);
        unsigned bB1 = (unsigned)__cvta_generic_to_shared(&sB[st][1][0]);
        unsigned a_h[4][4], b_h[2][4], b_l[2][4];
        #pragma unroll
        for (int mf = 0; mf < 4; mf++)
            LDSM4(a_h[mf], bA0 + aoff + mf * 512);
        #pragma unroll
        for (int j = 0; j < 2; j++) {
            LDSM4(b_h[j], bB0 + boff + j * 512);
            LDSM4(b_l[j], bB1 + boff + j * 512);
        }
        #pragma unroll
        for (int mf = 0; mf < 4; mf++)
            #pragma unroll
            for (int nf = 0; nf < 4; nf++) {
                unsigned* bh = &b_h[nf >> 1][(nf & 1) * 2];
                unsigned* bl = &b_l[nf >> 1][(nf & 1) * 2];
                MMA(acc[mf][nf], a_h[mf], bh);
                MMA(acc[mf][nf], a_h[mf], bl);
            }
    };

    LOADG(0); STORES(0); __syncthreads();
    for (int ks = 0; ks < 16; ks++) {
        int cur = ks & 1;
        if (ks < 15) LOADG(ks + 1);
        DOMMA(cur);
        __syncthreads();
        if (ks < 15) { STORES(cur ^ 1); __syncthreads(); }
    }

    #pragma unroll
    for (int mf = 0; mf < 4; mf++) {
        float rsa = 0.f, rsb = 0.f;
        #pragma unroll
        for (int nf = 0; nf < 4; nf++) {
            int c = warp_n * 32 + nf * 8 + 2 * t;
            float b0 = sb1[c], b1v = sb1[c + 1];
            float w20 = sw2[c], w21 = sw2[c + 1];
            rsa += tanha(acc[mf][nf][0] + b0) * w20 + tanha(acc[mf][nf][1] + b1v) * w21;
            rsb += tanha(acc[mf][nf][2] + b0) * w20 + tanha(acc[mf][nf][3] + b1v) * w21;
        }
        rsa += __shfl_xor_sync(0xffffffffu, rsa, 1);
        rsa += __shfl_xor_sync(0xffffffffu, rsa, 2);
        rsb += __shfl_xor_sync(0xffffffffu, rsb, 1);
        rsb += __shfl_xor_sync(0xffffffffu, rsb, 2);
        if (t == 0) {
            atomicAdd(&s_rsum[warp_m * 64 + mf * 16 + g], rsa);
            atomicAdd(&s_rsum[warp_m * 64 + mf * 16 + g + 8], rsb);
        }
    }
    __syncthreads();
    if (tid < 128) {
        int r = row0 + tid;
        if (r < NZ) atomicAdd(&s_mw[r / Nn], s_rsum[tid]);
    }
    __syncthreads();
    if (tid < 3) atomicAdd(&g_w[tid], s_mw[tid]);
}

// ---------------------------------------------------------------------------
__global__ void k_aw() {
    float w0 = g_w[0] / (float)Nn;
    float w1 = g_w[1] / (float)Nn;
    float w2 = g_w[2] / (float)Nn;
    float mx = fmaxf(w0, fmaxf(w1, w2));
    float e0 = expf(w0 - mx), e1 = expf(w1 - mx), e2 = expf(w2 - mx);
    float s = e0 + e1 + e2;
    g_aw[0] = e0 / s; g_aw[1] = e1 / s; g_aw[2] = e2 / s;
}

// z = sum_m z16_m * a_w[m], output fp32
__global__ void k_comb(float* __restrict__ out) {
    int i = blockIdx.x * blockDim.x + threadIdx.x;   // over Nn*Fh/8 chunks
    int total = Nn * (Fh / 8);
    if (i >= total) return;
    float a0 = g_aw[0], a1 = g_aw[1], a2 = g_aw[2];
    const uint4* z0 = (const uint4*)g_z16;
    size_t stride = (size_t)Nn * Fh / 8;
    uint4 p0 = z0[i], p1 = z0[i + stride], p2 = z0[i + 2 * stride];
    __half2* h0 = (__half2*)&p0;
    __half2* h1 = (__half2*)&p1;
    __half2* h2 = (__half2*)&p2;
    float4 o[2];
    float* op = (float*)o;
    #pragma unroll
    for (int j = 0; j < 4; j++) {
        float2 v0 = __half22float2(h0[j]);
        float2 v1 = __half22float2(h1[j]);
        float2 v2 = __half22float2(h2[j]);
        op[2 * j]     = v0.x * a0 + v1.x * a1 + v2.x * a2;
        op[2 * j + 1] = v0.y * a0 + v1.y * a1 + v2.y * a2;
    }
    ((float4*)out)[2 * i]     = o[0];
    ((float4*)out)[2 * i + 1] = o[1];
}

// ---------------------------------------------------------------------------
extern "C" void kernel_launch(void* const* d_in, const int* in_sizes, int n_in,
                              void* d_out, int out_size) {
    const float* h      = (const float*)d_in[0];
    const int*   src    = (const int*)d_in[1];
    const int*   dst    = (const int*)d_in[2];
    const float* fc_w   = (const float*)d_in[3];
    const float* attn_l = (const float*)d_in[4];
    const float* attn_r = (const float*)d_in[5];
    const float* bias   = (const float*)d_in[6];
    const float* sem_w1 = (const float*)d_in[7];
    const float* sem_b1 = (const float*)d_in[8];
    const float* sem_w2 = (const float*)d_in[9];
    float* out = (float*)d_out;

    // Fork a side stream for the CSR chain (independent of the GEMM chain).
    cudaStream_t sB;
    cudaEvent_t evFork, evJoin;
    cudaStreamCreateWithFlags(&sB, cudaStreamNonBlocking);
    cudaEventCreateWithFlags(&evFork, cudaEventDisableTiming);
    cudaEventCreateWithFlags(&evJoin, cudaEventDisableTiming);

    cudaEventRecord(evFork, 0);
    cudaStreamWaitEvent(sB, evFork, 0);

    // Stream B: CSR build
    k_zero<<<256, 256, 0, sB>>>();
    k_hist<<<dim3((Ee + 255) / 256, Mm), 256, 0, sB>>>(dst);
    k_scan1<<<dim3(SCANB, Mm), 256, 0, sB>>>();
    k_scan2<<<Mm, 256, 0, sB>>>();
    k_scan3<<<dim3(SCANB, Mm), 256, 0, sB>>>();
    k_scatter<<<dim3((Ee + 255) / 256, Mm), 256, 0, sB>>>(src, dst);
    cudaEventRecord(evJoin, sB);

    // Main stream: weight split + feature GEMM (+el/er)
    k_split_w<<<(Mm * Fh * Fh + Fh * HID + 255) / 256, 256>>>(fc_w, sem_w1);
    dim3 gfeat((Nn + 127) / 128, Fh / 128, Mm);
    k_gemm_feat<<<gfeat, 256>>>(h, attn_l, attn_r);

    // Join: pass needs both CSR and feat/el/er
    cudaStreamWaitEvent(0, evJoin, 0);

    k_pass_all<<<dim3((Nn + 7) / 8, Mm), 256>>>(bias);
    k_gemm_sem<<<(NZ + 127) / 128, 256>>>(sem_b1, sem_w2);
    k_aw<<<1, 1>>>();
    k_comb<<<(Nn * (Fh / 8) + 255) / 256, 256>>>(out);

    cudaEventDestroy(evFork);
    cudaEventDestroy(evJoin);
    cudaStreamDestroy(sB);
}

// round 14
// speedup vs baseline: 3.4372x; 1.0588x over previous
#include <cuda_runtime.h>
#include <cuda_fp16.h>
#include <math.h>

#define Nn 50000
#define Ee 800000
#define Mm 3
#define Fh 256   // H*D
#define Hh 8
#define HID 128
#define NZ (Mm * Nn)        // 150000 rows of z
#define SCANB 196           // ceil(Nn/256)

__device__ __align__(16) __half g_feat16[(size_t)Mm * Nn * Fh];
__device__ __align__(16) __half g_z16[(size_t)Mm * Nn * Fh];
__device__ __align__(16) float  g_el[(size_t)Mm * Nn * Hh];
__device__ __align__(16) float  g_er[(size_t)Mm * Nn * Hh];
__device__ float g_w[Mm];

// CSR scratch
__device__ int g_hist[Mm * Nn];
__device__ int g_off[Mm * Nn];
__device__ int g_bsum[Mm * 256];
__device__ int g_cursor[Mm * Nn];
__device__ int g_csrc[(size_t)Mm * Ee];

// fp16 hi/lo split weights (pre-transposed to [n][k])
__device__ __align__(16) __half g_fwT_hi[(size_t)Mm * Fh * Fh];
__device__ __align__(16) __half g_fwT_lo[(size_t)Mm * Fh * Fh];
__device__ __align__(16) __half g_w1T_hi[HID * Fh];
__device__ __align__(16) __half g_w1T_lo[HID * Fh];

__device__ __forceinline__ float tanha(float x) {
    float y; asm("tanh.approx.f32 %0, %1;" : "=f"(y) : "f"(x)); return y;
}

#define MMA(d, a, b)                                                              \
    asm volatile("mma.sync.aligned.m16n8k16.row.col.f32.f16.f16.f32 "             \
                 "{%0,%1,%2,%3},{%4,%5,%6,%7},{%8,%9},{%0,%1,%2,%3};"             \
                 : "+f"((d)[0]), "+f"((d)[1]), "+f"((d)[2]), "+f"((d)[3])         \
                 : "r"((a)[0]), "r"((a)[1]), "r"((a)[2]), "r"((a)[3]),            \
                   "r"((b)[0]), "r"((b)[1]))

#define LDSM4(r, addr)                                                            \
    asm volatile("ldmatrix.sync.aligned.m8n8.x4.shared.b16 {%0,%1,%2,%3}, [%4];"  \
                 : "=r"((r)[0]), "=r"((r)[1]), "=r"((r)[2]), "=r"((r)[3])         \
                 : "r"(addr))

// chunk swizzle: 16B chunks, 2 per 32B row; conflict-free for STS.128 and LDSM
__device__ __forceinline__ int chunk_idx(int r, int c) {
    return r * 2 + (c ^ ((r >> 2) & 1));
}

// convert 8 floats to packed fp16 (uint4)
__device__ __forceinline__ void cvt8(const float* f, uint4* hv) {
    unsigned* hi = (unsigned*)hv;
    #pragma unroll
    for (int i = 0; i < 4; i++) {
        __half2 H = __floats2half2_rn(f[2 * i], f[2 * i + 1]);
        hi[i] = *reinterpret_cast<unsigned*>(&H);
    }
}

// ---------------------------------------------------------------------------
__global__ void k_zero() {
    int i = blockIdx.x * blockDim.x + threadIdx.x;
    int stride = gridDim.x * blockDim.x;
    for (int j = i; j < Mm * Nn; j += stride) g_hist[j] = 0;
    if (i < Mm) g_w[i] = 0.f;
}

// ---------------------------------------------------------------------------
__global__ void k_split_w(const float* __restrict__ fc_w, const float* __restrict__ sem_w1) {
    int i = blockIdx.x * blockDim.x + threadIdx.x;
    int total1 = Mm * Fh * Fh;
    if (i < total1) {
        int m = i / (Fh * Fh);
        int r = i % (Fh * Fh);
        int k = r / Fh, n = r % Fh;
        float a = fc_w[i];
        __half hi = __float2half_rn(a);
        __half lo = __float2half_rn(a - __half2float(hi));
        size_t o = (size_t)m * Fh * Fh + (size_t)n * Fh + k;
        g_fwT_hi[o] = hi; g_fwT_lo[o] = lo;
    } else if (i < total1 + Fh * HID) {
        int j = i - total1;
        int k = j / HID, n = j % HID;
        float a = sem_w1[j];
        __half hi = __float2half_rn(a);
        __half lo = __float2half_rn(a - __half2float(hi));
        size_t o = (size_t)n * Fh + k;
        g_w1T_hi[o] = hi; g_w1T_lo[o] = lo;
    }
}

// ---------------------------------------------------------------------------
// feat[m] = h @ fc_w[m]: fp16 mma, 2-term (A-hi x B-hi + A-hi x B-lo).
// ldmatrix fragment loads, 3-stage pipeline. Epilogue computes el/er.
// ---------------------------------------------------------------------------
__global__ __launch_bounds__(256) void k_gemm_feat(const float* __restrict__ hsrc,
                                                   const float* __restrict__ attn_l,
                                                   const float* __restrict__ attn_r) {
    __shared__ uint4 sA[3][256];
    __shared__ uint4 sB[3][2][256];

    int tid = threadIdx.x;
    int lane = tid & 31, warp = tid >> 5;
    int g = lane >> 2, t = lane & 3;
    int warp_m = warp >> 2, warp_n = warp & 3;
    int row0 = blockIdx.x * 128;
    int col0 = blockIdx.y * 128;
    int m = blockIdx.z;

    const unsigned* Bh = (const unsigned*)(g_fwT_hi + (size_t)m * Fh * Fh);
    const unsigned* Bl = (const unsigned*)(g_fwT_lo + (size_t)m * Fh * Fh);

    int lr = tid >> 1;         // tile row 0..127
    int ch = tid & 1;          // 8-elem chunk 0/1

    float acc[4][4][4] = {};
    uint4 pa, pb_h, pb_l;

    auto LOADG = [&](int ks) {
        int grow = row0 + lr;
        float f[8];
        if (grow < Nn) {
            const float4* ap = (const float4*)(hsrc + (size_t)grow * 256 + ks * 16 + ch * 8);
            float4 v0 = ap[0], v1 = ap[1];
            f[0] = v0.x; f[1] = v0.y; f[2] = v0.z; f[3] = v0.w;
            f[4] = v1.x; f[5] = v1.y; f[6] = v1.z; f[7] = v1.w;
        } else {
            #pragma unroll
            for (int i = 0; i < 8; i++) f[i] = 0.f;
        }
        cvt8(f, &pa);
        int koff = ks * 8 + ch * 4;   // in uint (2-half) units
        pb_h = *(const uint4*)(Bh + (size_t)(col0 + lr) * 128 + koff);
        pb_l = *(const uint4*)(Bl + (size_t)(col0 + lr) * 128 + koff);
    };
    auto STORES = [&](int st) {
        int ci = chunk_idx(lr, ch);
        sA[st][ci] = pa;
        sB[st][0][ci] = pb_h;
        sB[st][1][ci] = pb_l;
    };
    int arow = warp_m * 64 + (lane & 15);
    int ac = lane >> 4;
    unsigned aoff = (unsigned)chunk_idx(arow, ac) * 16;
    int ngrp = lane >> 3;
    int nrow = warp_n * 32 + ((ngrp >> 1) << 3) + (lane & 7);
    int nc = ngrp & 1;
    unsigned boff = (unsigned)chunk_idx(nrow, nc) * 16;

    auto DOMMA = [&](int st) {
        unsigned bA0 = (unsigned)__cvta_generic_to_shared(&sA[st][0]);
        unsigned bB0 = (unsigned)__cvta_generic_to_shared(&sB[st][0][0]);
        unsigned bB1 = (unsigned)__cvta_generic_to_shared(&sB[st][1][0]);
        unsigned a_h[4][4], b_h[2][4], b_l[2][4];
        #pragma unroll
        for (int mf = 0; mf < 4; mf++)
            LDSM4(a_h[mf], bA0 + aoff + mf * 512);
        #pragma unroll
        for (int j = 0; j < 2; j++) {
            LDSM4(b_h[j], bB0 + boff + j * 512);
            LDSM4(b_l[j], bB1 + boff + j * 512);
        }
        #pragma unroll
        for (int mf = 0; mf < 4; mf++)
            #pragma unroll
            for (int nf = 0; nf < 4; nf++) {
                unsigned* bh = &b_h[nf >> 1][(nf & 1) * 2];
                unsigned* bl = &b_l[nf >> 1][(nf & 1) * 2];
                MMA(acc[mf][nf], a_h[mf], bh);
                MMA(acc[mf][nf], a_h[mf], bl);
            }
    };

    LOADG(0); STORES(0);
    LOADG(1);
    __syncthreads();
    #pragma unroll 1
    for (int ks = 0; ks < 16; ks++) {
        if (ks + 1 < 16) STORES((ks + 1) % 3);
        if (ks + 2 < 16) LOADG(ks + 2);
        DOMMA(ks % 3);
        __syncthreads();
    }

    // --- epilogue: store feat16; compute el/er for this warp's head ---
    int head = blockIdx.y * 4 + warp_n;
    float alv[8], arv[8];
    #pragma unroll
    for (int nf = 0; nf < 4; nf++) {
        int c = head * 32 + nf * 8 + 2 * t;
        alv[nf * 2]     = attn_l[m * 256 + c];
        alv[nf * 2 + 1] = attn_l[m * 256 + c + 1];
        arv[nf * 2]     = attn_r[m * 256 + c];
        arv[nf * 2 + 1] = attn_r[m * 256 + c + 1];
    }

    __half* C = g_feat16 + (size_t)m * Nn * Fh;
    #pragma unroll
    for (int mf = 0; mf < 4; mf++) {
        int r = row0 + warp_m * 64 + mf * 16 + g;
        float e0 = 0.f, e1 = 0.f, f0 = 0.f, f1 = 0.f;
        #pragma unroll
        for (int nf = 0; nf < 4; nf++) {
            int c = col0 + warp_n * 32 + nf * 8 + 2 * t;
            if (r < Nn)
                *(__half2*)&C[(size_t)r * 256 + c] = __floats2half2_rn(acc[mf][nf][0], acc[mf][nf][1]);
            if (r + 8 < Nn)
                *(__half2*)&C[(size_t)(r + 8) * 256 + c] = __floats2half2_rn(acc[mf][nf][2], acc[mf][nf][3]);
            e0 += acc[mf][nf][0] * alv[nf * 2] + acc[mf][nf][1] * alv[nf * 2 + 1];
            e1 += acc[mf][nf][2] * alv[nf * 2] + acc[mf][nf][3] * alv[nf * 2 + 1];
            f0 += acc[mf][nf][0] * arv[nf * 2] + acc[mf][nf][1] * arv[nf * 2 + 1];
            f1 += acc[mf][nf][2] * arv[nf * 2] + acc[mf][nf][3] * arv[nf * 2 + 1];
        }
        e0 += __shfl_xor_sync(0xffffffffu, e0, 1); e0 += __shfl_xor_sync(0xffffffffu, e0, 2);
        e1 += __shfl_xor_sync(0xffffffffu, e1, 1); e1 += __shfl_xor_sync(0xffffffffu, e1, 2);
        f0 += __shfl_xor_sync(0xffffffffu, f0, 1); f0 += __shfl_xor_sync(0xffffffffu, f0, 2);
        f1 += __shfl_xor_sync(0xffffffffu, f1, 1); f1 += __shfl_xor_sync(0xffffffffu, f1, 2);
        if (t == 0) {
            if (r < Nn) {
                g_el[((size_t)m * Nn + r) * 8 + head] = e0;
                g_er[((size_t)m * Nn + r) * 8 + head] = f0;
            }
            if (r + 8 < Nn) {
                g_el[((size_t)m * Nn + r + 8) * 8 + head] = e1;
                g_er[((size_t)m * Nn + r + 8) * 8 + head] = f1;
            }
        }
    }
}

// ---------------------------------------------------------------------------
// CSR build
// ---------------------------------------------------------------------------
__global__ void k_hist(const int* __restrict__ dst_all) {
    int m = blockIdx.y;
    int e = blockIdx.x * blockDim.x + threadIdx.x;
    if (e < Ee) atomicAdd(&g_hist[m * Nn + dst_all[(size_t)m * Ee + e]], 1);
}

__global__ void k_scan1() {
    __shared__ int s[256];
    int m = blockIdx.y, tid = threadIdx.x;
    int i = blockIdx.x * 256 + tid;
    int v = (i < Nn) ? g_hist[m * Nn + i] : 0;
    s[tid] = v; __syncthreads();
    #pragma unroll
    for (int o = 1; o < 256; o <<= 1) {
        int t = (tid >= o) ? s[tid - o] : 0;
        __syncthreads();
        s[tid] += t;
        __syncthreads();
    }
    if (i < Nn) g_off[m * Nn + i] = s[tid] - v;
    if (tid == 255) g_bsum[m * 256 + blockIdx.x] = s[tid];
}

__global__ void k_scan2() {
    __shared__ int s[256];
    int m = blockIdx.x, tid = threadIdx.x;
    int v = (tid < SCANB) ? g_bsum[m * 256 + tid] : 0;
    s[tid] = v; __syncthreads();
    #pragma unroll
    for (int o = 1; o < 256; o <<= 1) {
        int t = (tid >= o) ? s[tid - o] : 0;
        __syncthreads();
        s[tid] += t;
        __syncthreads();
    }
    g_bsum[m * 256 + tid] = s[tid] - v;
}

__global__ void k_scan3() {
    int m = blockIdx.y, tid = threadIdx.x;
    int i = blockIdx.x * 256 + tid;
    if (i < Nn) {
        int o = g_off[m * Nn + i] + g_bsum[m * 256 + blockIdx.x];
        g_off[m * Nn + i] = o;
        g_cursor[m * Nn + i] = o;
    }
}

__global__ void k_scatter(const int* __restrict__ src_all, const int* __restrict__ dst_all) {
    int m = blockIdx.y;
    int e = blockIdx.x * blockDim.x + threadIdx.x;
    if (e >= Ee) return;
    int d = dst_all[(size_t)m * Ee + e];
    int p = atomicAdd(&g_cursor[m * Nn + d], 1);
    g_csrc[(size_t)m * Ee + p] = src_all[(size_t)m * Ee + e];
}

// ---------------------------------------------------------------------------
// Fused edge pass, all metapaths (grid.y = m). Warp per dst node.
// Writes z as fp16.
// ---------------------------------------------------------------------------
__global__ __launch_bounds__(256) void k_pass_all(const float* __restrict__ bias) {
    int warp = threadIdx.x >> 5, lane = threadIdx.x & 31;
    int d = blockIdx.x * 8 + warp;
    int m = blockIdx.y;
    if (d >= Nn) return;

    int beg = g_off[m * Nn + d];
    int end = (d + 1 < Nn) ? g_off[m * Nn + d + 1] : Ee;

    const float*  elb = g_el + (size_t)m * Nn * Hh;
    const float*  erb = g_er + (size_t)m * Nn * Hh;
    const int*    cs  = g_csrc + (size_t)m * Ee;
    const __half* F   = g_feat16 + (size_t)m * Nn * Fh;

    int myh = lane & 7;
    int esub = lane >> 3;
    float er8 = __ldg(&erb[(size_t)d * 8 + myh]);

    float acc[8] = {};
    float esum = 0.f;

    for (int base = beg; base < end; base += 32) {
        int rem = end - base;
        int idx = 0;
        if (lane < rem) idx = __ldg(&cs[base + lane]);

        float ev[8];
        #pragma unroll
        for (int j = 0; j < 8; j++) {
            int k = j * 4 + esub;
            int s = __shfl_sync(0xffffffffu, idx, k);
            float e = 0.f;
            if (k < rem) {
                float x = __ldg(&elb[(size_t)s * 8 + myh]) + er8;
                x = x > 0.f ? x : 0.2f * x;
                e = __expf(x);
            }
            ev[j] = e;
            esum += e;
        }

        int cnt = rem < 32 ? rem : 32;
        #pragma unroll
        for (int j = 0; j < 8; j++) {
            int k0 = j * 4;
            if (k0 >= cnt) break;
            float evj = ev[j];
            #pragma unroll
            for (int u = 0; u < 4; u++) {
                int kk = k0 + u;
                if (kk < cnt) {
                    int s = __shfl_sync(0xffffffffu, idx, kk);
                    float w = __shfl_sync(0xffffffffu, evj, ((kk & 3) << 3) + (lane >> 2));
                    uint4 p = *(const uint4*)(F + (size_t)s * 256 + lane * 8);
                    __half2* hp = (__half2*)&p;
                    float2 v0 = __half22float2(hp[0]);
                    float2 v1 = __half22float2(hp[1]);
                    float2 v2 = __half22float2(hp[2]);
                    float2 v3 = __half22float2(hp[3]);
                    acc[0] += w * v0.x; acc[1] += w * v0.y;
                    acc[2] += w * v1.x; acc[3] += w * v1.y;
                    acc[4] += w * v2.x; acc[5] += w * v2.y;
                    acc[6] += w * v3.x; acc[7] += w * v3.y;
                }
            }
        }
    }

    esum += __shfl_xor_sync(0xffffffffu, esum, 8);
    esum += __shfl_xor_sync(0xffffffffu, esum, 16);
    float es = __shfl_sync(0xffffffffu, esum, lane >> 2);
    float inv = 1.f / fmaxf(es, 1e-38f);

    const float4* bp = (const float4*)(bias + (size_t)m * 256 + lane * 8);
    float4 b0 = bp[0], b1 = bp[1];
    float r[8];
    r[0] = acc[0] * inv + b0.x; r[1] = acc[1] * inv + b0.y;
    r[2] = acc[2] * inv + b0.z; r[3] = acc[3] * inv + b0.w;
    r[4] = acc[4] * inv + b1.x; r[5] = acc[5] * inv + b1.y;
    r[6] = acc[6] * inv + b1.z; r[7] = acc[7] * inv + b1.w;
    #pragma unroll
    for (int i = 0; i < 8; i++) r[i] = r[i] > 0.f ? r[i] : expm1f(r[i]);

    size_t rowb = ((size_t)m * Nn + d) * 256 + lane * 8;
    __half2 o[4];
    #pragma unroll
    for (int i = 0; i < 4; i++) o[i] = __floats2half2_rn(r[2 * i], r[2 * i + 1]);
    *(uint4*)(g_z16 + rowb) = *(uint4*)o;
}

// ---------------------------------------------------------------------------
// Semantic GEMM: A = z fp16 (exact, single term), B = w1T fp16 hi/lo (2-term).
// Fused tanh/w2/row-reduction epilogue.
// ---------------------------------------------------------------------------
__global__ __launch_bounds__(256) void k_gemm_sem(const float* __restrict__ sem_b1,
                                                  const float* __restrict__ sem_w2) {
    __shared__ uint4 sA[2][256];
    __shared__ uint4 sB[2][2][256];
    __shared__ float s_rsum[128];
    __shared__ float s_mw[3];
    __shared__ float sb1[128], sw2[128];

    int tid = threadIdx.x;
    int lane = tid & 31, warp = tid >> 5;
    int g = lane >> 2, t = lane & 3;
    int warp_m = warp >> 2, warp_n = warp & 3;
    int row0 = blockIdx.x * 128;

    if (tid < 128) { s_rsum[tid] = 0.f; sb1[tid] = sem_b1[tid]; sw2[tid] = sem_w2[tid]; }
    if (tid < 3) s_mw[tid] = 0.f;

    const unsigned* Az = (const unsigned*)g_z16;
    const unsigned* Bh = (const unsigned*)g_w1T_hi;
    const unsigned* Bl = (const unsigned*)g_w1T_lo;

    int lr = tid >> 1;
    int ch = tid & 1;

    float acc[4][4][4] = {};
    uint4 pa, pb_h, pb_l;

    auto LOADG = [&](int ks) {
        int grow = row0 + lr;
        int koff = ks * 8 + ch * 4;
        if (grow < NZ) {
            pa = *(const uint4*)(Az + (size_t)grow * 128 + koff);
        } else {
            pa = make_uint4(0, 0, 0, 0);
        }
        pb_h = *(const uint4*)(Bh + (size_t)lr * 128 + koff);
        pb_l = *(const uint4*)(Bl + (size_t)lr * 128 + koff);
    };
    auto STORES = [&](int st) {
        int ci = chunk_idx(lr, ch);
        sA[st][ci] = pa;
        sB[st][0][ci] = pb_h;
        sB[st][1][ci] = pb_l;
    };
    int arow = warp_m * 64 + (lane & 15);
    int ac = lane >> 4;
    unsigned aoff = (unsigned)chunk_idx(arow, ac) * 16;
    int ngrp = lane >> 3;
    int nrow = warp_n * 32 + ((ngrp >> 1) << 3) + (lane & 7);
    int nc = ngrp & 1;
    unsigned boff = (unsigned)chunk_idx(nrow, nc) * 16;

    auto DOMMA = [&](int st) {
        unsigned bA0 = (unsigned)__cvta_generic_to_shared(&sA[st][0]);
        unsigned bB0 = (unsigned)__cvta_generic_to_shared(&sB[st][0][0]);
        unsigned bB1 = (unsigned)__cvta_generic_to_shared(&sB[st][1][0]);
        unsigned a_h[4][4], b_h[2][4], b_l[2][4];
        #pragma unroll
        for (int mf = 0; mf < 4; mf++)
            LDSM4(a_h[mf], bA0 + aoff + mf * 512);
        #pragma unroll
        for (int j = 0; j < 2; j++) {
            LDSM4(b_h[j], bB0 + boff + j * 512);
            LDSM4(b_l[j], bB1 + boff + j * 512);
        }
        #pragma unroll
        for (int mf = 0; mf < 4; mf++)
            #pragma unroll
            for (int nf = 0; nf < 4; nf++) {
                unsigned* bh = &b_h[nf >> 1][(nf & 1) * 2];
                unsigned* bl = &b_l[nf >> 1][(nf & 1) * 2];
                MMA(acc[mf][nf], a_h[mf], bh);
                MMA(acc[mf][nf], a_h[mf], bl);
            }
    };

    LOADG(0); STORES(0); __syncthreads();
    for (int ks = 0; ks < 16; ks++) {
        int cur = ks & 1;
        if (ks < 15) LOADG(ks + 1);
        DOMMA(cur);
        __syncthreads();
        if (ks < 15) { STORES(cur ^ 1); __syncthreads(); }
    }

    #pragma unroll
    for (int mf = 0; mf < 4; mf++) {
        float rsa = 0.f, rsb = 0.f;
        #pragma unroll
        for (int nf = 0; nf < 4; nf++) {
            int c = warp_n * 32 + nf * 8 + 2 * t;
            float b0 = sb1[c], b1v = sb1[c + 1];
            float w20 = sw2[c], w21 = sw2[c + 1];
            rsa += tanha(acc[mf][nf][0] + b0) * w20 + tanha(acc[mf][nf][1] + b1v) * w21;
            rsb += tanha(acc[mf][nf][2] + b0) * w20 + tanha(acc[mf][nf][3] + b1v) * w21;
        }
        rsa += __shfl_xor_sync(0xffffffffu, rsa, 1);
        rsa += __shfl_xor_sync(0xffffffffu, rsa, 2);
        rsb += __shfl_xor_sync(0xffffffffu, rsb, 1);
        rsb += __shfl_xor_sync(0xffffffffu, rsb, 2);
        if (t == 0) {
            atomicAdd(&s_rsum[warp_m * 64 + mf * 16 + g], rsa);
            atomicAdd(&s_rsum[warp_m * 64 + mf * 16 + g + 8], rsb);
        }
    }
    __syncthreads();
    if (tid < 128) {
        int r = row0 + tid;
        if (r < NZ) atomicAdd(&s_mw[r / Nn], s_rsum[tid]);
    }
    __syncthreads();
    if (tid < 3) atomicAdd(&g_w[tid], s_mw[tid]);
}

// ---------------------------------------------------------------------------
// z = sum_m z16_m * a_w[m] (softmax over metapath scores computed in-block)
// ---------------------------------------------------------------------------
__global__ void k_comb(float* __restrict__ out) {
    __shared__ float s_aw[3];
    if (threadIdx.x == 0) {
        float w0 = g_w[0] / (float)Nn;
        float w1 = g_w[1] / (float)Nn;
        float w2 = g_w[2] / (float)Nn;
        float mx = fmaxf(w0, fmaxf(w1, w2));
        float e0 = expf(w0 - mx), e1 = expf(w1 - mx), e2 = expf(w2 - mx);
        float s = e0 + e1 + e2;
        s_aw[0] = e0 / s; s_aw[1] = e1 / s; s_aw[2] = e2 / s;
    }
    __syncthreads();

    int i = blockIdx.x * blockDim.x + threadIdx.x;   // over Nn*Fh/8 chunks
    int total = Nn * (Fh / 8);
    if (i >= total) return;
    float a0 = s_aw[0], a1 = s_aw[1], a2 = s_aw[2];
    const uint4* z0 = (const uint4*)g_z16;
    size_t stride = (size_t)Nn * Fh / 8;
    uint4 p0 = z0[i], p1 = z0[i + stride], p2 = z0[i + 2 * stride];
    __half2* h0 = (__half2*)&p0;
    __half2* h1 = (__half2*)&p1;
    __half2* h2 = (__half2*)&p2;
    float4 o[2];
    float* op = (float*)o;
    #pragma unroll
    for (int j = 0; j < 4; j++) {
        float2 v0 = __half22float2(h0[j]);
        float2 v1 = __half22float2(h1[j]);
        float2 v2 = __half22float2(h2[j]);
        op[2 * j]     = v0.x * a0 + v1.x * a1 + v2.x * a2;
        op[2 * j + 1] = v0.y * a0 + v1.y * a1 + v2.y * a2;
    }
    ((float4*)out)[2 * i]     = o[0];
    ((float4*)out)[2 * i + 1] = o[1];
}

// ---------------------------------------------------------------------------
extern "C" void kernel_launch(void* const* d_in, const int* in_sizes, int n_in,
                              void* d_out, int out_size) {
    const float* h      = (const float*)d_in[0];
    const int*   src    = (const int*)d_in[1];
    const int*   dst    = (const int*)d_in[2];
    const float* fc_w   = (const float*)d_in[3];
    const float* attn_l = (const float*)d_in[4];
    const float* attn_r = (const float*)d_in[5];
    const float* bias   = (const float*)d_in[6];
    const float* sem_w1 = (const float*)d_in[7];
    const float* sem_b1 = (const float*)d_in[8];
    const float* sem_w2 = (const float*)d_in[9];
    float* out = (float*)d_out;

    // Fork a side stream for the CSR chain (independent of the GEMM chain).
    cudaStream_t sB;
    cudaEvent_t evFork, evJoin;
    cudaStreamCreateWithFlags(&sB, cudaStreamNonBlocking);
    cudaEventCreateWithFlags(&evFork, cudaEventDisableTiming);
    cudaEventCreateWithFlags(&evJoin, cudaEventDisableTiming);

    cudaEventRecord(evFork, 0);
    cudaStreamWaitEvent(sB, evFork, 0);

    // Stream B: CSR build
    k_zero<<<256, 256, 0, sB>>>();
    k_hist<<<dim3((Ee + 255) / 256, Mm), 256, 0, sB>>>(dst);
    k_scan1<<<dim3(SCANB, Mm), 256, 0, sB>>>();
    k_scan2<<<Mm, 256, 0, sB>>>();
    k_scan3<<<dim3(SCANB, Mm), 256, 0, sB>>>();
    k_scatter<<<dim3((Ee + 255) / 256, Mm), 256, 0, sB>>>(src, dst);
    cudaEventRecord(evJoin, sB);

    // Main stream: weight split + feature GEMM (+el/er)
    k_split_w<<<(Mm * Fh * Fh + Fh * HID + 255) / 256, 256>>>(fc_w, sem_w1);
    dim3 gfeat((Nn + 127) / 128, Fh / 128, Mm);
    k_gemm_feat<<<gfeat, 256>>>(h, attn_l, attn_r);

    // Join: pass needs both CSR and feat/el/er
    cudaStreamWaitEvent(0, evJoin, 0);

    k_pass_all<<<dim3((Nn + 7) / 8, Mm), 256>>>(bias);
    k_gemm_sem<<<(NZ + 127) / 128, 256>>>(sem_b1, sem_w2);
    k_comb<<<(Nn * (Fh / 8) + 255) / 256, 256>>>(out);

    cudaEventDestroy(evFork);
    cudaEventDestroy(evJoin);
    cudaStreamDestroy(sB);
}

// round 16
// speedup vs baseline: 3.8095x; 1.1083x over previous
#include <cuda_runtime.h>
#include <cuda_fp16.h>
#include <math.h>

#define Nn 50000
#define Ee 800000
#define Mm 3
#define Fh 256   // H*D
#define Hh 8
#define HID 128
#define NZ (Mm * Nn)        // 150000 rows of z
#define SCANB 196           // ceil(Nn/256)

__device__ __align__(16) __half g_feat16[(size_t)Mm * Nn * Fh];
__device__ __align__(16) __half g_z16[(size_t)Mm * Nn * Fh];
__device__ __align__(16) float  g_el[(size_t)Mm * Nn * Hh];
__device__ __align__(16) float  g_er[(size_t)Mm * Nn * Hh];
__device__ float g_w[Mm];

// CSR scratch
__device__ int g_hist[Mm * Nn];
__device__ int g_off[Mm * Nn];
__device__ int g_bsum[Mm * 256];
__device__ int g_cursor[Mm * Nn];
__device__ int g_csrc[(size_t)Mm * Ee];

// fp16 weights (pre-transposed to [n][k])
__device__ __align__(16) __half g_fwT[(size_t)Mm * Fh * Fh];
__device__ __align__(16) __half g_w1T[HID * Fh];

__device__ __forceinline__ float tanha(float x) {
    float y; asm("tanh.approx.f32 %0, %1;" : "=f"(y) : "f"(x)); return y;
}

#define MMA(d, a, b)                                                              \
    asm volatile("mma.sync.aligned.m16n8k16.row.col.f32.f16.f16.f32 "             \
                 "{%0,%1,%2,%3},{%4,%5,%6,%7},{%8,%9},{%0,%1,%2,%3};"             \
                 : "+f"((d)[0]), "+f"((d)[1]), "+f"((d)[2]), "+f"((d)[3])         \
                 : "r"((a)[0]), "r"((a)[1]), "r"((a)[2]), "r"((a)[3]),            \
                   "r"((b)[0]), "r"((b)[1]))

#define LDSM4(r, addr)                                                            \
    asm volatile("ldmatrix.sync.aligned.m8n8.x4.shared.b16 {%0,%1,%2,%3}, [%4];"  \
                 : "=r"((r)[0]), "=r"((r)[1]), "=r"((r)[2]), "=r"((r)[3])         \
                 : "r"(addr))

// chunk swizzle: 16B chunks, 2 per 32B row; conflict-free for STS.128 and LDSM
__device__ __forceinline__ int chunk_idx(int r, int c) {
    return r * 2 + (c ^ ((r >> 2) & 1));
}

// convert 8 floats to packed fp16 (uint4)
__device__ __forceinline__ void cvt8(const float* f, uint4* hv) {
    unsigned* hi = (unsigned*)hv;
    #pragma unroll
    for (int i = 0; i < 4; i++) {
        __half2 H = __floats2half2_rn(f[2 * i], f[2 * i + 1]);
        hi[i] = *reinterpret_cast<unsigned*>(&H);
    }
}

// ---------------------------------------------------------------------------
__global__ void k_zero() {
    int i = blockIdx.x * blockDim.x + threadIdx.x;
    int stride = gridDim.x * blockDim.x;
    for (int j = i; j < Mm * Nn; j += stride) g_hist[j] = 0;
    if (i < Mm) g_w[i] = 0.f;
}

// ---------------------------------------------------------------------------
// Convert + transpose weights: fc_w [m][k][n] -> fwT [m][n][k]; w1 [k][n] -> w1T [n][k]
// ---------------------------------------------------------------------------
__global__ void k_cvt_w(const float* __restrict__ fc_w, const float* __restrict__ sem_w1) {
    int i = blockIdx.x * blockDim.x + threadIdx.x;
    int total1 = Mm * Fh * Fh;
    if (i < total1) {
        int m = i / (Fh * Fh);
        int r = i % (Fh * Fh);
        int k = r / Fh, n = r % Fh;
        g_fwT[(size_t)m * Fh * Fh + (size_t)n * Fh + k] = __float2half_rn(fc_w[i]);
    } else if (i < total1 + Fh * HID) {
        int j = i - total1;
        int k = j / HID, n = j % HID;
        g_w1T[(size_t)n * Fh + k] = __float2half_rn(sem_w1[j]);
    }
}

// ---------------------------------------------------------------------------
// feat[m] = h @ fc_w[m]: pure fp16 mma, ldmatrix, 3-stage pipeline.
// Epilogue computes el/er in-register.
// ---------------------------------------------------------------------------
__global__ __launch_bounds__(256) void k_gemm_feat(const float* __restrict__ hsrc,
                                                   const float* __restrict__ attn_l,
                                                   const float* __restrict__ attn_r) {
    __shared__ uint4 sA[3][256];
    __shared__ uint4 sB[3][256];

    int tid = threadIdx.x;
    int lane = tid & 31, warp = tid >> 5;
    int g = lane >> 2, t = lane & 3;
    int warp_m = warp >> 2, warp_n = warp & 3;
    int row0 = blockIdx.x * 128;
    int col0 = blockIdx.y * 128;
    int m = blockIdx.z;

    const unsigned* Bw = (const unsigned*)(g_fwT + (size_t)m * Fh * Fh);

    int lr = tid >> 1;         // tile row 0..127
    int ch = tid & 1;          // 8-elem chunk 0/1

    float acc[4][4][4] = {};
    uint4 pa, pb;

    auto LOADG = [&](int ks) {
        int grow = row0 + lr;
        float f[8];
        if (grow < Nn) {
            const float4* ap = (const float4*)(hsrc + (size_t)grow * 256 + ks * 16 + ch * 8);
            float4 v0 = ap[0], v1 = ap[1];
            f[0] = v0.x; f[1] = v0.y; f[2] = v0.z; f[3] = v0.w;
            f[4] = v1.x; f[5] = v1.y; f[6] = v1.z; f[7] = v1.w;
        } else {
            #pragma unroll
            for (int i = 0; i < 8; i++) f[i] = 0.f;
        }
        cvt8(f, &pa);
        int koff = ks * 8 + ch * 4;   // in uint (2-half) units
        pb = *(const uint4*)(Bw + (size_t)(col0 + lr) * 128 + koff);
    };
    auto STORES = [&](int st) {
        int ci = chunk_idx(lr, ch);
        sA[st][ci] = pa;
        sB[st][ci] = pb;
    };
    int arow = warp_m * 64 + (lane & 15);
    int ac = lane >> 4;
    unsigned aoff = (unsigned)chunk_idx(arow, ac) * 16;
    int ngrp = lane >> 3;
    int nrow = warp_n * 32 + ((ngrp >> 1) << 3) + (lane & 7);
    int nc = ngrp & 1;
    unsigned boff = (unsigned)chunk_idx(nrow, nc) * 16;

    auto DOMMA = [&](int st) {
        unsigned bA0 = (unsigned)__cvta_generic_to_shared(&sA[st][0]);
        unsigned bB0 = (unsigned)__cvta_generic_to_shared(&sB[st][0]);
        unsigned a_h[4][4], b_h[2][4];
        #pragma unroll
        for (int mf = 0; mf < 4; mf++)
            LDSM4(a_h[mf], bA0 + aoff + mf * 512);
        #pragma unroll
        for (int j = 0; j < 2; j++)
            LDSM4(b_h[j], bB0 + boff + j * 512);
        #pragma unroll
        for (int mf = 0; mf < 4; mf++)
            #pragma unroll
            for (int nf = 0; nf < 4; nf++)
                MMA(acc[mf][nf], a_h[mf], &b_h[nf >> 1][(nf & 1) * 2]);
    };

    LOADG(0); STORES(0);
    LOADG(1);
    __syncthreads();
    #pragma unroll 1
    for (int ks = 0; ks < 16; ks++) {
        if (ks + 1 < 16) STORES((ks + 1) % 3);
        if (ks + 2 < 16) LOADG(ks + 2);
        DOMMA(ks % 3);
        __syncthreads();
    }

    // --- epilogue: store feat16; compute el/er for this warp's head ---
    int head = blockIdx.y * 4 + warp_n;
    float alv[8], arv[8];
    #pragma unroll
    for (int nf = 0; nf < 4; nf++) {
        int c = head * 32 + nf * 8 + 2 * t;
        alv[nf * 2]     = attn_l[m * 256 + c];
        alv[nf * 2 + 1] = attn_l[m * 256 + c + 1];
        arv[nf * 2]     = attn_r[m * 256 + c];
        arv[nf * 2 + 1] = attn_r[m * 256 + c + 1];
    }

    __half* C = g_feat16 + (size_t)m * Nn * Fh;
    #pragma unroll
    for (int mf = 0; mf < 4; mf++) {
        int r = row0 + warp_m * 64 + mf * 16 + g;
        float e0 = 0.f, e1 = 0.f, f0 = 0.f, f1 = 0.f;
        #pragma unroll
        for (int nf = 0; nf < 4; nf++) {
            int c = col0 + warp_n * 32 + nf * 8 + 2 * t;
            if (r < Nn)
                *(__half2*)&C[(size_t)r * 256 + c] = __floats2half2_rn(acc[mf][nf][0], acc[mf][nf][1]);
            if (r + 8 < Nn)
                *(__half2*)&C[(size_t)(r + 8) * 256 + c] = __floats2half2_rn(acc[mf][nf][2], acc[mf][nf][3]);
            e0 += acc[mf][nf][0] * alv[nf * 2] + acc[mf][nf][1] * alv[nf * 2 + 1];
            e1 += acc[mf][nf][2] * alv[nf * 2] + acc[mf][nf][3] * alv[nf * 2 + 1];
            f0 += acc[mf][nf][0] * arv[nf * 2] + acc[mf][nf][1] * arv[nf * 2 + 1];
            f1 += acc[mf][nf][2] * arv[nf * 2] + acc[mf][nf][3] * arv[nf * 2 + 1];
        }
        e0 += __shfl_xor_sync(0xffffffffu, e0, 1); e0 += __shfl_xor_sync(0xffffffffu, e0, 2);
        e1 += __shfl_xor_sync(0xffffffffu, e1, 1); e1 += __shfl_xor_sync(0xffffffffu, e1, 2);
        f0 += __shfl_xor_sync(0xffffffffu, f0, 1); f0 += __shfl_xor_sync(0xffffffffu, f0, 2);
        f1 += __shfl_xor_sync(0xffffffffu, f1, 1); f1 += __shfl_xor_sync(0xffffffffu, f1, 2);
        if (t == 0) {
            if (r < Nn) {
                g_el[((size_t)m * Nn + r) * 8 + head] = e0;
                g_er[((size_t)m * Nn + r) * 8 + head] = f0;
            }
            if (r + 8 < Nn) {
                g_el[((size_t)m * Nn + r + 8) * 8 + head] = e1;
                g_er[((size_t)m * Nn + r + 8) * 8 + head] = f1;
            }
        }
    }
}

// ---------------------------------------------------------------------------
// CSR build
// ---------------------------------------------------------------------------
__global__ void k_hist(const int* __restrict__ dst_all) {
    int m = blockIdx.y;
    int e = blockIdx.x * blockDim.x + threadIdx.x;
    if (e < Ee) atomicAdd(&g_hist[m * Nn + dst_all[(size_t)m * Ee + e]], 1);
}

__global__ void k_scan1() {
    __shared__ int s[256];
    int m = blockIdx.y, tid = threadIdx.x;
    int i = blockIdx.x * 256 + tid;
    int v = (i < Nn) ? g_hist[m * Nn + i] : 0;
    s[tid] = v; __syncthreads();
    #pragma unroll
    for (int o = 1; o < 256; o <<= 1) {
        int t = (tid >= o) ? s[tid - o] : 0;
        __syncthreads();
        s[tid] += t;
        __syncthreads();
    }
    if (i < Nn) g_off[m * Nn + i] = s[tid] - v;
    if (tid == 255) g_bsum[m * 256 + blockIdx.x] = s[tid];
}

__global__ void k_scan2() {
    __shared__ int s[256];
    int m = blockIdx.x, tid = threadIdx.x;
    int v = (tid < SCANB) ? g_bsum[m * 256 + tid] : 0;
    s[tid] = v; __syncthreads();
    #pragma unroll
    for (int o = 1; o < 256; o <<= 1) {
        int t = (tid >= o) ? s[tid - o] : 0;
        __syncthreads();
        s[tid] += t;
        __syncthreads();
    }
    g_bsum[m * 256 + tid] = s[tid] - v;
}

__global__ void k_scan3() {
    int m = blockIdx.y, tid = threadIdx.x;
    int i = blockIdx.x * 256 + tid;
    if (i < Nn) {
        int o = g_off[m * Nn + i] + g_bsum[m * 256 + blockIdx.x];
        g_off[m * Nn + i] = o;
        g_cursor[m * Nn + i] = o;
    }
}

__global__ void k_scatter(const int* __restrict__ src_all, const int* __restrict__ dst_all) {
    int m = blockIdx.y;
    int e = blockIdx.x * blockDim.x + threadIdx.x;
    if (e >= Ee) return;
    int d = dst_all[(size_t)m * Ee + e];
    int p = atomicAdd(&g_cursor[m * Nn + d], 1);
    g_csrc[(size_t)m * Ee + p] = src_all[(size_t)m * Ee + e];
}

// ---------------------------------------------------------------------------
// Fused edge pass, all metapaths (grid.y = m). Warp per dst node.
// Writes z as fp16.
// ---------------------------------------------------------------------------
__global__ __launch_bounds__(256) void k_pass_all(const float* __restrict__ bias) {
    int warp = threadIdx.x >> 5, lane = threadIdx.x & 31;
    int d = blockIdx.x * 8 + warp;
    int m = blockIdx.y;
    if (d >= Nn) return;

    int beg = g_off[m * Nn + d];
    int end = (d + 1 < Nn) ? g_off[m * Nn + d + 1] : Ee;

    const float*  elb = g_el + (size_t)m * Nn * Hh;
    const float*  erb = g_er + (size_t)m * Nn * Hh;
    const int*    cs  = g_csrc + (size_t)m * Ee;
    const __half* F   = g_feat16 + (size_t)m * Nn * Fh;

    int myh = lane & 7;
    int esub = lane >> 3;
    float er8 = __ldg(&erb[(size_t)d * 8 + myh]);

    float acc[8] = {};
    float esum = 0.f;

    for (int base = beg; base < end; base += 32) {
        int rem = end - base;
        int idx = 0;
        if (lane < rem) idx = __ldg(&cs[base + lane]);

        float ev[8];
        #pragma unroll
        for (int j = 0; j < 8; j++) {
            int k = j * 4 + esub;
            int s = __shfl_sync(0xffffffffu, idx, k);
            float e = 0.f;
            if (k < rem) {
                float x = __ldg(&elb[(size_t)s * 8 + myh]) + er8;
                x = x > 0.f ? x : 0.2f * x;
                e = __expf(x);
            }
            ev[j] = e;
            esum += e;
        }

        int cnt = rem < 32 ? rem : 32;
        #pragma unroll
        for (int j = 0; j < 8; j++) {
            int k0 = j * 4;
            if (k0 >= cnt) break;
            float evj = ev[j];
            #pragma unroll
            for (int u = 0; u < 4; u++) {
                int kk = k0 + u;
                if (kk < cnt) {
                    int s = __shfl_sync(0xffffffffu, idx, kk);
                    float w = __shfl_sync(0xffffffffu, evj, ((kk & 3) << 3) + (lane >> 2));
                    uint4 p = *(const uint4*)(F + (size_t)s * 256 + lane * 8);
                    __half2* hp = (__half2*)&p;
                    float2 v0 = __half22float2(hp[0]);
                    float2 v1 = __half22float2(hp[1]);
                    float2 v2 = __half22float2(hp[2]);
                    float2 v3 = __half22float2(hp[3]);
                    acc[0] += w * v0.x; acc[1] += w * v0.y;
                    acc[2] += w * v1.x; acc[3] += w * v1.y;
                    acc[4] += w * v2.x; acc[5] += w * v2.y;
                    acc[6] += w * v3.x; acc[7] += w * v3.y;
                }
            }
        }
    }

    esum += __shfl_xor_sync(0xffffffffu, esum, 8);
    esum += __shfl_xor_sync(0xffffffffu, esum, 16);
    float es = __shfl_sync(0xffffffffu, esum, lane >> 2);
    float inv = 1.f / fmaxf(es, 1e-38f);

    const float4* bp = (const float4*)(bias + (size_t)m * 256 + lane * 8);
    float4 b0 = bp[0], b1 = bp[1];
    float r[8];
    r[0] = acc[0] * inv + b0.x; r[1] = acc[1] * inv + b0.y;
    r[2] = acc[2] * inv + b0.z; r[3] = acc[3] * inv + b0.w;
    r[4] = acc[4] * inv + b1.x; r[5] = acc[5] * inv + b1.y;
    r[6] = acc[6] * inv + b1.z; r[7] = acc[7] * inv + b1.w;
    #pragma unroll
    for (int i = 0; i < 8; i++) r[i] = r[i] > 0.f ? r[i] : expm1f(r[i]);

    size_t rowb = ((size_t)m * Nn + d) * 256 + lane * 8;
    __half2 o[4];
    #pragma unroll
    for (int i = 0; i < 4; i++) o[i] = __floats2half2_rn(r[2 * i], r[2 * i + 1]);
    *(uint4*)(g_z16 + rowb) = *(uint4*)o;
}

// ---------------------------------------------------------------------------
// Semantic GEMM: A = z fp16, B = w1T fp16 (single term).
// Fused tanh/w2/row-reduction epilogue.
// ---------------------------------------------------------------------------
__global__ __launch_bounds__(256) void k_gemm_sem(const float* __restrict__ sem_b1,
                                                  const float* __restrict__ sem_w2) {
    __shared__ uint4 sA[2][256];
    __shared__ uint4 sB[2][256];
    __shared__ float s_rsum[128];
    __shared__ float s_mw[3];
    __shared__ float sb1[128], sw2[128];

    int tid = threadIdx.x;
    int lane = tid & 31, warp = tid >> 5;
    int g = lane >> 2, t = lane & 3;
    int warp_m = warp >> 2, warp_n = warp & 3;
    int row0 = blockIdx.x * 128;

    if (tid < 128) { s_rsum[tid] = 0.f; sb1[tid] = sem_b1[tid]; sw2[tid] = sem_w2[tid]; }
    if (tid < 3) s_mw[tid] = 0.f;

    const unsigned* Az = (const unsigned*)g_z16;
    const unsigned* Bw = (const unsigned*)g_w1T;

    int lr = tid >> 1;
    int ch = tid & 1;

    float acc[4][4][4] = {};
    uint4 pa, pb;

    auto LOADG = [&](int ks) {
        int grow = row0 + lr;
        int koff = ks * 8 + ch * 4;
        if (grow < NZ) {
            pa = *(const uint4*)(Az + (size_t)grow * 128 + koff);
        } else {
            pa = make_uint4(0, 0, 0, 0);
        }
        pb = *(const uint4*)(Bw + (size_t)lr * 128 + koff);
    };
    auto STORES = [&](int st) {
        int ci = chunk_idx(lr, ch);
        sA[st][ci] = pa;
        sB[st][ci] = pb;
    };
    int arow = warp_m * 64 + (lane & 15);
    int ac = lane >> 4;
    unsigned aoff = (unsigned)chunk_idx(arow, ac) * 16;
    int ngrp = lane >> 3;
    int nrow = warp_n * 32 + ((ngrp >> 1) << 3) + (lane & 7);
    int nc = ngrp & 1;
    unsigned boff = (unsigned)chunk_idx(nrow, nc) * 16;

    auto DOMMA = [&](int st) {
        unsigned bA0 = (unsigned)__cvta_generic_to_shared(&sA[st][0]);
        unsigned bB0 = (unsigned)__cvta_generic_to_shared(&sB[st][0]);
        unsigned a_h[4][4], b_h[2][4];
        #pragma unroll
        for (int mf = 0; mf < 4; mf++)
            LDSM4(a_h[mf], bA0 + aoff + mf * 512);
        #pragma unroll
        for (int j = 0; j < 2; j++)
            LDSM4(b_h[j], bB0 + boff + j * 512);
        #pragma unroll
        for (int mf = 0; mf < 4; mf++)
            #pragma unroll
            for (int nf = 0; nf < 4; nf++)
                MMA(acc[mf][nf], a_h[mf], &b_h[nf >> 1][(nf & 1) * 2]);
    };

    LOADG(0); STORES(0); __syncthreads();
    for (int ks = 0; ks < 16; ks++) {
        int cur = ks & 1;
        if (ks < 15) LOADG(ks + 1);
        DOMMA(cur);
        __syncthreads();
        if (ks < 15) { STORES(cur ^ 1); __syncthreads(); }
    }

    #pragma unroll
    for (int mf = 0; mf < 4; mf++) {
        float rsa = 0.f, rsb = 0.f;
        #pragma unroll
        for (int nf = 0; nf < 4; nf++) {
            int c = warp_n * 32 + nf * 8 + 2 * t;
            float b0 = sb1[c], b1v = sb1[c + 1];
            float w20 = sw2[c], w21 = sw2[c + 1];
            rsa += tanha(acc[mf][nf][0] + b0) * w20 + tanha(acc[mf][nf][1] + b1v) * w21;
            rsb += tanha(acc[mf][nf][2] + b0) * w20 + tanha(acc[mf][nf][3] + b1v) * w21;
        }
        rsa += __shfl_xor_sync(0xffffffffu, rsa, 1);
        rsa += __shfl_xor_sync(0xffffffffu, rsa, 2);
        rsb += __shfl_xor_sync(0xffffffffu, rsb, 1);
        rsb += __shfl_xor_sync(0xffffffffu, rsb, 2);
        if (t == 0) {
            atomicAdd(&s_rsum[warp_m * 64 + mf * 16 + g], rsa);
            atomicAdd(&s_rsum[warp_m * 64 + mf * 16 + g + 8], rsb);
        }
    }
    __syncthreads();
    if (tid < 128) {
        int r = row0 + tid;
        if (r < NZ) atomicAdd(&s_mw[r / Nn], s_rsum[tid]);
    }
    __syncthreads();
    if (tid < 3) atomicAdd(&g_w[tid], s_mw[tid]);
}

// ---------------------------------------------------------------------------
// z = sum_m z16_m * a_w[m] (softmax over metapath scores computed in-block)
// ---------------------------------------------------------------------------
__global__ void k_comb(float* __restrict__ out) {
    __shared__ float s_aw[3];
    if (threadIdx.x == 0) {
        float w0 = g_w[0] / (float)Nn;
        float w1 = g_w[1] / (float)Nn;
        float w2 = g_w[2] / (float)Nn;
        float mx = fmaxf(w0, fmaxf(w1, w2));
        float e0 = expf(w0 - mx), e1 = expf(w1 - mx), e2 = expf(w2 - mx);
        float s = e0 + e1 + e2;
        s_aw[0] = e0 / s; s_aw[1] = e1 / s; s_aw[2] = e2 / s;
    }
    __syncthreads();

    int i = blockIdx.x * blockDim.x + threadIdx.x;   // over Nn*Fh/8 chunks
    int total = Nn * (Fh / 8);
    if (i >= total) return;
    float a0 = s_aw[0], a1 = s_aw[1], a2 = s_aw[2];
    const uint4* z0 = (const uint4*)g_z16;
    size_t stride = (size_t)Nn * Fh / 8;
    uint4 p0 = z0[i], p1 = z0[i + stride], p2 = z0[i + 2 * stride];
    __half2* h0 = (__half2*)&p0;
    __half2* h1 = (__half2*)&p1;
    __half2* h2 = (__half2*)&p2;
    float4 o[2];
    float* op = (float*)o;
    #pragma unroll
    for (int j = 0; j < 4; j++) {
        float2 v0 = __half22float2(h0[j]);
        float2 v1 = __half22float2(h1[j]);
        float2 v2 = __half22float2(h2[j]);
        op[2 * j]     = v0.x * a0 + v1.x * a1 + v2.x * a2;
        op[2 * j + 1] = v0.y * a0 + v1.y * a1 + v2.y * a2;
    }
    ((float4*)out)[2 * i]     = o[0];
    ((float4*)out)[2 * i + 1] = o[1];
}

// ---------------------------------------------------------------------------
extern "C" void kernel_launch(void* const* d_in, const int* in_sizes, int n_in,
                              void* d_out, int out_size) {
    const float* h      = (const float*)d_in[0];
    const int*   src    = (const int*)d_in[1];
    const int*   dst    = (const int*)d_in[2];
    const float* fc_w   = (const float*)d_in[3];
    const float* attn_l = (const float*)d_in[4];
    const float* attn_r = (const float*)d_in[5];
    const float* bias   = (const float*)d_in[6];
    const float* sem_w1 = (const float*)d_in[7];
    const float* sem_b1 = (const float*)d_in[8];
    const float* sem_w2 = (const float*)d_in[9];
    float* out = (float*)d_out;

    // Fork a side stream for the CSR chain (independent of the GEMM chain).
    cudaStream_t sB;
    cudaEvent_t evFork, evJoin;
    cudaStreamCreateWithFlags(&sB, cudaStreamNonBlocking);
    cudaEventCreateWithFlags(&evFork, cudaEventDisableTiming);
    cudaEventCreateWithFlags(&evJoin, cudaEventDisableTiming);

    cudaEventRecord(evFork, 0);
    cudaStreamWaitEvent(sB, evFork, 0);

    // Stream B: CSR build
    k_zero<<<256, 256, 0, sB>>>();
    k_hist<<<dim3((Ee + 255) / 256, Mm), 256, 0, sB>>>(dst);
    k_scan1<<<dim3(SCANB, Mm), 256, 0, sB>>>();
    k_scan2<<<Mm, 256, 0, sB>>>();
    k_scan3<<<dim3(SCANB, Mm), 256, 0, sB>>>();
    k_scatter<<<dim3((Ee + 255) / 256, Mm), 256, 0, sB>>>(src, dst);
    cudaEventRecord(evJoin, sB);

    // Main stream: weight convert + feature GEMM (+el/er)
    k_cvt_w<<<(Mm * Fh * Fh + Fh * HID + 255) / 256, 256>>>(fc_w, sem_w1);
    dim3 gfeat((Nn + 127) / 128, Fh / 128, Mm);
    k_gemm_feat<<<gfeat, 256>>>(h, attn_l, attn_r);

    // Join: pass needs both CSR and feat/el/er
    cudaStreamWaitEvent(0, evJoin, 0);

    k_pass_all<<<dim3((Nn + 7) / 8, Mm), 256>>>(bias);
    k_gemm_sem<<<(NZ + 127) / 128, 256>>>(sem_b1, sem_w2);
    k_comb<<<(Nn * (Fh / 8) + 255) / 256, 256>>>(out);

    cudaEventDestroy(evFork);
    cudaEventDestroy(evJoin);
    cudaStreamDestroy(sB);
}